// round 7
// baseline (speedup 1.0000x reference)
#include <cuda_runtime.h>
#include <cuda_bf16.h>
#include <math.h>
#include <stdint.h>

#define N_NODES 50000
#define E_EDGES 1600000
#define NEG_SLOPE 0.2f
#define BN_EPS 1e-5f

// ---------------- scratch (static device globals; no allocation) ------------
__device__ float g_bufA[(size_t)N_NODES * 128];
__device__ float g_bufB[(size_t)N_NODES * 128];
__device__ float g_bufC[(size_t)N_NODES * 128];
__device__ float g_bufD[(size_t)N_NODES * 64];
__device__ float g_bufE[(size_t)N_NODES * 64];
__device__ float g_bufF[(size_t)N_NODES * 64];
__device__ float g_als[N_NODES * 2];
__device__ float g_ald[N_NODES * 2];
__device__ float g_wc1[128 * 128];
__device__ float g_wc2[128 * 128];
__device__ int   g_deg[N_NODES];
__device__ int   g_roff[N_NODES + 1];
__device__ int   g_cur[N_NODES];
__device__ int   g_esrc[E_EDGES];

// ---------------- helpers ----------------------------------------------------
__device__ __forceinline__ float lrelu(float x) {
    return x > 0.0f ? x : NEG_SLOPE * x;
}

__device__ __forceinline__ uint32_t smem_u32(const void* p) {
    return (uint32_t)__cvta_generic_to_shared(p);
}

__device__ __forceinline__ void ldsm_x4(uint32_t* r, uint32_t addr) {
    asm volatile("ldmatrix.sync.aligned.m8n8.x4.shared.b16 {%0,%1,%2,%3}, [%4];"
        : "=r"(r[0]), "=r"(r[1]), "=r"(r[2]), "=r"(r[3]) : "r"(addr));
}

__device__ __forceinline__ void ldsm_x4_t(uint32_t* r, uint32_t addr) {
    asm volatile("ldmatrix.sync.aligned.m8n8.x4.trans.shared.b16 {%0,%1,%2,%3}, [%4];"
        : "=r"(r[0]), "=r"(r[1]), "=r"(r[2]), "=r"(r[3]) : "r"(addr));
}

__device__ __forceinline__ void mma_bf16(float* d, const uint32_t* a,
                                         const uint32_t* b) {
    asm volatile(
        "mma.sync.aligned.m16n8k16.row.col.f32.bf16.bf16.f32 "
        "{%0,%1,%2,%3}, {%4,%5,%6,%7}, {%8,%9}, {%0,%1,%2,%3};"
        : "+f"(d[0]), "+f"(d[1]), "+f"(d[2]), "+f"(d[3])
        : "r"(a[0]), "r"(a[1]), "r"(a[2]), "r"(a[3]), "r"(b[0]), "r"(b[1]));
}

// ---------------- tensor-core GEMM via mma.sync (bf16 x3 split) --------------
// Double-buffered smem + reg prefetch. Optional fused attention-logit epilogue:
// als[row,head] += sum_c out[row,c]*aSrc[c] (atomicAdd, als pre-zeroed).
#define APAD 24
#define BPAD 136

struct MmaSmem {
    __align__(16) __nv_bfloat16 Ahi[128 * APAD];
    __align__(16) __nv_bfloat16 Alo[128 * APAD];
    __align__(16) __nv_bfloat16 Bhi[16 * BPAD];
    __align__(16) __nv_bfloat16 Blo[16 * BPAD];
};

__global__ __launch_bounds__(256, 2) void mma_gemm_kernel(
    const float* __restrict__ A, const float* __restrict__ W,
    float* __restrict__ outA, int strideA,
    float* __restrict__ outB, int strideB,
    int M, int K,
    const float* __restrict__ aSrcVec, const float* __restrict__ aDstVec,
    float* __restrict__ als, float* __restrict__ ald)
{
    __shared__ MmaSmem sm[2];

    int tid  = threadIdx.x;
    int wid  = tid >> 5;
    int lane = tid & 31;
    int rowBase = blockIdx.x * 128;

    int warp_m = wid & 1;
    int warp_n = wid >> 1;

    float acc[4][4][4];
    #pragma unroll
    for (int mi = 0; mi < 4; mi++)
        #pragma unroll
        for (int ni = 0; ni < 4; ni++)
            #pragma unroll
            for (int q = 0; q < 4; q++) acc[mi][ni][q] = 0.0f;

    uint32_t aHiB[2] = {smem_u32(sm[0].Ahi), smem_u32(sm[1].Ahi)};
    uint32_t aLoB[2] = {smem_u32(sm[0].Alo), smem_u32(sm[1].Alo)};
    uint32_t bHiB[2] = {smem_u32(sm[0].Bhi), smem_u32(sm[1].Bhi)};
    uint32_t bLoB[2] = {smem_u32(sm[0].Blo), smem_u32(sm[1].Blo)};

    int a_r = (lane & 7) + ((lane >> 3) & 1) * 8;
    int a_c = (lane >> 4) * 8;
    int b_r = lane & 15;
    int b_c = (lane >> 4) * 8;

    int aR[2], aC[2], wR[2], wC[2], arow[2], wrow[2];
    bool aok[2];
    #pragma unroll
    for (int h = 0; h < 2; h++) {
        int i = tid + h * 256;
        aR[h] = i >> 2;  aC[h] = (i & 3) * 4;
        wR[h] = i >> 5;  wC[h] = (i & 31) * 4;
        arow[h] = aR[h] * APAD + aC[h];
        wrow[h] = wR[h] * BPAD + wC[h];
        aok[h]  = (rowBase + aR[h]) < M;
    }

    float4 av[2], wv[2];
    #pragma unroll
    for (int h = 0; h < 2; h++) {
        av[h] = make_float4(0.f, 0.f, 0.f, 0.f);
        if (aok[h]) av[h] = *(const float4*)(A + (size_t)(rowBase + aR[h]) * K + aC[h]);
        wv[h] = *(const float4*)(W + (size_t)wR[h] * 128 + wC[h]);
    }
    // store chunk 0 into buffer 0
    #pragma unroll
    for (int h = 0; h < 2; h++) {
        float* vp = (float*)&av[h];
        #pragma unroll
        for (int q = 0; q < 4; q++) {
            __nv_bfloat16 hi = __float2bfloat16(vp[q]);
            sm[0].Ahi[arow[h] + q] = hi;
            sm[0].Alo[arow[h] + q] = __float2bfloat16(vp[q] - __bfloat162float(hi));
        }
        float* wp = (float*)&wv[h];
        #pragma unroll
        for (int q = 0; q < 4; q++) {
            __nv_bfloat16 hi = __float2bfloat16(wp[q]);
            sm[0].Bhi[wrow[h] + q] = hi;
            sm[0].Blo[wrow[h] + q] = __float2bfloat16(wp[q] - __bfloat162float(hi));
        }
    }
    __syncthreads();

    int nchunk = K >> 4;
    for (int c = 0; c < nchunk; c++) {
        int sel = c & 1;

        // prefetch chunk c+1 into registers (latency hidden under MMAs)
        bool more = (c + 1 < nchunk);
        if (more) {
            int k0n = (c + 1) << 4;
            #pragma unroll
            for (int h = 0; h < 2; h++) {
                av[h] = make_float4(0.f, 0.f, 0.f, 0.f);
                if (aok[h])
                    av[h] = *(const float4*)(A + (size_t)(rowBase + aR[h]) * K + k0n + aC[h]);
                wv[h] = *(const float4*)(W + (size_t)(k0n + wR[h]) * 128 + wC[h]);
            }
        }

        // MMA block for current chunk from buffer sel
        uint32_t bh[2][4], bl[2][4];
        #pragma unroll
        for (int nh = 0; nh < 2; nh++) {
            uint32_t boff = (uint32_t)(b_r * BPAD + warp_n * 32 + nh * 16 + b_c) * 2;
            ldsm_x4_t(bh[nh], bHiB[sel] + boff);
            ldsm_x4_t(bl[nh], bLoB[sel] + boff);
        }
        #pragma unroll
        for (int mi = 0; mi < 4; mi++) {
            uint32_t aoff = (uint32_t)((warp_m * 64 + mi * 16 + a_r) * APAD + a_c) * 2;
            uint32_t ah[4], al[4];
            ldsm_x4(ah, aHiB[sel] + aoff);
            ldsm_x4(al, aLoB[sel] + aoff);
            #pragma unroll
            for (int ni = 0; ni < 4; ni++) {
                const uint32_t* bhp = &bh[ni >> 1][(ni & 1) * 2];
                const uint32_t* blp = &bl[ni >> 1][(ni & 1) * 2];
                mma_bf16(acc[mi][ni], ah, bhp);
                mma_bf16(acc[mi][ni], ah, blp);
                mma_bf16(acc[mi][ni], al, bhp);
            }
        }

        // store chunk c+1 into the other buffer
        if (more) {
            MmaSmem& dst = sm[sel ^ 1];
            #pragma unroll
            for (int h = 0; h < 2; h++) {
                float* vp = (float*)&av[h];
                #pragma unroll
                for (int q = 0; q < 4; q++) {
                    __nv_bfloat16 hi = __float2bfloat16(vp[q]);
                    dst.Ahi[arow[h] + q] = hi;
                    dst.Alo[arow[h] + q] = __float2bfloat16(vp[q] - __bfloat162float(hi));
                }
                float* wp = (float*)&wv[h];
                #pragma unroll
                for (int q = 0; q < 4; q++) {
                    __nv_bfloat16 hi = __float2bfloat16(wp[q]);
                    dst.Bhi[wrow[h] + q] = hi;
                    dst.Blo[wrow[h] + q] = __float2bfloat16(wp[q] - __bfloat162float(hi));
                }
            }
            __syncthreads();
        }
    }

    int g = lane >> 2, tig = lane & 3;

    // write output (split columns)
    #pragma unroll
    for (int mi = 0; mi < 4; mi++) {
        int row = rowBase + warp_m * 64 + mi * 16 + g;
        #pragma unroll
        for (int ni = 0; ni < 4; ni++) {
            int col = warp_n * 32 + ni * 8 + tig * 2;
            float* p0;
            if (col < 64) p0 = outA + (size_t)row * strideA + col;
            else          p0 = outB + (size_t)row * strideB + (col - 64);
            size_t rs = (col < 64) ? (size_t)strideA : (size_t)strideB;
            if (row < M)
                *(float2*)p0 = make_float2(acc[mi][ni][0], acc[mi][ni][1]);
            if (row + 8 < M)
                *(float2*)(p0 + 8 * rs) = make_float2(acc[mi][ni][2], acc[mi][ni][3]);
        }
    }

    // fused attention-logit epilogue
    if (aSrcVec != nullptr) {
        int head = warp_n >> 1;
        float asv[8], adv[8];
        #pragma unroll
        for (int ni = 0; ni < 4; ni++)
            #pragma unroll
            for (int t = 0; t < 2; t++) {
                int col = warp_n * 32 + ni * 8 + tig * 2 + t;
                asv[ni * 2 + t] = __ldg(aSrcVec + col);
                adv[ni * 2 + t] = __ldg(aDstVec + col);
            }
        #pragma unroll
        for (int mi = 0; mi < 4; mi++) {
            float ps0 = 0.f, pd0 = 0.f, ps1 = 0.f, pd1 = 0.f;
            #pragma unroll
            for (int ni = 0; ni < 4; ni++) {
                ps0 += acc[mi][ni][0] * asv[ni * 2] + acc[mi][ni][1] * asv[ni * 2 + 1];
                pd0 += acc[mi][ni][0] * adv[ni * 2] + acc[mi][ni][1] * adv[ni * 2 + 1];
                ps1 += acc[mi][ni][2] * asv[ni * 2] + acc[mi][ni][3] * asv[ni * 2 + 1];
                pd1 += acc[mi][ni][2] * adv[ni * 2] + acc[mi][ni][3] * adv[ni * 2 + 1];
            }
            #pragma unroll
            for (int o = 1; o < 4; o <<= 1) {
                ps0 += __shfl_xor_sync(0xffffffffu, ps0, o);
                pd0 += __shfl_xor_sync(0xffffffffu, pd0, o);
                ps1 += __shfl_xor_sync(0xffffffffu, ps1, o);
                pd1 += __shfl_xor_sync(0xffffffffu, pd1, o);
            }
            if (tig == 0) {
                int row = rowBase + warp_m * 64 + mi * 16 + g;
                if (row < M) {
                    atomicAdd(&als[row * 2 + head], ps0);
                    atomicAdd(&ald[row * 2 + head], pd0);
                }
                if (row + 8 < M) {
                    atomicAdd(&als[(row + 8) * 2 + head], ps1);
                    atomicAdd(&ald[(row + 8) * 2 + head], pd1);
                }
            }
        }
    }
}

// ---------------- CSR build ---------------------------------------------------
__global__ void hist_kernel(const int* __restrict__ dst, int* __restrict__ deg)
{
    int e = blockIdx.x * blockDim.x + threadIdx.x;
    if (e < E_EDGES) atomicAdd(&deg[dst[e]], 1);
}

__global__ __launch_bounds__(1024) void scan_kernel(
    const int* __restrict__ deg, int* __restrict__ roff, int* __restrict__ cur)
{
    __shared__ int part[1024];
    const int CH = (N_NODES + 1023) / 1024;
    int t = threadIdx.x;
    int base = t * CH;
    int sum = 0;
    for (int i = 0; i < CH; i++) {
        int idx = base + i;
        if (idx < N_NODES) sum += deg[idx];
    }
    part[t] = sum;
    __syncthreads();
    for (int off = 1; off < 1024; off <<= 1) {
        int v = (t >= off) ? part[t - off] : 0;
        __syncthreads();
        part[t] += v;
        __syncthreads();
    }
    int run = part[t] - sum;
    for (int i = 0; i < CH; i++) {
        int idx = base + i;
        if (idx < N_NODES) {
            roff[idx] = run;
            cur[idx]  = run;
            run += deg[idx];
        }
    }
    if (t == 1023) roff[N_NODES] = run;
}

__global__ void scatter_kernel(const int* __restrict__ src,
                               const int* __restrict__ dst,
                               int* __restrict__ cur, int* __restrict__ esrc)
{
    int e = blockIdx.x * blockDim.x + threadIdx.x;
    if (e >= E_EDGES) return;
    int d = dst[e];
    int p = atomicAdd(&cur[d], 1);
    esrc[p] = src[e];
}

// ---------------- fused GAT gather: single pass, 4-way unrolled ---------------
__global__ __launch_bounds__(256) void gat_gather_kernel(
    const int* __restrict__ roff, const int* __restrict__ esrc,
    const float* __restrict__ als, const float* __restrict__ ald,
    const float* __restrict__ h, const float* __restrict__ bias,
    float* __restrict__ out, int relu)
{
    int d = (blockIdx.x * blockDim.x + threadIdx.x) >> 5;
    int lane = threadIdx.x & 31;
    if (d >= N_NODES) return;

    float2 ad = *(const float2*)(ald + 2 * d);
    float2 a_self = *(const float2*)(als + 2 * d);
    int head = (lane >= 16);

    float w_self0 = expf(lrelu(a_self.x + ad.x));
    float w_self1 = expf(lrelu(a_self.y + ad.y));
    float s0 = w_self0, s1 = w_self1;
    float wsh = head ? w_self1 : w_self0;

    float4 hv = *(const float4*)(h + (size_t)d * 128 + lane * 4);
    float4 acc;
    acc.x = wsh * hv.x;
    acc.y = wsh * hv.y;
    acc.z = wsh * hv.z;
    acc.w = wsh * hv.w;

    int beg = roff[d], end = roff[d + 1];
    int i = beg;
    for (; i + 4 <= end; i += 4) {
        int sI[4];
        float2 aI[4];
        float4 vI[4];
        #pragma unroll
        for (int j = 0; j < 4; j++) sI[j] = __ldg(esrc + i + j);
        #pragma unroll
        for (int j = 0; j < 4; j++) aI[j] = *(const float2*)(als + 2 * sI[j]);
        #pragma unroll
        for (int j = 0; j < 4; j++)
            vI[j] = *(const float4*)(h + (size_t)sI[j] * 128 + lane * 4);
        #pragma unroll
        for (int j = 0; j < 4; j++) {
            float w0 = expf(lrelu(aI[j].x + ad.x));
            float w1 = expf(lrelu(aI[j].y + ad.y));
            s0 += w0;
            s1 += w1;
            float wh = head ? w1 : w0;
            acc.x = fmaf(wh, vI[j].x, acc.x);
            acc.y = fmaf(wh, vI[j].y, acc.y);
            acc.z = fmaf(wh, vI[j].z, acc.z);
            acc.w = fmaf(wh, vI[j].w, acc.w);
        }
    }
    for (; i < end; i++) {
        int s = __ldg(esrc + i);
        float2 a = *(const float2*)(als + 2 * s);
        float4 v = *(const float4*)(h + (size_t)s * 128 + lane * 4);
        float w0 = expf(lrelu(a.x + ad.x));
        float w1 = expf(lrelu(a.y + ad.y));
        s0 += w0;
        s1 += w1;
        float wh = head ? w1 : w0;
        acc.x = fmaf(wh, v.x, acc.x);
        acc.y = fmaf(wh, v.y, acc.y);
        acc.z = fmaf(wh, v.z, acc.z);
        acc.w = fmaf(wh, v.w, acc.w);
    }

    float inv = 1.0f / (head ? s1 : s0);
    float4 b = *(const float4*)(bias + lane * 4);
    acc.x = fmaf(acc.x, inv, b.x);
    acc.y = fmaf(acc.y, inv, b.y);
    acc.z = fmaf(acc.z, inv, b.z);
    acc.w = fmaf(acc.w, inv, b.w);
    if (relu) {
        acc.x = fmaxf(acc.x, 0.0f);
        acc.y = fmaxf(acc.y, 0.0f);
        acc.z = fmaxf(acc.z, 0.0f);
        acc.w = fmaxf(acc.w, 0.0f);
    }
    *(float4*)(out + (size_t)d * 128 + lane * 4) = acc;
}

// ---------------- weight concat for fused SAGE GEMM --------------------------
__global__ void concat_w_kernel(const float* __restrict__ wl,
                                const float* __restrict__ wr,
                                float* __restrict__ wc, int K)
{
    int i = blockIdx.x * blockDim.x + threadIdx.x;
    if (i >= K * 64) return;
    int k = i >> 6, c = i & 63;
    wc[k * 128 + c]      = wl[i];
    wc[k * 128 + 64 + c] = wr[i];
}

// ---------------- fused SAGE gather (mean + bias + root + relu [+ BN]) -------
__global__ __launch_bounds__(256) void sage_gather_kernel(
    const int* __restrict__ roff, const int* __restrict__ esrc,
    const float* __restrict__ y, const float* __restrict__ bl,
    const float* __restrict__ r, float* __restrict__ out,
    const float* __restrict__ gamma, const float* __restrict__ beta,
    const float* __restrict__ mean, const float* __restrict__ var,
    int do_bn)
{
    int d = (blockIdx.x * blockDim.x + threadIdx.x) >> 5;
    int lane = threadIdx.x & 31;
    if (d >= N_NODES) return;

    int beg = roff[d], end = roff[d + 1];
    float ax = 0.0f, ay = 0.0f;
    int i = beg;
    for (; i + 4 <= end; i += 4) {
        int sI[4];
        float2 vI[4];
        #pragma unroll
        for (int j = 0; j < 4; j++) sI[j] = __ldg(esrc + i + j);
        #pragma unroll
        for (int j = 0; j < 4; j++)
            vI[j] = *(const float2*)(y + (size_t)sI[j] * 64 + lane * 2);
        #pragma unroll
        for (int j = 0; j < 4; j++) { ax += vI[j].x; ay += vI[j].y; }
    }
    for (; i < end; i++) {
        int s = __ldg(esrc + i);
        float2 v = *(const float2*)(y + (size_t)s * 64 + lane * 2);
        ax += v.x;
        ay += v.y;
    }
    float invc = 1.0f / fmaxf((float)(end - beg), 1.0f);
    int c = lane * 2;
    float2 bb = *(const float2*)(bl + c);
    float2 rr = *(const float2*)(r + (size_t)d * 64 + c);
    float vx = fmaxf(ax * invc + bb.x + rr.x, 0.0f);
    float vy = fmaxf(ay * invc + bb.y + rr.y, 0.0f);
    if (do_bn) {
        float sx = gamma[c]     * rsqrtf(var[c]     + BN_EPS);
        float sy = gamma[c + 1] * rsqrtf(var[c + 1] + BN_EPS);
        vx = (vx - mean[c])     * sx + beta[c];
        vy = (vy - mean[c + 1]) * sy + beta[c + 1];
    }
    *(float2*)(out + (size_t)d * 64 + c) = make_float2(vx, vy);
}

// ---------------- host orchestration -----------------------------------------
extern "C" void kernel_launch(void* const* d_in, const int* in_sizes, int n_in,
                              void* d_out, int out_size)
{
    const float* x      = (const float*)d_in[0];
    const int*   ei     = (const int*)d_in[1];
    const float* W1     = (const float*)d_in[2];
    const float* a_src1 = (const float*)d_in[3];
    const float* a_dst1 = (const float*)d_in[4];
    const float* b1     = (const float*)d_in[5];
    const float* W2     = (const float*)d_in[6];
    const float* a_src2 = (const float*)d_in[7];
    const float* a_dst2 = (const float*)d_in[8];
    const float* b2     = (const float*)d_in[9];
    const float* s1wl   = (const float*)d_in[10];
    const float* s1bl   = (const float*)d_in[11];
    const float* s1wr   = (const float*)d_in[12];
    const float* s2wl   = (const float*)d_in[13];
    const float* s2bl   = (const float*)d_in[14];
    const float* s2wr   = (const float*)d_in[15];
    const float* bng    = (const float*)d_in[16];
    const float* bnb    = (const float*)d_in[17];
    const float* bnm    = (const float*)d_in[18];
    const float* bnv    = (const float*)d_in[19];
    float* out = (float*)d_out;

    const int* src = ei;
    const int* dst = ei + E_EDGES;

    float *A, *B, *C, *D, *Ebuf, *F, *als, *ald, *wc1, *wc2;
    int *deg, *roff, *cur, *esrc;
    cudaGetSymbolAddress((void**)&A,    g_bufA);
    cudaGetSymbolAddress((void**)&B,    g_bufB);
    cudaGetSymbolAddress((void**)&C,    g_bufC);
    cudaGetSymbolAddress((void**)&D,    g_bufD);
    cudaGetSymbolAddress((void**)&Ebuf, g_bufE);
    cudaGetSymbolAddress((void**)&F,    g_bufF);
    cudaGetSymbolAddress((void**)&als,  g_als);
    cudaGetSymbolAddress((void**)&ald,  g_ald);
    cudaGetSymbolAddress((void**)&wc1,  g_wc1);
    cudaGetSymbolAddress((void**)&wc2,  g_wc2);
    cudaGetSymbolAddress((void**)&deg,  g_deg);
    cudaGetSymbolAddress((void**)&roff, g_roff);
    cudaGetSymbolAddress((void**)&cur,  g_cur);
    cudaGetSymbolAddress((void**)&esrc, g_esrc);

    static cudaStream_t s_side = nullptr;
    static cudaEvent_t ev_fork = nullptr, ev_join = nullptr;
    if (s_side == nullptr) {
        cudaStreamCreateWithFlags(&s_side, cudaStreamNonBlocking);
        cudaEventCreateWithFlags(&ev_fork, cudaEventDisableTiming);
        cudaEventCreateWithFlags(&ev_join, cudaEventDisableTiming);
    }

    int gemmBlocks   = (N_NODES + 127) / 128;
    int gatherBlocks = (N_NODES * 32 + 255) / 256;

    // ---- fork: CSR build + weight concats on side stream ----
    cudaEventRecord(ev_fork, 0);
    cudaStreamWaitEvent(s_side, ev_fork, 0);
    cudaMemsetAsync(deg, 0, N_NODES * sizeof(int), s_side);
    concat_w_kernel<<<(128 * 64 + 255) / 256, 256, 0, s_side>>>(s1wl, s1wr, wc1, 128);
    concat_w_kernel<<<(64 * 64 + 255) / 256, 256, 0, s_side>>>(s2wl, s2wr, wc2, 64);
    hist_kernel<<<(E_EDGES + 255) / 256, 256, 0, s_side>>>(dst, deg);
    scan_kernel<<<1, 1024, 0, s_side>>>(deg, roff, cur);
    scatter_kernel<<<(E_EDGES + 255) / 256, 256, 0, s_side>>>(src, dst, cur, esrc);
    cudaEventRecord(ev_join, s_side);

    // ---- main stream: GAT layer 1 GEMM (with fused al) ----
    cudaMemsetAsync(als, 0, N_NODES * 2 * sizeof(float), 0);
    cudaMemsetAsync(ald, 0, N_NODES * 2 * sizeof(float), 0);
    mma_gemm_kernel<<<gemmBlocks, 256>>>(x, W1, A, 128, A + 64, 128,
                                         N_NODES, 256, a_src1, a_dst1, als, ald);

    // ---- join: gathers need CSR ----
    cudaStreamWaitEvent(0, ev_join, 0);
    gat_gather_kernel<<<gatherBlocks, 256>>>(roff, esrc, als, ald, A, b1, B, 1);

    // ---- GAT layer 2 ----
    cudaMemsetAsync(als, 0, N_NODES * 2 * sizeof(float), 0);
    cudaMemsetAsync(ald, 0, N_NODES * 2 * sizeof(float), 0);
    mma_gemm_kernel<<<gemmBlocks, 256>>>(B, W2, C, 128, C + 64, 128,
                                         N_NODES, 128, a_src2, a_dst2, als, ald);
    gat_gather_kernel<<<gatherBlocks, 256>>>(roff, esrc, als, ald, C, b2, A, 0);

    // ---- SAGE layer 1 ----
    mma_gemm_kernel<<<gemmBlocks, 256>>>(A, wc1, D, 64, Ebuf, 64, N_NODES, 128,
                                         nullptr, nullptr, nullptr, nullptr);
    sage_gather_kernel<<<gatherBlocks, 256>>>(roff, esrc, D, s1bl, Ebuf, F,
                                              nullptr, nullptr, nullptr, nullptr, 0);

    // ---- SAGE layer 2 + BN fused ----
    mma_gemm_kernel<<<gemmBlocks, 256>>>(F, wc2, D, 64, Ebuf, 64, N_NODES, 64,
                                         nullptr, nullptr, nullptr, nullptr);
    sage_gather_kernel<<<gatherBlocks, 256>>>(roff, esrc, D, s2bl, Ebuf, out,
                                              bng, bnb, bnm, bnv, 1);
}

// round 8
// speedup vs baseline: 1.1838x; 1.1838x over previous
#include <cuda_runtime.h>
#include <cuda_bf16.h>
#include <math.h>
#include <stdint.h>

#define N_NODES 50000
#define E_EDGES 1600000
#define NEG_SLOPE 0.2f
#define BN_EPS 1e-5f
#define SCAN_NB ((N_NODES + 255) / 256)   // 196

// ---------------- scratch (static device globals; no allocation) ------------
__device__ float g_bufA[(size_t)N_NODES * 128];
__device__ float g_bufB[(size_t)N_NODES * 128];
__device__ float g_bufC[(size_t)N_NODES * 128];
__device__ float g_bufD[(size_t)N_NODES * 64];
__device__ float g_bufE[(size_t)N_NODES * 64];
__device__ float g_bufF[(size_t)N_NODES * 64];
__device__ float g_als[N_NODES * 2];
__device__ float g_ald[N_NODES * 2];
__device__ float g_wc1[128 * 128];
__device__ float g_wc2[128 * 128];
__device__ int   g_deg[N_NODES];
__device__ int   g_roff[N_NODES + 1];
__device__ int   g_cur[N_NODES];
__device__ int   g_esrc[E_EDGES];
__device__ int   g_bsum[256];
__device__ int   g_boff[256];

// ---------------- helpers ----------------------------------------------------
__device__ __forceinline__ float lrelu(float x) {
    return x > 0.0f ? x : NEG_SLOPE * x;
}

__device__ __forceinline__ uint32_t smem_u32(const void* p) {
    return (uint32_t)__cvta_generic_to_shared(p);
}

__device__ __forceinline__ void ldsm_x4(uint32_t* r, uint32_t addr) {
    asm volatile("ldmatrix.sync.aligned.m8n8.x4.shared.b16 {%0,%1,%2,%3}, [%4];"
        : "=r"(r[0]), "=r"(r[1]), "=r"(r[2]), "=r"(r[3]) : "r"(addr));
}

__device__ __forceinline__ void ldsm_x4_t(uint32_t* r, uint32_t addr) {
    asm volatile("ldmatrix.sync.aligned.m8n8.x4.trans.shared.b16 {%0,%1,%2,%3}, [%4];"
        : "=r"(r[0]), "=r"(r[1]), "=r"(r[2]), "=r"(r[3]) : "r"(addr));
}

__device__ __forceinline__ void mma_bf16(float* d, const uint32_t* a,
                                         const uint32_t* b) {
    asm volatile(
        "mma.sync.aligned.m16n8k16.row.col.f32.bf16.bf16.f32 "
        "{%0,%1,%2,%3}, {%4,%5,%6,%7}, {%8,%9}, {%0,%1,%2,%3};"
        : "+f"(d[0]), "+f"(d[1]), "+f"(d[2]), "+f"(d[3])
        : "r"(a[0]), "r"(a[1]), "r"(a[2]), "r"(a[3]), "r"(b[0]), "r"(b[1]));
}

// ---------------- tensor-core GEMM via mma.sync (bf16 x3 split) --------------
#define APAD 24
#define BPAD 136

struct MmaSmem {
    __align__(16) __nv_bfloat16 Ahi[128 * APAD];
    __align__(16) __nv_bfloat16 Alo[128 * APAD];
    __align__(16) __nv_bfloat16 Bhi[16 * BPAD];
    __align__(16) __nv_bfloat16 Blo[16 * BPAD];
};

__global__ __launch_bounds__(256, 2) void mma_gemm_kernel(
    const float* __restrict__ A, const float* __restrict__ W,
    float* __restrict__ outA, int strideA,
    float* __restrict__ outB, int strideB,
    int M, int K,
    const float* __restrict__ aSrcVec, const float* __restrict__ aDstVec,
    float* __restrict__ als, float* __restrict__ ald)
{
    __shared__ MmaSmem sm[2];

    int tid  = threadIdx.x;
    int wid  = tid >> 5;
    int lane = tid & 31;
    int rowBase = blockIdx.x * 128;

    int warp_m = wid & 1;
    int warp_n = wid >> 1;

    float acc[4][4][4];
    #pragma unroll
    for (int mi = 0; mi < 4; mi++)
        #pragma unroll
        for (int ni = 0; ni < 4; ni++)
            #pragma unroll
            for (int q = 0; q < 4; q++) acc[mi][ni][q] = 0.0f;

    uint32_t aHiB[2] = {smem_u32(sm[0].Ahi), smem_u32(sm[1].Ahi)};
    uint32_t aLoB[2] = {smem_u32(sm[0].Alo), smem_u32(sm[1].Alo)};
    uint32_t bHiB[2] = {smem_u32(sm[0].Bhi), smem_u32(sm[1].Bhi)};
    uint32_t bLoB[2] = {smem_u32(sm[0].Blo), smem_u32(sm[1].Blo)};

    int a_r = (lane & 7) + ((lane >> 3) & 1) * 8;
    int a_c = (lane >> 4) * 8;
    int b_r = lane & 15;
    int b_c = (lane >> 4) * 8;

    int aR[2], aC[2], wR[2], wC[2], arow[2], wrow[2];
    bool aok[2];
    #pragma unroll
    for (int h = 0; h < 2; h++) {
        int i = tid + h * 256;
        aR[h] = i >> 2;  aC[h] = (i & 3) * 4;
        wR[h] = i >> 5;  wC[h] = (i & 31) * 4;
        arow[h] = aR[h] * APAD + aC[h];
        wrow[h] = wR[h] * BPAD + wC[h];
        aok[h]  = (rowBase + aR[h]) < M;
    }

    float4 av[2], wv[2];
    #pragma unroll
    for (int h = 0; h < 2; h++) {
        av[h] = make_float4(0.f, 0.f, 0.f, 0.f);
        if (aok[h]) av[h] = *(const float4*)(A + (size_t)(rowBase + aR[h]) * K + aC[h]);
        wv[h] = *(const float4*)(W + (size_t)wR[h] * 128 + wC[h]);
    }
    #pragma unroll
    for (int h = 0; h < 2; h++) {
        float* vp = (float*)&av[h];
        #pragma unroll
        for (int q = 0; q < 4; q++) {
            __nv_bfloat16 hi = __float2bfloat16(vp[q]);
            sm[0].Ahi[arow[h] + q] = hi;
            sm[0].Alo[arow[h] + q] = __float2bfloat16(vp[q] - __bfloat162float(hi));
        }
        float* wp = (float*)&wv[h];
        #pragma unroll
        for (int q = 0; q < 4; q++) {
            __nv_bfloat16 hi = __float2bfloat16(wp[q]);
            sm[0].Bhi[wrow[h] + q] = hi;
            sm[0].Blo[wrow[h] + q] = __float2bfloat16(wp[q] - __bfloat162float(hi));
        }
    }
    __syncthreads();

    int nchunk = K >> 4;
    for (int c = 0; c < nchunk; c++) {
        int sel = c & 1;
        bool more = (c + 1 < nchunk);
        if (more) {
            int k0n = (c + 1) << 4;
            #pragma unroll
            for (int h = 0; h < 2; h++) {
                av[h] = make_float4(0.f, 0.f, 0.f, 0.f);
                if (aok[h])
                    av[h] = *(const float4*)(A + (size_t)(rowBase + aR[h]) * K + k0n + aC[h]);
                wv[h] = *(const float4*)(W + (size_t)(k0n + wR[h]) * 128 + wC[h]);
            }
        }

        uint32_t bh[2][4], bl[2][4];
        #pragma unroll
        for (int nh = 0; nh < 2; nh++) {
            uint32_t boff = (uint32_t)(b_r * BPAD + warp_n * 32 + nh * 16 + b_c) * 2;
            ldsm_x4_t(bh[nh], bHiB[sel] + boff);
            ldsm_x4_t(bl[nh], bLoB[sel] + boff);
        }
        #pragma unroll
        for (int mi = 0; mi < 4; mi++) {
            uint32_t aoff = (uint32_t)((warp_m * 64 + mi * 16 + a_r) * APAD + a_c) * 2;
            uint32_t ah[4], al[4];
            ldsm_x4(ah, aHiB[sel] + aoff);
            ldsm_x4(al, aLoB[sel] + aoff);
            #pragma unroll
            for (int ni = 0; ni < 4; ni++) {
                const uint32_t* bhp = &bh[ni >> 1][(ni & 1) * 2];
                const uint32_t* blp = &bl[ni >> 1][(ni & 1) * 2];
                mma_bf16(acc[mi][ni], ah, bhp);
                mma_bf16(acc[mi][ni], ah, blp);
                mma_bf16(acc[mi][ni], al, bhp);
            }
        }

        if (more) {
            MmaSmem& dst = sm[sel ^ 1];
            #pragma unroll
            for (int h = 0; h < 2; h++) {
                float* vp = (float*)&av[h];
                #pragma unroll
                for (int q = 0; q < 4; q++) {
                    __nv_bfloat16 hi = __float2bfloat16(vp[q]);
                    dst.Ahi[arow[h] + q] = hi;
                    dst.Alo[arow[h] + q] = __float2bfloat16(vp[q] - __bfloat162float(hi));
                }
                float* wp = (float*)&wv[h];
                #pragma unroll
                for (int q = 0; q < 4; q++) {
                    __nv_bfloat16 hi = __float2bfloat16(wp[q]);
                    dst.Bhi[wrow[h] + q] = hi;
                    dst.Blo[wrow[h] + q] = __float2bfloat16(wp[q] - __bfloat162float(hi));
                }
            }
            __syncthreads();
        }
    }

    int g = lane >> 2, tig = lane & 3;

    #pragma unroll
    for (int mi = 0; mi < 4; mi++) {
        int row = rowBase + warp_m * 64 + mi * 16 + g;
        #pragma unroll
        for (int ni = 0; ni < 4; ni++) {
            int col = warp_n * 32 + ni * 8 + tig * 2;
            float* p0;
            if (col < 64) p0 = outA + (size_t)row * strideA + col;
            else          p0 = outB + (size_t)row * strideB + (col - 64);
            size_t rs = (col < 64) ? (size_t)strideA : (size_t)strideB;
            if (row < M)
                *(float2*)p0 = make_float2(acc[mi][ni][0], acc[mi][ni][1]);
            if (row + 8 < M)
                *(float2*)(p0 + 8 * rs) = make_float2(acc[mi][ni][2], acc[mi][ni][3]);
        }
    }

    if (aSrcVec != nullptr) {
        int head = warp_n >> 1;
        float asv[8], adv[8];
        #pragma unroll
        for (int ni = 0; ni < 4; ni++)
            #pragma unroll
            for (int t = 0; t < 2; t++) {
                int col = warp_n * 32 + ni * 8 + tig * 2 + t;
                asv[ni * 2 + t] = __ldg(aSrcVec + col);
                adv[ni * 2 + t] = __ldg(aDstVec + col);
            }
        #pragma unroll
        for (int mi = 0; mi < 4; mi++) {
            float ps0 = 0.f, pd0 = 0.f, ps1 = 0.f, pd1 = 0.f;
            #pragma unroll
            for (int ni = 0; ni < 4; ni++) {
                ps0 += acc[mi][ni][0] * asv[ni * 2] + acc[mi][ni][1] * asv[ni * 2 + 1];
                pd0 += acc[mi][ni][0] * adv[ni * 2] + acc[mi][ni][1] * adv[ni * 2 + 1];
                ps1 += acc[mi][ni][2] * asv[ni * 2] + acc[mi][ni][3] * asv[ni * 2 + 1];
                pd1 += acc[mi][ni][2] * adv[ni * 2] + acc[mi][ni][3] * adv[ni * 2 + 1];
            }
            #pragma unroll
            for (int o = 1; o < 4; o <<= 1) {
                ps0 += __shfl_xor_sync(0xffffffffu, ps0, o);
                pd0 += __shfl_xor_sync(0xffffffffu, pd0, o);
                ps1 += __shfl_xor_sync(0xffffffffu, ps1, o);
                pd1 += __shfl_xor_sync(0xffffffffu, pd1, o);
            }
            if (tig == 0) {
                int row = rowBase + warp_m * 64 + mi * 16 + g;
                if (row < M) {
                    atomicAdd(&als[row * 2 + head], ps0);
                    atomicAdd(&ald[row * 2 + head], pd0);
                }
                if (row + 8 < M) {
                    atomicAdd(&als[(row + 8) * 2 + head], ps1);
                    atomicAdd(&ald[(row + 8) * 2 + head], pd1);
                }
            }
        }
    }
}

// ---------------- CSR build ---------------------------------------------------
__global__ void hist_kernel(const int* __restrict__ dst, int* __restrict__ deg)
{
    int e = blockIdx.x * blockDim.x + threadIdx.x;
    if (e < E_EDGES) atomicAdd(&deg[dst[e]], 1);
}

// phase 1: block-local exclusive scan of deg -> roff; block totals -> bsum
__global__ __launch_bounds__(256) void scan1_kernel(
    const int* __restrict__ deg, int* __restrict__ roff, int* __restrict__ bsum)
{
    int b = blockIdx.x, t = threadIdx.x;
    int idx = b * 256 + t;
    int v = (idx < N_NODES) ? deg[idx] : 0;
    int lane = t & 31, w = t >> 5;

    int x = v;
    #pragma unroll
    for (int o = 1; o < 32; o <<= 1) {
        int y = __shfl_up_sync(0xffffffffu, x, o);
        if (lane >= o) x += y;
    }
    __shared__ int ws[8];
    if (lane == 31) ws[w] = x;
    __syncthreads();
    if (t < 8) {
        int y = ws[t], z = y;
        #pragma unroll
        for (int o = 1; o < 8; o <<= 1) {
            int q = __shfl_up_sync(0xffu, z, o);
            if (t >= o) z += q;
        }
        ws[t] = z - y;   // exclusive warp offset
    }
    __syncthreads();
    int excl = x - v + ws[w];
    if (idx < N_NODES) roff[idx] = excl;
    if (t == 255) bsum[b] = excl + v;
}

// phase 2: single block exclusive scan of block sums -> boff; total -> roff[N]
__global__ __launch_bounds__(256) void scan2_kernel(
    const int* __restrict__ bsum, int* __restrict__ boff, int* __restrict__ roff)
{
    int t = threadIdx.x;
    int v = (t < SCAN_NB) ? bsum[t] : 0;
    int lane = t & 31, w = t >> 5;
    int x = v;
    #pragma unroll
    for (int o = 1; o < 32; o <<= 1) {
        int y = __shfl_up_sync(0xffffffffu, x, o);
        if (lane >= o) x += y;
    }
    __shared__ int ws[8];
    if (lane == 31) ws[w] = x;
    __syncthreads();
    if (t < 8) {
        int y = ws[t], z = y;
        #pragma unroll
        for (int o = 1; o < 8; o <<= 1) {
            int q = __shfl_up_sync(0xffu, z, o);
            if (t >= o) z += q;
        }
        ws[t] = z - y;
    }
    __syncthreads();
    int excl = x - v + ws[w];
    boff[t] = excl;
    if (t == 255) roff[N_NODES] = excl + v;
}

// phase 3: add block offsets, fill cur
__global__ __launch_bounds__(256) void scan3_kernel(
    int* __restrict__ roff, const int* __restrict__ boff, int* __restrict__ cur)
{
    int idx = blockIdx.x * 256 + threadIdx.x;
    if (idx >= N_NODES) return;
    int r = roff[idx] + boff[blockIdx.x];
    roff[idx] = r;
    cur[idx]  = r;
}

__global__ void scatter_kernel(const int* __restrict__ src,
                               const int* __restrict__ dst,
                               int* __restrict__ cur, int* __restrict__ esrc)
{
    int e = blockIdx.x * blockDim.x + threadIdx.x;
    if (e >= E_EDGES) return;
    int d = dst[e];
    int p = atomicAdd(&cur[d], 1);
    esrc[p] = src[e];
}

// ---------------- fused GAT gather: single pass, 4-way unrolled ---------------
__global__ __launch_bounds__(256) void gat_gather_kernel(
    const int* __restrict__ roff, const int* __restrict__ esrc,
    const float* __restrict__ als, const float* __restrict__ ald,
    const float* __restrict__ h, const float* __restrict__ bias,
    float* __restrict__ out, int relu)
{
    int d = (blockIdx.x * blockDim.x + threadIdx.x) >> 5;
    int lane = threadIdx.x & 31;
    if (d >= N_NODES) return;

    float2 ad = *(const float2*)(ald + 2 * d);
    float2 a_self = *(const float2*)(als + 2 * d);
    int head = (lane >= 16);

    float w_self0 = expf(lrelu(a_self.x + ad.x));
    float w_self1 = expf(lrelu(a_self.y + ad.y));
    float s0 = w_self0, s1 = w_self1;
    float wsh = head ? w_self1 : w_self0;

    float4 hv = *(const float4*)(h + (size_t)d * 128 + lane * 4);
    float4 acc;
    acc.x = wsh * hv.x;
    acc.y = wsh * hv.y;
    acc.z = wsh * hv.z;
    acc.w = wsh * hv.w;

    int beg = roff[d], end = roff[d + 1];
    int i = beg;
    for (; i + 4 <= end; i += 4) {
        int sI[4];
        float2 aI[4];
        float4 vI[4];
        #pragma unroll
        for (int j = 0; j < 4; j++) sI[j] = __ldg(esrc + i + j);
        #pragma unroll
        for (int j = 0; j < 4; j++) aI[j] = *(const float2*)(als + 2 * sI[j]);
        #pragma unroll
        for (int j = 0; j < 4; j++)
            vI[j] = *(const float4*)(h + (size_t)sI[j] * 128 + lane * 4);
        #pragma unroll
        for (int j = 0; j < 4; j++) {
            float w0 = expf(lrelu(aI[j].x + ad.x));
            float w1 = expf(lrelu(aI[j].y + ad.y));
            s0 += w0;
            s1 += w1;
            float wh = head ? w1 : w0;
            acc.x = fmaf(wh, vI[j].x, acc.x);
            acc.y = fmaf(wh, vI[j].y, acc.y);
            acc.z = fmaf(wh, vI[j].z, acc.z);
            acc.w = fmaf(wh, vI[j].w, acc.w);
        }
    }
    for (; i < end; i++) {
        int s = __ldg(esrc + i);
        float2 a = *(const float2*)(als + 2 * s);
        float4 v = *(const float4*)(h + (size_t)s * 128 + lane * 4);
        float w0 = expf(lrelu(a.x + ad.x));
        float w1 = expf(lrelu(a.y + ad.y));
        s0 += w0;
        s1 += w1;
        float wh = head ? w1 : w0;
        acc.x = fmaf(wh, v.x, acc.x);
        acc.y = fmaf(wh, v.y, acc.y);
        acc.z = fmaf(wh, v.z, acc.z);
        acc.w = fmaf(wh, v.w, acc.w);
    }

    float inv = 1.0f / (head ? s1 : s0);
    float4 b = *(const float4*)(bias + lane * 4);
    acc.x = fmaf(acc.x, inv, b.x);
    acc.y = fmaf(acc.y, inv, b.y);
    acc.z = fmaf(acc.z, inv, b.z);
    acc.w = fmaf(acc.w, inv, b.w);
    if (relu) {
        acc.x = fmaxf(acc.x, 0.0f);
        acc.y = fmaxf(acc.y, 0.0f);
        acc.z = fmaxf(acc.z, 0.0f);
        acc.w = fmaxf(acc.w, 0.0f);
    }
    *(float4*)(out + (size_t)d * 128 + lane * 4) = acc;
}

// ---------------- weight concat for fused SAGE GEMM --------------------------
__global__ void concat_w_kernel(const float* __restrict__ wl,
                                const float* __restrict__ wr,
                                float* __restrict__ wc, int K)
{
    int i = blockIdx.x * blockDim.x + threadIdx.x;
    if (i >= K * 64) return;
    int k = i >> 6, c = i & 63;
    wc[k * 128 + c]      = wl[i];
    wc[k * 128 + 64 + c] = wr[i];
}

// ---------------- fused SAGE gather (mean + bias + root + relu [+ BN]) -------
__global__ __launch_bounds__(256) void sage_gather_kernel(
    const int* __restrict__ roff, const int* __restrict__ esrc,
    const float* __restrict__ y, const float* __restrict__ bl,
    const float* __restrict__ r, float* __restrict__ out,
    const float* __restrict__ gamma, const float* __restrict__ beta,
    const float* __restrict__ mean, const float* __restrict__ var,
    int do_bn)
{
    int d = (blockIdx.x * blockDim.x + threadIdx.x) >> 5;
    int lane = threadIdx.x & 31;
    if (d >= N_NODES) return;

    int beg = roff[d], end = roff[d + 1];
    float ax = 0.0f, ay = 0.0f;
    int i = beg;
    for (; i + 4 <= end; i += 4) {
        int sI[4];
        float2 vI[4];
        #pragma unroll
        for (int j = 0; j < 4; j++) sI[j] = __ldg(esrc + i + j);
        #pragma unroll
        for (int j = 0; j < 4; j++)
            vI[j] = *(const float2*)(y + (size_t)sI[j] * 64 + lane * 2);
        #pragma unroll
        for (int j = 0; j < 4; j++) { ax += vI[j].x; ay += vI[j].y; }
    }
    for (; i < end; i++) {
        int s = __ldg(esrc + i);
        float2 v = *(const float2*)(y + (size_t)s * 64 + lane * 2);
        ax += v.x;
        ay += v.y;
    }
    float invc = 1.0f / fmaxf((float)(end - beg), 1.0f);
    int c = lane * 2;
    float2 bb = *(const float2*)(bl + c);
    float2 rr = *(const float2*)(r + (size_t)d * 64 + c);
    float vx = fmaxf(ax * invc + bb.x + rr.x, 0.0f);
    float vy = fmaxf(ay * invc + bb.y + rr.y, 0.0f);
    if (do_bn) {
        float sx = gamma[c]     * rsqrtf(var[c]     + BN_EPS);
        float sy = gamma[c + 1] * rsqrtf(var[c + 1] + BN_EPS);
        vx = (vx - mean[c])     * sx + beta[c];
        vy = (vy - mean[c + 1]) * sy + beta[c + 1];
    }
    *(float2*)(out + (size_t)d * 64 + c) = make_float2(vx, vy);
}

// ---------------- host orchestration -----------------------------------------
extern "C" void kernel_launch(void* const* d_in, const int* in_sizes, int n_in,
                              void* d_out, int out_size)
{
    const float* x      = (const float*)d_in[0];
    const int*   ei     = (const int*)d_in[1];
    const float* W1     = (const float*)d_in[2];
    const float* a_src1 = (const float*)d_in[3];
    const float* a_dst1 = (const float*)d_in[4];
    const float* b1     = (const float*)d_in[5];
    const float* W2     = (const float*)d_in[6];
    const float* a_src2 = (const float*)d_in[7];
    const float* a_dst2 = (const float*)d_in[8];
    const float* b2     = (const float*)d_in[9];
    const float* s1wl   = (const float*)d_in[10];
    const float* s1bl   = (const float*)d_in[11];
    const float* s1wr   = (const float*)d_in[12];
    const float* s2wl   = (const float*)d_in[13];
    const float* s2bl   = (const float*)d_in[14];
    const float* s2wr   = (const float*)d_in[15];
    const float* bng    = (const float*)d_in[16];
    const float* bnb    = (const float*)d_in[17];
    const float* bnm    = (const float*)d_in[18];
    const float* bnv    = (const float*)d_in[19];
    float* out = (float*)d_out;

    const int* src = ei;
    const int* dst = ei + E_EDGES;

    float *A, *B, *C, *D, *Ebuf, *F, *als, *ald, *wc1, *wc2;
    int *deg, *roff, *cur, *esrc, *bsum, *boff;
    cudaGetSymbolAddress((void**)&A,    g_bufA);
    cudaGetSymbolAddress((void**)&B,    g_bufB);
    cudaGetSymbolAddress((void**)&C,    g_bufC);
    cudaGetSymbolAddress((void**)&D,    g_bufD);
    cudaGetSymbolAddress((void**)&Ebuf, g_bufE);
    cudaGetSymbolAddress((void**)&F,    g_bufF);
    cudaGetSymbolAddress((void**)&als,  g_als);
    cudaGetSymbolAddress((void**)&ald,  g_ald);
    cudaGetSymbolAddress((void**)&wc1,  g_wc1);
    cudaGetSymbolAddress((void**)&wc2,  g_wc2);
    cudaGetSymbolAddress((void**)&deg,  g_deg);
    cudaGetSymbolAddress((void**)&roff, g_roff);
    cudaGetSymbolAddress((void**)&cur,  g_cur);
    cudaGetSymbolAddress((void**)&esrc, g_esrc);
    cudaGetSymbolAddress((void**)&bsum, g_bsum);
    cudaGetSymbolAddress((void**)&boff, g_boff);

    static cudaStream_t s_side = nullptr;
    static cudaEvent_t ev_fork = nullptr, ev_join = nullptr;
    if (s_side == nullptr) {
        cudaStreamCreateWithFlags(&s_side, cudaStreamNonBlocking);
        cudaEventCreateWithFlags(&ev_fork, cudaEventDisableTiming);
        cudaEventCreateWithFlags(&ev_join, cudaEventDisableTiming);
    }

    int gemmBlocks   = (N_NODES + 127) / 128;
    int gatherBlocks = (N_NODES * 32 + 255) / 256;

    // ---- fork: CSR build + weight concats on side stream ----
    cudaEventRecord(ev_fork, 0);
    cudaStreamWaitEvent(s_side, ev_fork, 0);
    cudaMemsetAsync(deg, 0, N_NODES * sizeof(int), s_side);
    hist_kernel<<<(E_EDGES + 255) / 256, 256, 0, s_side>>>(dst, deg);
    scan1_kernel<<<SCAN_NB, 256, 0, s_side>>>(deg, roff, bsum);
    scan2_kernel<<<1, 256, 0, s_side>>>(bsum, boff, roff);
    scan3_kernel<<<SCAN_NB, 256, 0, s_side>>>(roff, boff, cur);
    scatter_kernel<<<(E_EDGES + 255) / 256, 256, 0, s_side>>>(src, dst, cur, esrc);
    concat_w_kernel<<<(128 * 64 + 255) / 256, 256, 0, s_side>>>(s1wl, s1wr, wc1, 128);
    concat_w_kernel<<<(64 * 64 + 255) / 256, 256, 0, s_side>>>(s2wl, s2wr, wc2, 64);
    cudaEventRecord(ev_join, s_side);

    // ---- main stream: GAT layer 1 GEMM (with fused al) ----
    cudaMemsetAsync(als, 0, N_NODES * 2 * sizeof(float), 0);
    cudaMemsetAsync(ald, 0, N_NODES * 2 * sizeof(float), 0);
    mma_gemm_kernel<<<gemmBlocks, 256>>>(x, W1, A, 128, A + 64, 128,
                                         N_NODES, 256, a_src1, a_dst1, als, ald);

    // ---- join: gathers need CSR ----
    cudaStreamWaitEvent(0, ev_join, 0);
    gat_gather_kernel<<<gatherBlocks, 256>>>(roff, esrc, als, ald, A, b1, B, 1);

    // ---- GAT layer 2 ----
    cudaMemsetAsync(als, 0, N_NODES * 2 * sizeof(float), 0);
    cudaMemsetAsync(ald, 0, N_NODES * 2 * sizeof(float), 0);
    mma_gemm_kernel<<<gemmBlocks, 256>>>(B, W2, C, 128, C + 64, 128,
                                         N_NODES, 128, a_src2, a_dst2, als, ald);
    gat_gather_kernel<<<gatherBlocks, 256>>>(roff, esrc, als, ald, C, b2, A, 0);

    // ---- SAGE layer 1 ----
    mma_gemm_kernel<<<gemmBlocks, 256>>>(A, wc1, D, 64, Ebuf, 64, N_NODES, 128,
                                         nullptr, nullptr, nullptr, nullptr);
    sage_gather_kernel<<<gatherBlocks, 256>>>(roff, esrc, D, s1bl, Ebuf, F,
                                              nullptr, nullptr, nullptr, nullptr, 0);

    // ---- SAGE layer 2 + BN fused ----
    mma_gemm_kernel<<<gemmBlocks, 256>>>(F, wc2, D, 64, Ebuf, 64, N_NODES, 64,
                                         nullptr, nullptr, nullptr, nullptr);
    sage_gather_kernel<<<gatherBlocks, 256>>>(roff, esrc, D, s2bl, Ebuf, out,
                                              bng, bnb, bnm, bnv, 1);
}

// round 9
// speedup vs baseline: 1.2058x; 1.0186x over previous
#include <cuda_runtime.h>
#include <cuda_bf16.h>
#include <math.h>
#include <stdint.h>

#define N_NODES 50000
#define E_EDGES 1600000
#define NEG_SLOPE 0.2f
#define BN_EPS 1e-5f
#define SCAN_NB ((N_NODES + 255) / 256)   // 196

// ---------------- scratch (static device globals; no allocation) ------------
__device__ float g_bufA[(size_t)N_NODES * 128];
__device__ float g_bufB[(size_t)N_NODES * 128];
__device__ float g_bufC[(size_t)N_NODES * 128];
__device__ float g_bufD[(size_t)N_NODES * 64];
__device__ float g_bufE[(size_t)N_NODES * 64];
__device__ float g_bufF[(size_t)N_NODES * 64];
__device__ float g_als1[N_NODES * 2];
__device__ float g_ald1[N_NODES * 2];
__device__ float g_als2[N_NODES * 2];
__device__ float g_ald2[N_NODES * 2];
__device__ float g_wc1[128 * 128];
__device__ float g_wc2[128 * 128];
__device__ int   g_deg[N_NODES];
__device__ int   g_roff[N_NODES + 1];
__device__ int   g_cur[N_NODES];
__device__ int   g_esrc[E_EDGES];
__device__ int   g_bsum[256];
__device__ int   g_boff[256];

// ---------------- helpers ----------------------------------------------------
__device__ __forceinline__ float lrelu(float x) {
    return x > 0.0f ? x : NEG_SLOPE * x;
}

__device__ __forceinline__ uint32_t smem_u32(const void* p) {
    return (uint32_t)__cvta_generic_to_shared(p);
}

__device__ __forceinline__ void ldsm_x4(uint32_t* r, uint32_t addr) {
    asm volatile("ldmatrix.sync.aligned.m8n8.x4.shared.b16 {%0,%1,%2,%3}, [%4];"
        : "=r"(r[0]), "=r"(r[1]), "=r"(r[2]), "=r"(r[3]) : "r"(addr));
}

__device__ __forceinline__ void ldsm_x4_t(uint32_t* r, uint32_t addr) {
    asm volatile("ldmatrix.sync.aligned.m8n8.x4.trans.shared.b16 {%0,%1,%2,%3}, [%4];"
        : "=r"(r[0]), "=r"(r[1]), "=r"(r[2]), "=r"(r[3]) : "r"(addr));
}

__device__ __forceinline__ void mma_bf16(float* d, const uint32_t* a,
                                         const uint32_t* b) {
    asm volatile(
        "mma.sync.aligned.m16n8k16.row.col.f32.bf16.bf16.f32 "
        "{%0,%1,%2,%3}, {%4,%5,%6,%7}, {%8,%9}, {%0,%1,%2,%3};"
        : "+f"(d[0]), "+f"(d[1]), "+f"(d[2]), "+f"(d[3])
        : "r"(a[0]), "r"(a[1]), "r"(a[2]), "r"(a[3]), "r"(b[0]), "r"(b[1]));
}

// ---------------- tensor-core GEMM via mma.sync (bf16 x3 split) --------------
// BM=64 tile, 256 threads (8 warps x 64x16), double-buffered, reg prefetch.
#define APAD 24
#define BPAD 136

struct MmaSmem {
    __align__(16) __nv_bfloat16 Ahi[64 * APAD];
    __align__(16) __nv_bfloat16 Alo[64 * APAD];
    __align__(16) __nv_bfloat16 Bhi[16 * BPAD];
    __align__(16) __nv_bfloat16 Blo[16 * BPAD];
};

__global__ __launch_bounds__(256, 3) void mma_gemm_kernel(
    const float* __restrict__ A, const float* __restrict__ W,
    float* __restrict__ outA, int strideA,
    float* __restrict__ outB, int strideB,
    int M, int K,
    const float* __restrict__ aSrcVec, const float* __restrict__ aDstVec,
    float* __restrict__ als, float* __restrict__ ald)
{
    __shared__ MmaSmem sm[2];

    int tid  = threadIdx.x;
    int w    = tid >> 5;            // warp = n-segment 0..7 (16 cols each)
    int lane = tid & 31;
    int rowBase = blockIdx.x * 64;

    float acc[4][2][4];
    #pragma unroll
    for (int mi = 0; mi < 4; mi++)
        #pragma unroll
        for (int ni = 0; ni < 2; ni++)
            #pragma unroll
            for (int q = 0; q < 4; q++) acc[mi][ni][q] = 0.0f;

    uint32_t aHiB[2] = {smem_u32(sm[0].Ahi), smem_u32(sm[1].Ahi)};
    uint32_t aLoB[2] = {smem_u32(sm[0].Alo), smem_u32(sm[1].Alo)};
    uint32_t bHiB[2] = {smem_u32(sm[0].Bhi), smem_u32(sm[1].Bhi)};
    uint32_t bLoB[2] = {smem_u32(sm[0].Blo), smem_u32(sm[1].Blo)};

    int a_r = (lane & 7) + ((lane >> 3) & 1) * 8;
    int a_c = (lane >> 4) * 8;
    int b_r = lane & 15;
    int b_c = (lane >> 4) * 8;

    // A tile: 64x16 floats = 256 float4, 1 per thread
    int aR = tid >> 2, aC = (tid & 3) * 4;
    int arow = aR * APAD + aC;
    bool aok = (rowBase + aR) < M;
    // B tile: 16x128 floats = 512 float4, 2 per thread
    int wR[2], wC[2], wrow[2];
    #pragma unroll
    for (int h = 0; h < 2; h++) {
        int i = tid + h * 256;
        wR[h] = i >> 5;  wC[h] = (i & 31) * 4;
        wrow[h] = wR[h] * BPAD + wC[h];
    }

    float4 av, wv[2];
    av = make_float4(0.f, 0.f, 0.f, 0.f);
    if (aok) av = *(const float4*)(A + (size_t)(rowBase + aR) * K + aC);
    #pragma unroll
    for (int h = 0; h < 2; h++)
        wv[h] = *(const float4*)(W + (size_t)wR[h] * 128 + wC[h]);

    {   // store chunk 0
        float* vp = (float*)&av;
        #pragma unroll
        for (int q = 0; q < 4; q++) {
            __nv_bfloat16 hi = __float2bfloat16(vp[q]);
            sm[0].Ahi[arow + q] = hi;
            sm[0].Alo[arow + q] = __float2bfloat16(vp[q] - __bfloat162float(hi));
        }
        #pragma unroll
        for (int h = 0; h < 2; h++) {
            float* wp = (float*)&wv[h];
            #pragma unroll
            for (int q = 0; q < 4; q++) {
                __nv_bfloat16 hi = __float2bfloat16(wp[q]);
                sm[0].Bhi[wrow[h] + q] = hi;
                sm[0].Blo[wrow[h] + q] = __float2bfloat16(wp[q] - __bfloat162float(hi));
            }
        }
    }
    __syncthreads();

    int nchunk = K >> 4;
    for (int c = 0; c < nchunk; c++) {
        int sel = c & 1;
        bool more = (c + 1 < nchunk);
        if (more) {
            int k0n = (c + 1) << 4;
            av = make_float4(0.f, 0.f, 0.f, 0.f);
            if (aok) av = *(const float4*)(A + (size_t)(rowBase + aR) * K + k0n + aC);
            #pragma unroll
            for (int h = 0; h < 2; h++)
                wv[h] = *(const float4*)(W + (size_t)(k0n + wR[h]) * 128 + wC[h]);
        }

        uint32_t bh[4], bl[4];
        {
            uint32_t boff = (uint32_t)(b_r * BPAD + w * 16 + b_c) * 2;
            ldsm_x4_t(bh, bHiB[sel] + boff);
            ldsm_x4_t(bl, bLoB[sel] + boff);
        }
        #pragma unroll
        for (int mi = 0; mi < 4; mi++) {
            uint32_t aoff = (uint32_t)((mi * 16 + a_r) * APAD + a_c) * 2;
            uint32_t ah[4], al[4];
            ldsm_x4(ah, aHiB[sel] + aoff);
            ldsm_x4(al, aLoB[sel] + aoff);
            #pragma unroll
            for (int ni = 0; ni < 2; ni++) {
                mma_bf16(acc[mi][ni], ah, &bh[ni * 2]);
                mma_bf16(acc[mi][ni], ah, &bl[ni * 2]);
                mma_bf16(acc[mi][ni], al, &bh[ni * 2]);
            }
        }

        if (more) {
            MmaSmem& dst = sm[sel ^ 1];
            float* vp = (float*)&av;
            #pragma unroll
            for (int q = 0; q < 4; q++) {
                __nv_bfloat16 hi = __float2bfloat16(vp[q]);
                dst.Ahi[arow + q] = hi;
                dst.Alo[arow + q] = __float2bfloat16(vp[q] - __bfloat162float(hi));
            }
            #pragma unroll
            for (int h = 0; h < 2; h++) {
                float* wp = (float*)&wv[h];
                #pragma unroll
                for (int q = 0; q < 4; q++) {
                    __nv_bfloat16 hi = __float2bfloat16(wp[q]);
                    dst.Bhi[wrow[h] + q] = hi;
                    dst.Blo[wrow[h] + q] = __float2bfloat16(wp[q] - __bfloat162float(hi));
                }
            }
            __syncthreads();
        }
    }

    int g = lane >> 2, tig = lane & 3;

    // write output (split columns across outA/outB)
    #pragma unroll
    for (int mi = 0; mi < 4; mi++) {
        int row = rowBase + mi * 16 + g;
        #pragma unroll
        for (int ni = 0; ni < 2; ni++) {
            int col = w * 16 + ni * 8 + tig * 2;
            float* p0;
            if (col < 64) p0 = outA + (size_t)row * strideA + col;
            else          p0 = outB + (size_t)row * strideB + (col - 64);
            size_t rs = (col < 64) ? (size_t)strideA : (size_t)strideB;
            if (row < M)
                *(float2*)p0 = make_float2(acc[mi][ni][0], acc[mi][ni][1]);
            if (row + 8 < M)
                *(float2*)(p0 + 8 * rs) = make_float2(acc[mi][ni][2], acc[mi][ni][3]);
        }
    }

    // fused attention-logit epilogue: head = w>>2 (cols 0-63 = head0)
    if (aSrcVec != nullptr) {
        int head = w >> 2;
        float asv[4], adv[4];
        #pragma unroll
        for (int ni = 0; ni < 2; ni++)
            #pragma unroll
            for (int t = 0; t < 2; t++) {
                int col = w * 16 + ni * 8 + tig * 2 + t;
                asv[ni * 2 + t] = __ldg(aSrcVec + col);
                adv[ni * 2 + t] = __ldg(aDstVec + col);
            }
        #pragma unroll
        for (int mi = 0; mi < 4; mi++) {
            float ps0 = 0.f, pd0 = 0.f, ps1 = 0.f, pd1 = 0.f;
            #pragma unroll
            for (int ni = 0; ni < 2; ni++) {
                ps0 += acc[mi][ni][0] * asv[ni * 2] + acc[mi][ni][1] * asv[ni * 2 + 1];
                pd0 += acc[mi][ni][0] * adv[ni * 2] + acc[mi][ni][1] * adv[ni * 2 + 1];
                ps1 += acc[mi][ni][2] * asv[ni * 2] + acc[mi][ni][3] * asv[ni * 2 + 1];
                pd1 += acc[mi][ni][2] * adv[ni * 2] + acc[mi][ni][3] * adv[ni * 2 + 1];
            }
            #pragma unroll
            for (int o = 1; o < 4; o <<= 1) {
                ps0 += __shfl_xor_sync(0xffffffffu, ps0, o);
                pd0 += __shfl_xor_sync(0xffffffffu, pd0, o);
                ps1 += __shfl_xor_sync(0xffffffffu, ps1, o);
                pd1 += __shfl_xor_sync(0xffffffffu, pd1, o);
            }
            if (tig == 0) {
                int row = rowBase + mi * 16 + g;
                if (row < M) {
                    atomicAdd(&als[row * 2 + head], ps0);
                    atomicAdd(&ald[row * 2 + head], pd0);
                }
                if (row + 8 < M) {
                    atomicAdd(&als[(row + 8) * 2 + head], ps1);
                    atomicAdd(&ald[(row + 8) * 2 + head], pd1);
                }
            }
        }
    }
}

// ---------------- CSR build ---------------------------------------------------
__global__ void hist_kernel(const int* __restrict__ dst, int* __restrict__ deg)
{
    int e = blockIdx.x * blockDim.x + threadIdx.x;
    if (e < E_EDGES) atomicAdd(&deg[dst[e]], 1);
}

__global__ __launch_bounds__(256) void scan1_kernel(
    const int* __restrict__ deg, int* __restrict__ roff, int* __restrict__ bsum)
{
    int b = blockIdx.x, t = threadIdx.x;
    int idx = b * 256 + t;
    int v = (idx < N_NODES) ? deg[idx] : 0;
    int lane = t & 31, w = t >> 5;

    int x = v;
    #pragma unroll
    for (int o = 1; o < 32; o <<= 1) {
        int y = __shfl_up_sync(0xffffffffu, x, o);
        if (lane >= o) x += y;
    }
    __shared__ int ws[8];
    if (lane == 31) ws[w] = x;
    __syncthreads();
    if (t < 8) {
        int y = ws[t], z = y;
        #pragma unroll
        for (int o = 1; o < 8; o <<= 1) {
            int q = __shfl_up_sync(0xffu, z, o);
            if (t >= o) z += q;
        }
        ws[t] = z - y;
    }
    __syncthreads();
    int excl = x - v + ws[w];
    if (idx < N_NODES) roff[idx] = excl;
    if (t == 255) bsum[b] = excl + v;
}

__global__ __launch_bounds__(256) void scan2_kernel(
    const int* __restrict__ bsum, int* __restrict__ boff, int* __restrict__ roff)
{
    int t = threadIdx.x;
    int v = (t < SCAN_NB) ? bsum[t] : 0;
    int lane = t & 31, w = t >> 5;
    int x = v;
    #pragma unroll
    for (int o = 1; o < 32; o <<= 1) {
        int y = __shfl_up_sync(0xffffffffu, x, o);
        if (lane >= o) x += y;
    }
    __shared__ int ws[8];
    if (lane == 31) ws[w] = x;
    __syncthreads();
    if (t < 8) {
        int y = ws[t], z = y;
        #pragma unroll
        for (int o = 1; o < 8; o <<= 1) {
            int q = __shfl_up_sync(0xffu, z, o);
            if (t >= o) z += q;
        }
        ws[t] = z - y;
    }
    __syncthreads();
    int excl = x - v + ws[w];
    boff[t] = excl;
    if (t == 255) roff[N_NODES] = excl + v;
}

__global__ __launch_bounds__(256) void scan3_kernel(
    int* __restrict__ roff, const int* __restrict__ boff, int* __restrict__ cur)
{
    int idx = blockIdx.x * 256 + threadIdx.x;
    if (idx >= N_NODES) return;
    int r = roff[idx] + boff[blockIdx.x];
    roff[idx] = r;
    cur[idx]  = r;
}

__global__ void scatter_kernel(const int* __restrict__ src,
                               const int* __restrict__ dst,
                               int* __restrict__ cur, int* __restrict__ esrc)
{
    int e = blockIdx.x * blockDim.x + threadIdx.x;
    if (e >= E_EDGES) return;
    int d = dst[e];
    int p = atomicAdd(&cur[d], 1);
    esrc[p] = src[e];
}

// ---------------- fused GAT gather: single pass, 4-way unrolled ---------------
__global__ __launch_bounds__(256) void gat_gather_kernel(
    const int* __restrict__ roff, const int* __restrict__ esrc,
    const float* __restrict__ als, const float* __restrict__ ald,
    const float* __restrict__ h, const float* __restrict__ bias,
    float* __restrict__ out, int relu)
{
    int d = (blockIdx.x * blockDim.x + threadIdx.x) >> 5;
    int lane = threadIdx.x & 31;
    if (d >= N_NODES) return;

    float2 ad = *(const float2*)(ald + 2 * d);
    float2 a_self = *(const float2*)(als + 2 * d);
    int head = (lane >= 16);

    float w_self0 = expf(lrelu(a_self.x + ad.x));
    float w_self1 = expf(lrelu(a_self.y + ad.y));
    float s0 = w_self0, s1 = w_self1;
    float wsh = head ? w_self1 : w_self0;

    float4 hv = *(const float4*)(h + (size_t)d * 128 + lane * 4);
    float4 acc;
    acc.x = wsh * hv.x;
    acc.y = wsh * hv.y;
    acc.z = wsh * hv.z;
    acc.w = wsh * hv.w;

    int beg = roff[d], end = roff[d + 1];
    int i = beg;
    for (; i + 4 <= end; i += 4) {
        int sI[4];
        float2 aI[4];
        float4 vI[4];
        #pragma unroll
        for (int j = 0; j < 4; j++) sI[j] = __ldg(esrc + i + j);
        #pragma unroll
        for (int j = 0; j < 4; j++) aI[j] = *(const float2*)(als + 2 * sI[j]);
        #pragma unroll
        for (int j = 0; j < 4; j++)
            vI[j] = *(const float4*)(h + (size_t)sI[j] * 128 + lane * 4);
        #pragma unroll
        for (int j = 0; j < 4; j++) {
            float w0 = expf(lrelu(aI[j].x + ad.x));
            float w1 = expf(lrelu(aI[j].y + ad.y));
            s0 += w0;
            s1 += w1;
            float wh = head ? w1 : w0;
            acc.x = fmaf(wh, vI[j].x, acc.x);
            acc.y = fmaf(wh, vI[j].y, acc.y);
            acc.z = fmaf(wh, vI[j].z, acc.z);
            acc.w = fmaf(wh, vI[j].w, acc.w);
        }
    }
    for (; i < end; i++) {
        int s = __ldg(esrc + i);
        float2 a = *(const float2*)(als + 2 * s);
        float4 v = *(const float4*)(h + (size_t)s * 128 + lane * 4);
        float w0 = expf(lrelu(a.x + ad.x));
        float w1 = expf(lrelu(a.y + ad.y));
        s0 += w0;
        s1 += w1;
        float wh = head ? w1 : w0;
        acc.x = fmaf(wh, v.x, acc.x);
        acc.y = fmaf(wh, v.y, acc.y);
        acc.z = fmaf(wh, v.z, acc.z);
        acc.w = fmaf(wh, v.w, acc.w);
    }

    float inv = 1.0f / (head ? s1 : s0);
    float4 b = *(const float4*)(bias + lane * 4);
    acc.x = fmaf(acc.x, inv, b.x);
    acc.y = fmaf(acc.y, inv, b.y);
    acc.z = fmaf(acc.z, inv, b.z);
    acc.w = fmaf(acc.w, inv, b.w);
    if (relu) {
        acc.x = fmaxf(acc.x, 0.0f);
        acc.y = fmaxf(acc.y, 0.0f);
        acc.z = fmaxf(acc.z, 0.0f);
        acc.w = fmaxf(acc.w, 0.0f);
    }
    *(float4*)(out + (size_t)d * 128 + lane * 4) = acc;
}

// ---------------- weight concat for fused SAGE GEMM --------------------------
__global__ void concat_w_kernel(const float* __restrict__ wl,
                                const float* __restrict__ wr,
                                float* __restrict__ wc, int K)
{
    int i = blockIdx.x * blockDim.x + threadIdx.x;
    if (i >= K * 64) return;
    int k = i >> 6, c = i & 63;
    wc[k * 128 + c]      = wl[i];
    wc[k * 128 + 64 + c] = wr[i];
}

// ---------------- fused SAGE gather (mean + bias + root + relu [+ BN]) -------
__global__ __launch_bounds__(256) void sage_gather_kernel(
    const int* __restrict__ roff, const int* __restrict__ esrc,
    const float* __restrict__ y, const float* __restrict__ bl,
    const float* __restrict__ r, float* __restrict__ out,
    const float* __restrict__ gamma, const float* __restrict__ beta,
    const float* __restrict__ mean, const float* __restrict__ var,
    int do_bn)
{
    int d = (blockIdx.x * blockDim.x + threadIdx.x) >> 5;
    int lane = threadIdx.x & 31;
    if (d >= N_NODES) return;

    int beg = roff[d], end = roff[d + 1];
    float ax = 0.0f, ay = 0.0f;
    int i = beg;
    for (; i + 4 <= end; i += 4) {
        int sI[4];
        float2 vI[4];
        #pragma unroll
        for (int j = 0; j < 4; j++) sI[j] = __ldg(esrc + i + j);
        #pragma unroll
        for (int j = 0; j < 4; j++)
            vI[j] = *(const float2*)(y + (size_t)sI[j] * 64 + lane * 2);
        #pragma unroll
        for (int j = 0; j < 4; j++) { ax += vI[j].x; ay += vI[j].y; }
    }
    for (; i < end; i++) {
        int s = __ldg(esrc + i);
        float2 v = *(const float2*)(y + (size_t)s * 64 + lane * 2);
        ax += v.x;
        ay += v.y;
    }
    float invc = 1.0f / fmaxf((float)(end - beg), 1.0f);
    int c = lane * 2;
    float2 bb = *(const float2*)(bl + c);
    float2 rr = *(const float2*)(r + (size_t)d * 64 + c);
    float vx = fmaxf(ax * invc + bb.x + rr.x, 0.0f);
    float vy = fmaxf(ay * invc + bb.y + rr.y, 0.0f);
    if (do_bn) {
        float sx = gamma[c]     * rsqrtf(var[c]     + BN_EPS);
        float sy = gamma[c + 1] * rsqrtf(var[c + 1] + BN_EPS);
        vx = (vx - mean[c])     * sx + beta[c];
        vy = (vy - mean[c + 1]) * sy + beta[c + 1];
    }
    *(float2*)(out + (size_t)d * 64 + c) = make_float2(vx, vy);
}

// ---------------- host orchestration -----------------------------------------
extern "C" void kernel_launch(void* const* d_in, const int* in_sizes, int n_in,
                              void* d_out, int out_size)
{
    const float* x      = (const float*)d_in[0];
    const int*   ei     = (const int*)d_in[1];
    const float* W1     = (const float*)d_in[2];
    const float* a_src1 = (const float*)d_in[3];
    const float* a_dst1 = (const float*)d_in[4];
    const float* b1     = (const float*)d_in[5];
    const float* W2     = (const float*)d_in[6];
    const float* a_src2 = (const float*)d_in[7];
    const float* a_dst2 = (const float*)d_in[8];
    const float* b2     = (const float*)d_in[9];
    const float* s1wl   = (const float*)d_in[10];
    const float* s1bl   = (const float*)d_in[11];
    const float* s1wr   = (const float*)d_in[12];
    const float* s2wl   = (const float*)d_in[13];
    const float* s2bl   = (const float*)d_in[14];
    const float* s2wr   = (const float*)d_in[15];
    const float* bng    = (const float*)d_in[16];
    const float* bnb    = (const float*)d_in[17];
    const float* bnm    = (const float*)d_in[18];
    const float* bnv    = (const float*)d_in[19];
    float* out = (float*)d_out;

    const int* src = ei;
    const int* dst = ei + E_EDGES;

    float *A, *B, *C, *D, *Ebuf, *F, *als1, *ald1, *als2, *ald2, *wc1, *wc2;
    int *deg, *roff, *cur, *esrc, *bsum, *boff;
    cudaGetSymbolAddress((void**)&A,    g_bufA);
    cudaGetSymbolAddress((void**)&B,    g_bufB);
    cudaGetSymbolAddress((void**)&C,    g_bufC);
    cudaGetSymbolAddress((void**)&D,    g_bufD);
    cudaGetSymbolAddress((void**)&Ebuf, g_bufE);
    cudaGetSymbolAddress((void**)&F,    g_bufF);
    cudaGetSymbolAddress((void**)&als1, g_als1);
    cudaGetSymbolAddress((void**)&ald1, g_ald1);
    cudaGetSymbolAddress((void**)&als2, g_als2);
    cudaGetSymbolAddress((void**)&ald2, g_ald2);
    cudaGetSymbolAddress((void**)&wc1,  g_wc1);
    cudaGetSymbolAddress((void**)&wc2,  g_wc2);
    cudaGetSymbolAddress((void**)&deg,  g_deg);
    cudaGetSymbolAddress((void**)&roff, g_roff);
    cudaGetSymbolAddress((void**)&cur,  g_cur);
    cudaGetSymbolAddress((void**)&esrc, g_esrc);
    cudaGetSymbolAddress((void**)&bsum, g_bsum);
    cudaGetSymbolAddress((void**)&boff, g_boff);

    static cudaStream_t s_side = nullptr;
    static cudaEvent_t ev_fork = nullptr, ev_join = nullptr;
    if (s_side == nullptr) {
        cudaStreamCreateWithFlags(&s_side, cudaStreamNonBlocking);
        cudaEventCreateWithFlags(&ev_fork, cudaEventDisableTiming);
        cudaEventCreateWithFlags(&ev_join, cudaEventDisableTiming);
    }

    int gemmBlocks   = (N_NODES + 63) / 64;
    int gatherBlocks = (N_NODES * 32 + 255) / 256;

    // ---- fork: CSR build + weight concats + layer-2 al zeroing (side) ----
    cudaEventRecord(ev_fork, 0);
    cudaStreamWaitEvent(s_side, ev_fork, 0);
    cudaMemsetAsync(deg, 0, N_NODES * sizeof(int), s_side);
    cudaMemsetAsync(als2, 0, N_NODES * 2 * sizeof(float), s_side);
    cudaMemsetAsync(ald2, 0, N_NODES * 2 * sizeof(float), s_side);
    hist_kernel<<<(E_EDGES + 255) / 256, 256, 0, s_side>>>(dst, deg);
    scan1_kernel<<<SCAN_NB, 256, 0, s_side>>>(deg, roff, bsum);
    scan2_kernel<<<1, 256, 0, s_side>>>(bsum, boff, roff);
    scan3_kernel<<<SCAN_NB, 256, 0, s_side>>>(roff, boff, cur);
    scatter_kernel<<<(E_EDGES + 255) / 256, 256, 0, s_side>>>(src, dst, cur, esrc);
    concat_w_kernel<<<(128 * 64 + 255) / 256, 256, 0, s_side>>>(s1wl, s1wr, wc1, 128);
    concat_w_kernel<<<(64 * 64 + 255) / 256, 256, 0, s_side>>>(s2wl, s2wr, wc2, 64);
    cudaEventRecord(ev_join, s_side);

    // ---- main: GAT layer 1 GEMM (fused al) ----
    cudaMemsetAsync(als1, 0, N_NODES * 2 * sizeof(float), 0);
    cudaMemsetAsync(ald1, 0, N_NODES * 2 * sizeof(float), 0);
    mma_gemm_kernel<<<gemmBlocks, 256>>>(x, W1, A, 128, A + 64, 128,
                                         N_NODES, 256, a_src1, a_dst1, als1, ald1);

    // ---- join: gathers need CSR ----
    cudaStreamWaitEvent(0, ev_join, 0);
    gat_gather_kernel<<<gatherBlocks, 256>>>(roff, esrc, als1, ald1, A, b1, B, 1);

    // ---- GAT layer 2 (als2/ald2 pre-zeroed on side stream) ----
    mma_gemm_kernel<<<gemmBlocks, 256>>>(B, W2, C, 128, C + 64, 128,
                                         N_NODES, 128, a_src2, a_dst2, als2, ald2);
    gat_gather_kernel<<<gatherBlocks, 256>>>(roff, esrc, als2, ald2, C, b2, A, 0);

    // ---- SAGE layer 1 ----
    mma_gemm_kernel<<<gemmBlocks, 256>>>(A, wc1, D, 64, Ebuf, 64, N_NODES, 128,
                                         nullptr, nullptr, nullptr, nullptr);
    sage_gather_kernel<<<gatherBlocks, 256>>>(roff, esrc, D, s1bl, Ebuf, F,
                                              nullptr, nullptr, nullptr, nullptr, 0);

    // ---- SAGE layer 2 + BN fused ----
    mma_gemm_kernel<<<gemmBlocks, 256>>>(F, wc2, D, 64, Ebuf, 64, N_NODES, 64,
                                         nullptr, nullptr, nullptr, nullptr);
    sage_gather_kernel<<<gatherBlocks, 256>>>(roff, esrc, D, s2bl, Ebuf, out,
                                              bng, bnb, bnm, bnv, 1);
}

// round 10
// speedup vs baseline: 1.3083x; 1.0850x over previous
#include <cuda_runtime.h>
#include <cuda_bf16.h>
#include <math.h>
#include <stdint.h>

#define N_NODES 50000
#define E_EDGES 1600000
#define NEG_SLOPE 0.2f
#define BN_EPS 1e-5f
#define SCAN_NB ((N_NODES + 255) / 256)   // 196

// ---------------- scratch (static device globals; no allocation) ------------
__device__ float g_bufA[(size_t)N_NODES * 128];
__device__ float g_bufB[(size_t)N_NODES * 128];
__device__ float g_bufC[(size_t)N_NODES * 128];
__device__ float g_bufD[(size_t)N_NODES * 64];
__device__ float g_bufE[(size_t)N_NODES * 64];
__device__ float g_bufF[(size_t)N_NODES * 64];
__device__ float g_als1[N_NODES * 2];
__device__ float g_ald1[N_NODES * 2];
__device__ float g_als2[N_NODES * 2];
__device__ float g_ald2[N_NODES * 2];
__device__ float g_wc1[128 * 128];
__device__ float g_wc2[128 * 128];
__device__ int   g_deg[N_NODES];
__device__ int   g_roff[N_NODES + 1];
__device__ int   g_cur[N_NODES];
__device__ int   g_esrc[E_EDGES];
__device__ int   g_bsum[256];
__device__ int   g_boff[256];

// ---------------- helpers ----------------------------------------------------
__device__ __forceinline__ float lrelu(float x) {
    return x > 0.0f ? x : NEG_SLOPE * x;
}

__device__ __forceinline__ uint32_t smem_u32(const void* p) {
    return (uint32_t)__cvta_generic_to_shared(p);
}

__device__ __forceinline__ void ldsm_x4(uint32_t* r, uint32_t addr) {
    asm volatile("ldmatrix.sync.aligned.m8n8.x4.shared.b16 {%0,%1,%2,%3}, [%4];"
        : "=r"(r[0]), "=r"(r[1]), "=r"(r[2]), "=r"(r[3]) : "r"(addr));
}

__device__ __forceinline__ void ldsm_x4_t(uint32_t* r, uint32_t addr) {
    asm volatile("ldmatrix.sync.aligned.m8n8.x4.trans.shared.b16 {%0,%1,%2,%3}, [%4];"
        : "=r"(r[0]), "=r"(r[1]), "=r"(r[2]), "=r"(r[3]) : "r"(addr));
}

__device__ __forceinline__ void mma_bf16(float* d, const uint32_t* a,
                                         const uint32_t* b) {
    asm volatile(
        "mma.sync.aligned.m16n8k16.row.col.f32.bf16.bf16.f32 "
        "{%0,%1,%2,%3}, {%4,%5,%6,%7}, {%8,%9}, {%0,%1,%2,%3};"
        : "+f"(d[0]), "+f"(d[1]), "+f"(d[2]), "+f"(d[3])
        : "r"(a[0]), "r"(a[1]), "r"(a[2]), "r"(a[3]), "r"(b[0]), "r"(b[1]));
}

// ---------------- tensor-core GEMM via mma.sync (bf16 x3 split) --------------
// BM=64 tile, 256 threads (8 warps x 64x16), double-buffered, reg prefetch.
#define APAD 24
#define BPAD 136

struct MmaSmem {
    __align__(16) __nv_bfloat16 Ahi[64 * APAD];
    __align__(16) __nv_bfloat16 Alo[64 * APAD];
    __align__(16) __nv_bfloat16 Bhi[16 * BPAD];
    __align__(16) __nv_bfloat16 Blo[16 * BPAD];
};

__global__ __launch_bounds__(256, 3) void mma_gemm_kernel(
    const float* __restrict__ A, const float* __restrict__ W,
    float* __restrict__ outA, int strideA,
    float* __restrict__ outB, int strideB,
    int M, int K,
    const float* __restrict__ aSrcVec, const float* __restrict__ aDstVec,
    float* __restrict__ als, float* __restrict__ ald)
{
    __shared__ MmaSmem sm[2];

    int tid  = threadIdx.x;
    int w    = tid >> 5;
    int lane = tid & 31;
    int rowBase = blockIdx.x * 64;

    float acc[4][2][4];
    #pragma unroll
    for (int mi = 0; mi < 4; mi++)
        #pragma unroll
        for (int ni = 0; ni < 2; ni++)
            #pragma unroll
            for (int q = 0; q < 4; q++) acc[mi][ni][q] = 0.0f;

    uint32_t aHiB[2] = {smem_u32(sm[0].Ahi), smem_u32(sm[1].Ahi)};
    uint32_t aLoB[2] = {smem_u32(sm[0].Alo), smem_u32(sm[1].Alo)};
    uint32_t bHiB[2] = {smem_u32(sm[0].Bhi), smem_u32(sm[1].Bhi)};
    uint32_t bLoB[2] = {smem_u32(sm[0].Blo), smem_u32(sm[1].Blo)};

    int a_r = (lane & 7) + ((lane >> 3) & 1) * 8;
    int a_c = (lane >> 4) * 8;
    int b_r = lane & 15;
    int b_c = (lane >> 4) * 8;

    int aR = tid >> 2, aC = (tid & 3) * 4;
    int arow = aR * APAD + aC;
    bool aok = (rowBase + aR) < M;
    int wR[2], wC[2], wrow[2];
    #pragma unroll
    for (int h = 0; h < 2; h++) {
        int i = tid + h * 256;
        wR[h] = i >> 5;  wC[h] = (i & 31) * 4;
        wrow[h] = wR[h] * BPAD + wC[h];
    }

    float4 av, wv[2];
    av = make_float4(0.f, 0.f, 0.f, 0.f);
    if (aok) av = *(const float4*)(A + (size_t)(rowBase + aR) * K + aC);
    #pragma unroll
    for (int h = 0; h < 2; h++)
        wv[h] = *(const float4*)(W + (size_t)wR[h] * 128 + wC[h]);

    {
        float* vp = (float*)&av;
        #pragma unroll
        for (int q = 0; q < 4; q++) {
            __nv_bfloat16 hi = __float2bfloat16(vp[q]);
            sm[0].Ahi[arow + q] = hi;
            sm[0].Alo[arow + q] = __float2bfloat16(vp[q] - __bfloat162float(hi));
        }
        #pragma unroll
        for (int h = 0; h < 2; h++) {
            float* wp = (float*)&wv[h];
            #pragma unroll
            for (int q = 0; q < 4; q++) {
                __nv_bfloat16 hi = __float2bfloat16(wp[q]);
                sm[0].Bhi[wrow[h] + q] = hi;
                sm[0].Blo[wrow[h] + q] = __float2bfloat16(wp[q] - __bfloat162float(hi));
            }
        }
    }
    __syncthreads();

    int nchunk = K >> 4;
    for (int c = 0; c < nchunk; c++) {
        int sel = c & 1;
        bool more = (c + 1 < nchunk);
        if (more) {
            int k0n = (c + 1) << 4;
            av = make_float4(0.f, 0.f, 0.f, 0.f);
            if (aok) av = *(const float4*)(A + (size_t)(rowBase + aR) * K + k0n + aC);
            #pragma unroll
            for (int h = 0; h < 2; h++)
                wv[h] = *(const float4*)(W + (size_t)(k0n + wR[h]) * 128 + wC[h]);
        }

        uint32_t bh[4], bl[4];
        {
            uint32_t boff = (uint32_t)(b_r * BPAD + w * 16 + b_c) * 2;
            ldsm_x4_t(bh, bHiB[sel] + boff);
            ldsm_x4_t(bl, bLoB[sel] + boff);
        }
        #pragma unroll
        for (int mi = 0; mi < 4; mi++) {
            uint32_t aoff = (uint32_t)((mi * 16 + a_r) * APAD + a_c) * 2;
            uint32_t ah[4], al[4];
            ldsm_x4(ah, aHiB[sel] + aoff);
            ldsm_x4(al, aLoB[sel] + aoff);
            #pragma unroll
            for (int ni = 0; ni < 2; ni++) {
                mma_bf16(acc[mi][ni], ah, &bh[ni * 2]);
                mma_bf16(acc[mi][ni], ah, &bl[ni * 2]);
                mma_bf16(acc[mi][ni], al, &bh[ni * 2]);
            }
        }

        if (more) {
            MmaSmem& dst = sm[sel ^ 1];
            float* vp = (float*)&av;
            #pragma unroll
            for (int q = 0; q < 4; q++) {
                __nv_bfloat16 hi = __float2bfloat16(vp[q]);
                dst.Ahi[arow + q] = hi;
                dst.Alo[arow + q] = __float2bfloat16(vp[q] - __bfloat162float(hi));
            }
            #pragma unroll
            for (int h = 0; h < 2; h++) {
                float* wp = (float*)&wv[h];
                #pragma unroll
                for (int q = 0; q < 4; q++) {
                    __nv_bfloat16 hi = __float2bfloat16(wp[q]);
                    dst.Bhi[wrow[h] + q] = hi;
                    dst.Blo[wrow[h] + q] = __float2bfloat16(wp[q] - __bfloat162float(hi));
                }
            }
            __syncthreads();
        }
    }

    int g = lane >> 2, tig = lane & 3;

    #pragma unroll
    for (int mi = 0; mi < 4; mi++) {
        int row = rowBase + mi * 16 + g;
        #pragma unroll
        for (int ni = 0; ni < 2; ni++) {
            int col = w * 16 + ni * 8 + tig * 2;
            float* p0;
            if (col < 64) p0 = outA + (size_t)row * strideA + col;
            else          p0 = outB + (size_t)row * strideB + (col - 64);
            size_t rs = (col < 64) ? (size_t)strideA : (size_t)strideB;
            if (row < M)
                *(float2*)p0 = make_float2(acc[mi][ni][0], acc[mi][ni][1]);
            if (row + 8 < M)
                *(float2*)(p0 + 8 * rs) = make_float2(acc[mi][ni][2], acc[mi][ni][3]);
        }
    }

    if (aSrcVec != nullptr) {
        int head = w >> 2;
        float asv[4], adv[4];
        #pragma unroll
        for (int ni = 0; ni < 2; ni++)
            #pragma unroll
            for (int t = 0; t < 2; t++) {
                int col = w * 16 + ni * 8 + tig * 2 + t;
                asv[ni * 2 + t] = __ldg(aSrcVec + col);
                adv[ni * 2 + t] = __ldg(aDstVec + col);
            }
        #pragma unroll
        for (int mi = 0; mi < 4; mi++) {
            float ps0 = 0.f, pd0 = 0.f, ps1 = 0.f, pd1 = 0.f;
            #pragma unroll
            for (int ni = 0; ni < 2; ni++) {
                ps0 += acc[mi][ni][0] * asv[ni * 2] + acc[mi][ni][1] * asv[ni * 2 + 1];
                pd0 += acc[mi][ni][0] * adv[ni * 2] + acc[mi][ni][1] * adv[ni * 2 + 1];
                ps1 += acc[mi][ni][2] * asv[ni * 2] + acc[mi][ni][3] * asv[ni * 2 + 1];
                pd1 += acc[mi][ni][2] * adv[ni * 2] + acc[mi][ni][3] * adv[ni * 2 + 1];
            }
            #pragma unroll
            for (int o = 1; o < 4; o <<= 1) {
                ps0 += __shfl_xor_sync(0xffffffffu, ps0, o);
                pd0 += __shfl_xor_sync(0xffffffffu, pd0, o);
                ps1 += __shfl_xor_sync(0xffffffffu, ps1, o);
                pd1 += __shfl_xor_sync(0xffffffffu, pd1, o);
            }
            if (tig == 0) {
                int row = rowBase + mi * 16 + g;
                if (row < M) {
                    atomicAdd(&als[row * 2 + head], ps0);
                    atomicAdd(&ald[row * 2 + head], pd0);
                }
                if (row + 8 < M) {
                    atomicAdd(&als[(row + 8) * 2 + head], ps1);
                    atomicAdd(&ald[(row + 8) * 2 + head], pd1);
                }
            }
        }
    }
}

// ---------------- CSR build ---------------------------------------------------
__global__ void hist_kernel(const int* __restrict__ dst, int* __restrict__ deg)
{
    int e = blockIdx.x * blockDim.x + threadIdx.x;
    if (e < E_EDGES) atomicAdd(&deg[dst[e]], 1);
}

__global__ __launch_bounds__(256) void scan1_kernel(
    const int* __restrict__ deg, int* __restrict__ roff, int* __restrict__ bsum)
{
    int b = blockIdx.x, t = threadIdx.x;
    int idx = b * 256 + t;
    int v = (idx < N_NODES) ? deg[idx] : 0;
    int lane = t & 31, w = t >> 5;

    int x = v;
    #pragma unroll
    for (int o = 1; o < 32; o <<= 1) {
        int y = __shfl_up_sync(0xffffffffu, x, o);
        if (lane >= o) x += y;
    }
    __shared__ int ws[8];
    if (lane == 31) ws[w] = x;
    __syncthreads();
    if (t < 8) {
        int y = ws[t], z = y;
        #pragma unroll
        for (int o = 1; o < 8; o <<= 1) {
            int q = __shfl_up_sync(0xffu, z, o);
            if (t >= o) z += q;
        }
        ws[t] = z - y;
    }
    __syncthreads();
    int excl = x - v + ws[w];
    if (idx < N_NODES) roff[idx] = excl;
    if (t == 255) bsum[b] = excl + v;
}

__global__ __launch_bounds__(256) void scan2_kernel(
    const int* __restrict__ bsum, int* __restrict__ boff, int* __restrict__ roff)
{
    int t = threadIdx.x;
    int v = (t < SCAN_NB) ? bsum[t] : 0;
    int lane = t & 31, w = t >> 5;
    int x = v;
    #pragma unroll
    for (int o = 1; o < 32; o <<= 1) {
        int y = __shfl_up_sync(0xffffffffu, x, o);
        if (lane >= o) x += y;
    }
    __shared__ int ws[8];
    if (lane == 31) ws[w] = x;
    __syncthreads();
    if (t < 8) {
        int y = ws[t], z = y;
        #pragma unroll
        for (int o = 1; o < 8; o <<= 1) {
            int q = __shfl_up_sync(0xffu, z, o);
            if (t >= o) z += q;
        }
        ws[t] = z - y;
    }
    __syncthreads();
    int excl = x - v + ws[w];
    boff[t] = excl;
    if (t == 255) roff[N_NODES] = excl + v;
}

__global__ __launch_bounds__(256) void scan3_kernel(
    int* __restrict__ roff, const int* __restrict__ boff, int* __restrict__ cur)
{
    int idx = blockIdx.x * 256 + threadIdx.x;
    if (idx >= N_NODES) return;
    int r = roff[idx] + boff[blockIdx.x];
    roff[idx] = r;
    cur[idx]  = r;
}

__global__ void scatter_kernel(const int* __restrict__ src,
                               const int* __restrict__ dst,
                               int* __restrict__ cur, int* __restrict__ esrc)
{
    int e = blockIdx.x * blockDim.x + threadIdx.x;
    if (e >= E_EDGES) return;
    int d = dst[e];
    int p = atomicAdd(&cur[d], 1);
    esrc[p] = src[e];
}

// ---------------- fused GAT gather: single pass, __expf, 4-way unrolled ------
__global__ __launch_bounds__(256) void gat_gather_kernel(
    const int* __restrict__ roff, const int* __restrict__ esrc,
    const float* __restrict__ als, const float* __restrict__ ald,
    const float* __restrict__ h, const float* __restrict__ bias,
    float* __restrict__ out, int relu)
{
    int d = (blockIdx.x * blockDim.x + threadIdx.x) >> 5;
    int lane = threadIdx.x & 31;
    if (d >= N_NODES) return;

    float2 ad = *(const float2*)(ald + 2 * d);
    float2 a_self = *(const float2*)(als + 2 * d);
    int head = (lane >= 16);

    float w_self0 = __expf(lrelu(a_self.x + ad.x));
    float w_self1 = __expf(lrelu(a_self.y + ad.y));
    float s0 = w_self0, s1 = w_self1;
    float wsh = head ? w_self1 : w_self0;

    float4 hv = *(const float4*)(h + (size_t)d * 128 + lane * 4);
    float4 acc;
    acc.x = wsh * hv.x;
    acc.y = wsh * hv.y;
    acc.z = wsh * hv.z;
    acc.w = wsh * hv.w;

    int beg = roff[d], end = roff[d + 1];
    int i = beg;
    for (; i + 4 <= end; i += 4) {
        int sI[4];
        float2 aI[4];
        float4 vI[4];
        #pragma unroll
        for (int j = 0; j < 4; j++) sI[j] = __ldg(esrc + i + j);
        #pragma unroll
        for (int j = 0; j < 4; j++) aI[j] = *(const float2*)(als + 2 * sI[j]);
        #pragma unroll
        for (int j = 0; j < 4; j++)
            vI[j] = *(const float4*)(h + (size_t)sI[j] * 128 + lane * 4);
        #pragma unroll
        for (int j = 0; j < 4; j++) {
            float w0 = __expf(lrelu(aI[j].x + ad.x));
            float w1 = __expf(lrelu(aI[j].y + ad.y));
            s0 += w0;
            s1 += w1;
            float wh = head ? w1 : w0;
            acc.x = fmaf(wh, vI[j].x, acc.x);
            acc.y = fmaf(wh, vI[j].y, acc.y);
            acc.z = fmaf(wh, vI[j].z, acc.z);
            acc.w = fmaf(wh, vI[j].w, acc.w);
        }
    }
    for (; i < end; i++) {
        int s = __ldg(esrc + i);
        float2 a = *(const float2*)(als + 2 * s);
        float4 v = *(const float4*)(h + (size_t)s * 128 + lane * 4);
        float w0 = __expf(lrelu(a.x + ad.x));
        float w1 = __expf(lrelu(a.y + ad.y));
        s0 += w0;
        s1 += w1;
        float wh = head ? w1 : w0;
        acc.x = fmaf(wh, v.x, acc.x);
        acc.y = fmaf(wh, v.y, acc.y);
        acc.z = fmaf(wh, v.z, acc.z);
        acc.w = fmaf(wh, v.w, acc.w);
    }

    float inv = 1.0f / (head ? s1 : s0);
    float4 b = *(const float4*)(bias + lane * 4);
    acc.x = fmaf(acc.x, inv, b.x);
    acc.y = fmaf(acc.y, inv, b.y);
    acc.z = fmaf(acc.z, inv, b.z);
    acc.w = fmaf(acc.w, inv, b.w);
    if (relu) {
        acc.x = fmaxf(acc.x, 0.0f);
        acc.y = fmaxf(acc.y, 0.0f);
        acc.z = fmaxf(acc.z, 0.0f);
        acc.w = fmaxf(acc.w, 0.0f);
    }
    *(float4*)(out + (size_t)d * 128 + lane * 4) = acc;
}

// ---------------- weight concat for fused SAGE GEMM --------------------------
__global__ void concat_w_kernel(const float* __restrict__ wl,
                                const float* __restrict__ wr,
                                float* __restrict__ wc, int K)
{
    int i = blockIdx.x * blockDim.x + threadIdx.x;
    if (i >= K * 64) return;
    int k = i >> 6, c = i & 63;
    wc[k * 128 + c]      = wl[i];
    wc[k * 128 + 64 + c] = wr[i];
}

// ---------------- fused SAGE gather (mean + bias + root + relu [+ BN]) -------
// 8-way unrolled edge loop for MLP.
__global__ __launch_bounds__(256) void sage_gather_kernel(
    const int* __restrict__ roff, const int* __restrict__ esrc,
    const float* __restrict__ y, const float* __restrict__ bl,
    const float* __restrict__ r, float* __restrict__ out,
    const float* __restrict__ gamma, const float* __restrict__ beta,
    const float* __restrict__ mean, const float* __restrict__ var,
    int do_bn)
{
    int d = (blockIdx.x * blockDim.x + threadIdx.x) >> 5;
    int lane = threadIdx.x & 31;
    if (d >= N_NODES) return;

    int beg = roff[d], end = roff[d + 1];
    float ax = 0.0f, ay = 0.0f;
    int i = beg;
    for (; i + 8 <= end; i += 8) {
        int sI[8];
        float2 vI[8];
        #pragma unroll
        for (int j = 0; j < 8; j++) sI[j] = __ldg(esrc + i + j);
        #pragma unroll
        for (int j = 0; j < 8; j++)
            vI[j] = *(const float2*)(y + (size_t)sI[j] * 64 + lane * 2);
        #pragma unroll
        for (int j = 0; j < 8; j++) { ax += vI[j].x; ay += vI[j].y; }
    }
    for (; i < end; i++) {
        int s = __ldg(esrc + i);
        float2 v = *(const float2*)(y + (size_t)s * 64 + lane * 2);
        ax += v.x;
        ay += v.y;
    }
    float invc = 1.0f / fmaxf((float)(end - beg), 1.0f);
    int c = lane * 2;
    float2 bb = *(const float2*)(bl + c);
    float2 rr = *(const float2*)(r + (size_t)d * 64 + c);
    float vx = fmaxf(ax * invc + bb.x + rr.x, 0.0f);
    float vy = fmaxf(ay * invc + bb.y + rr.y, 0.0f);
    if (do_bn) {
        float sx = gamma[c]     * rsqrtf(var[c]     + BN_EPS);
        float sy = gamma[c + 1] * rsqrtf(var[c + 1] + BN_EPS);
        vx = (vx - mean[c])     * sx + beta[c];
        vy = (vy - mean[c + 1]) * sy + beta[c + 1];
    }
    *(float2*)(out + (size_t)d * 64 + c) = make_float2(vx, vy);
}

// ---------------- host orchestration -----------------------------------------
extern "C" void kernel_launch(void* const* d_in, const int* in_sizes, int n_in,
                              void* d_out, int out_size)
{
    const float* x      = (const float*)d_in[0];
    const int*   ei     = (const int*)d_in[1];
    const float* W1     = (const float*)d_in[2];
    const float* a_src1 = (const float*)d_in[3];
    const float* a_dst1 = (const float*)d_in[4];
    const float* b1     = (const float*)d_in[5];
    const float* W2     = (const float*)d_in[6];
    const float* a_src2 = (const float*)d_in[7];
    const float* a_dst2 = (const float*)d_in[8];
    const float* b2     = (const float*)d_in[9];
    const float* s1wl   = (const float*)d_in[10];
    const float* s1bl   = (const float*)d_in[11];
    const float* s1wr   = (const float*)d_in[12];
    const float* s2wl   = (const float*)d_in[13];
    const float* s2bl   = (const float*)d_in[14];
    const float* s2wr   = (const float*)d_in[15];
    const float* bng    = (const float*)d_in[16];
    const float* bnb    = (const float*)d_in[17];
    const float* bnm    = (const float*)d_in[18];
    const float* bnv    = (const float*)d_in[19];
    float* out = (float*)d_out;

    const int* src = ei;
    const int* dst = ei + E_EDGES;

    float *A, *B, *C, *D, *Ebuf, *F, *als1, *ald1, *als2, *ald2, *wc1, *wc2;
    int *deg, *roff, *cur, *esrc, *bsum, *boff;
    cudaGetSymbolAddress((void**)&A,    g_bufA);
    cudaGetSymbolAddress((void**)&B,    g_bufB);
    cudaGetSymbolAddress((void**)&C,    g_bufC);
    cudaGetSymbolAddress((void**)&D,    g_bufD);
    cudaGetSymbolAddress((void**)&Ebuf, g_bufE);
    cudaGetSymbolAddress((void**)&F,    g_bufF);
    cudaGetSymbolAddress((void**)&als1, g_als1);
    cudaGetSymbolAddress((void**)&ald1, g_ald1);
    cudaGetSymbolAddress((void**)&als2, g_als2);
    cudaGetSymbolAddress((void**)&ald2, g_ald2);
    cudaGetSymbolAddress((void**)&wc1,  g_wc1);
    cudaGetSymbolAddress((void**)&wc2,  g_wc2);
    cudaGetSymbolAddress((void**)&deg,  g_deg);
    cudaGetSymbolAddress((void**)&roff, g_roff);
    cudaGetSymbolAddress((void**)&cur,  g_cur);
    cudaGetSymbolAddress((void**)&esrc, g_esrc);
    cudaGetSymbolAddress((void**)&bsum, g_bsum);
    cudaGetSymbolAddress((void**)&boff, g_boff);

    static cudaStream_t s_side = nullptr;
    static cudaEvent_t ev_fork = nullptr, ev_join = nullptr;
    if (s_side == nullptr) {
        cudaStreamCreateWithFlags(&s_side, cudaStreamNonBlocking);
        cudaEventCreateWithFlags(&ev_fork, cudaEventDisableTiming);
        cudaEventCreateWithFlags(&ev_join, cudaEventDisableTiming);
    }

    int gemmBlocks   = (N_NODES + 63) / 64;
    int gatherBlocks = (N_NODES * 32 + 255) / 256;

    // ---- fork: CSR build + weight concats + layer-2 al zeroing (side) ----
    cudaEventRecord(ev_fork, 0);
    cudaStreamWaitEvent(s_side, ev_fork, 0);
    cudaMemsetAsync(deg, 0, N_NODES * sizeof(int), s_side);
    cudaMemsetAsync(als2, 0, N_NODES * 2 * sizeof(float), s_side);
    cudaMemsetAsync(ald2, 0, N_NODES * 2 * sizeof(float), s_side);
    hist_kernel<<<(E_EDGES + 255) / 256, 256, 0, s_side>>>(dst, deg);
    scan1_kernel<<<SCAN_NB, 256, 0, s_side>>>(deg, roff, bsum);
    scan2_kernel<<<1, 256, 0, s_side>>>(bsum, boff, roff);
    scan3_kernel<<<SCAN_NB, 256, 0, s_side>>>(roff, boff, cur);
    scatter_kernel<<<(E_EDGES + 255) / 256, 256, 0, s_side>>>(src, dst, cur, esrc);
    concat_w_kernel<<<(128 * 64 + 255) / 256, 256, 0, s_side>>>(s1wl, s1wr, wc1, 128);
    concat_w_kernel<<<(64 * 64 + 255) / 256, 256, 0, s_side>>>(s2wl, s2wr, wc2, 64);
    cudaEventRecord(ev_join, s_side);

    // ---- main: GAT layer 1 GEMM (fused al) ----
    cudaMemsetAsync(als1, 0, N_NODES * 2 * sizeof(float), 0);
    cudaMemsetAsync(ald1, 0, N_NODES * 2 * sizeof(float), 0);
    mma_gemm_kernel<<<gemmBlocks, 256>>>(x, W1, A, 128, A + 64, 128,
                                         N_NODES, 256, a_src1, a_dst1, als1, ald1);

    // ---- join: gathers need CSR ----
    cudaStreamWaitEvent(0, ev_join, 0);
    gat_gather_kernel<<<gatherBlocks, 256>>>(roff, esrc, als1, ald1, A, b1, B, 1);

    // ---- GAT layer 2 (als2/ald2 pre-zeroed on side stream) ----
    mma_gemm_kernel<<<gemmBlocks, 256>>>(B, W2, C, 128, C + 64, 128,
                                         N_NODES, 128, a_src2, a_dst2, als2, ald2);
    gat_gather_kernel<<<gatherBlocks, 256>>>(roff, esrc, als2, ald2, C, b2, A, 0);

    // ---- SAGE layer 1 ----
    mma_gemm_kernel<<<gemmBlocks, 256>>>(A, wc1, D, 64, Ebuf, 64, N_NODES, 128,
                                         nullptr, nullptr, nullptr, nullptr);
    sage_gather_kernel<<<gatherBlocks, 256>>>(roff, esrc, D, s1bl, Ebuf, F,
                                              nullptr, nullptr, nullptr, nullptr, 0);

    // ---- SAGE layer 2 + BN fused ----
    mma_gemm_kernel<<<gemmBlocks, 256>>>(F, wc2, D, 64, Ebuf, 64, N_NODES, 64,
                                         nullptr, nullptr, nullptr, nullptr);
    sage_gather_kernel<<<gatherBlocks, 256>>>(roff, esrc, D, s2bl, Ebuf, out,
                                              bng, bnb, bnm, bnv, 1);
}

// round 11
// speedup vs baseline: 1.3228x; 1.0111x over previous
#include <cuda_runtime.h>
#include <cuda_bf16.h>
#include <cuda_fp16.h>
#include <math.h>
#include <stdint.h>

#define N_NODES 50000
#define E_EDGES 1600000
#define NEG_SLOPE 0.2f
#define BN_EPS 1e-5f
#define SCAN_NB ((N_NODES + 255) / 256)   // 196

// ---------------- scratch (static device globals; no allocation) ------------
__device__ float  g_bufA[(size_t)N_NODES * 128];
__device__ float  g_bufB[(size_t)N_NODES * 128];
__device__ float  g_bufE[(size_t)N_NODES * 64];
__device__ float  g_bufF[(size_t)N_NODES * 64];
__device__ __half g_h16[(size_t)N_NODES * 128];   // fp16 GAT features
__device__ __half g_y16[(size_t)N_NODES * 64];    // fp16 SAGE projected feats
__device__ float  g_als1[N_NODES * 2];
__device__ float  g_ald1[N_NODES * 2];
__device__ float  g_als2[N_NODES * 2];
__device__ float  g_ald2[N_NODES * 2];
__device__ float  g_wc1[128 * 128];
__device__ float  g_wc2[128 * 128];
__device__ int    g_deg[N_NODES];
__device__ int    g_roff[N_NODES + 1];
__device__ int    g_cur[N_NODES];
__device__ int    g_esrc[E_EDGES];
__device__ int    g_bsum[256];
__device__ int    g_boff[256];

// ---------------- helpers ----------------------------------------------------
__device__ __forceinline__ float lrelu(float x) {
    return x > 0.0f ? x : NEG_SLOPE * x;
}

__device__ __forceinline__ uint32_t smem_u32(const void* p) {
    return (uint32_t)__cvta_generic_to_shared(p);
}

__device__ __forceinline__ void ldsm_x4(uint32_t* r, uint32_t addr) {
    asm volatile("ldmatrix.sync.aligned.m8n8.x4.shared.b16 {%0,%1,%2,%3}, [%4];"
        : "=r"(r[0]), "=r"(r[1]), "=r"(r[2]), "=r"(r[3]) : "r"(addr));
}

__device__ __forceinline__ void ldsm_x4_t(uint32_t* r, uint32_t addr) {
    asm volatile("ldmatrix.sync.aligned.m8n8.x4.trans.shared.b16 {%0,%1,%2,%3}, [%4];"
        : "=r"(r[0]), "=r"(r[1]), "=r"(r[2]), "=r"(r[3]) : "r"(addr));
}

__device__ __forceinline__ void mma_bf16(float* d, const uint32_t* a,
                                         const uint32_t* b) {
    asm volatile(
        "mma.sync.aligned.m16n8k16.row.col.f32.bf16.bf16.f32 "
        "{%0,%1,%2,%3}, {%4,%5,%6,%7}, {%8,%9}, {%0,%1,%2,%3};"
        : "+f"(d[0]), "+f"(d[1]), "+f"(d[2]), "+f"(d[3])
        : "r"(a[0]), "r"(a[1]), "r"(a[2]), "r"(a[3]), "r"(b[0]), "r"(b[1]));
}

// ---------------- tensor-core GEMM via mma.sync (bf16 x3 split) --------------
// BM=64, 256 threads, double-buffered. Output modes:
//   outF == null : all 128 cols -> fp16 outH (stride 128)    [GAT]
//   outF != null : cols 0-63 -> fp16 outH (stride 64),
//                  cols 64-127 -> fp32 outF (stride 64)       [SAGE]
#define APAD 24
#define BPAD 136

struct MmaSmem {
    __align__(16) __nv_bfloat16 Ahi[64 * APAD];
    __align__(16) __nv_bfloat16 Alo[64 * APAD];
    __align__(16) __nv_bfloat16 Bhi[16 * BPAD];
    __align__(16) __nv_bfloat16 Blo[16 * BPAD];
};

__global__ __launch_bounds__(256, 3) void mma_gemm_kernel(
    const float* __restrict__ A, const float* __restrict__ W,
    __half* __restrict__ outH, float* __restrict__ outF,
    int M, int K,
    const float* __restrict__ aSrcVec, const float* __restrict__ aDstVec,
    float* __restrict__ als, float* __restrict__ ald)
{
    __shared__ MmaSmem sm[2];

    int tid  = threadIdx.x;
    int w    = tid >> 5;
    int lane = tid & 31;
    int rowBase = blockIdx.x * 64;

    float acc[4][2][4];
    #pragma unroll
    for (int mi = 0; mi < 4; mi++)
        #pragma unroll
        for (int ni = 0; ni < 2; ni++)
            #pragma unroll
            for (int q = 0; q < 4; q++) acc[mi][ni][q] = 0.0f;

    uint32_t aHiB[2] = {smem_u32(sm[0].Ahi), smem_u32(sm[1].Ahi)};
    uint32_t aLoB[2] = {smem_u32(sm[0].Alo), smem_u32(sm[1].Alo)};
    uint32_t bHiB[2] = {smem_u32(sm[0].Bhi), smem_u32(sm[1].Bhi)};
    uint32_t bLoB[2] = {smem_u32(sm[0].Blo), smem_u32(sm[1].Blo)};

    int a_r = (lane & 7) + ((lane >> 3) & 1) * 8;
    int a_c = (lane >> 4) * 8;
    int b_r = lane & 15;
    int b_c = (lane >> 4) * 8;

    int aR = tid >> 2, aC = (tid & 3) * 4;
    int arow = aR * APAD + aC;
    bool aok = (rowBase + aR) < M;
    int wR[2], wC[2], wrow[2];
    #pragma unroll
    for (int h = 0; h < 2; h++) {
        int i = tid + h * 256;
        wR[h] = i >> 5;  wC[h] = (i & 31) * 4;
        wrow[h] = wR[h] * BPAD + wC[h];
    }

    float4 av, wv[2];
    av = make_float4(0.f, 0.f, 0.f, 0.f);
    if (aok) av = *(const float4*)(A + (size_t)(rowBase + aR) * K + aC);
    #pragma unroll
    for (int h = 0; h < 2; h++)
        wv[h] = *(const float4*)(W + (size_t)wR[h] * 128 + wC[h]);

    {
        float* vp = (float*)&av;
        #pragma unroll
        for (int q = 0; q < 4; q++) {
            __nv_bfloat16 hi = __float2bfloat16(vp[q]);
            sm[0].Ahi[arow + q] = hi;
            sm[0].Alo[arow + q] = __float2bfloat16(vp[q] - __bfloat162float(hi));
        }
        #pragma unroll
        for (int h = 0; h < 2; h++) {
            float* wp = (float*)&wv[h];
            #pragma unroll
            for (int q = 0; q < 4; q++) {
                __nv_bfloat16 hi = __float2bfloat16(wp[q]);
                sm[0].Bhi[wrow[h] + q] = hi;
                sm[0].Blo[wrow[h] + q] = __float2bfloat16(wp[q] - __bfloat162float(hi));
            }
        }
    }
    __syncthreads();

    int nchunk = K >> 4;
    for (int c = 0; c < nchunk; c++) {
        int sel = c & 1;
        bool more = (c + 1 < nchunk);
        if (more) {
            int k0n = (c + 1) << 4;
            av = make_float4(0.f, 0.f, 0.f, 0.f);
            if (aok) av = *(const float4*)(A + (size_t)(rowBase + aR) * K + k0n + aC);
            #pragma unroll
            for (int h = 0; h < 2; h++)
                wv[h] = *(const float4*)(W + (size_t)(k0n + wR[h]) * 128 + wC[h]);
        }

        uint32_t bh[4], bl[4];
        {
            uint32_t boff = (uint32_t)(b_r * BPAD + w * 16 + b_c) * 2;
            ldsm_x4_t(bh, bHiB[sel] + boff);
            ldsm_x4_t(bl, bLoB[sel] + boff);
        }
        #pragma unroll
        for (int mi = 0; mi < 4; mi++) {
            uint32_t aoff = (uint32_t)((mi * 16 + a_r) * APAD + a_c) * 2;
            uint32_t ah[4], al[4];
            ldsm_x4(ah, aHiB[sel] + aoff);
            ldsm_x4(al, aLoB[sel] + aoff);
            #pragma unroll
            for (int ni = 0; ni < 2; ni++) {
                mma_bf16(acc[mi][ni], ah, &bh[ni * 2]);
                mma_bf16(acc[mi][ni], ah, &bl[ni * 2]);
                mma_bf16(acc[mi][ni], al, &bh[ni * 2]);
            }
        }

        if (more) {
            MmaSmem& dst = sm[sel ^ 1];
            float* vp = (float*)&av;
            #pragma unroll
            for (int q = 0; q < 4; q++) {
                __nv_bfloat16 hi = __float2bfloat16(vp[q]);
                dst.Ahi[arow + q] = hi;
                dst.Alo[arow + q] = __float2bfloat16(vp[q] - __bfloat162float(hi));
            }
            #pragma unroll
            for (int h = 0; h < 2; h++) {
                float* wp = (float*)&wv[h];
                #pragma unroll
                for (int q = 0; q < 4; q++) {
                    __nv_bfloat16 hi = __float2bfloat16(wp[q]);
                    dst.Bhi[wrow[h] + q] = hi;
                    dst.Blo[wrow[h] + q] = __float2bfloat16(wp[q] - __bfloat162float(hi));
                }
            }
            __syncthreads();
        }
    }

    int g = lane >> 2, tig = lane & 3;

    // epilogue: fp16 (+ optional fp32 r split)
    #pragma unroll
    for (int mi = 0; mi < 4; mi++) {
        int row = rowBase + mi * 16 + g;
        #pragma unroll
        for (int ni = 0; ni < 2; ni++) {
            int col = w * 16 + ni * 8 + tig * 2;
            if (outF == nullptr) {
                __half2 v0 = __floats2half2_rn(acc[mi][ni][0], acc[mi][ni][1]);
                __half2 v1 = __floats2half2_rn(acc[mi][ni][2], acc[mi][ni][3]);
                if (row < M)
                    *(__half2*)(outH + (size_t)row * 128 + col) = v0;
                if (row + 8 < M)
                    *(__half2*)(outH + (size_t)(row + 8) * 128 + col) = v1;
            } else if (col < 64) {
                __half2 v0 = __floats2half2_rn(acc[mi][ni][0], acc[mi][ni][1]);
                __half2 v1 = __floats2half2_rn(acc[mi][ni][2], acc[mi][ni][3]);
                if (row < M)
                    *(__half2*)(outH + (size_t)row * 64 + col) = v0;
                if (row + 8 < M)
                    *(__half2*)(outH + (size_t)(row + 8) * 64 + col) = v1;
            } else {
                int c2 = col - 64;
                if (row < M)
                    *(float2*)(outF + (size_t)row * 64 + c2) =
                        make_float2(acc[mi][ni][0], acc[mi][ni][1]);
                if (row + 8 < M)
                    *(float2*)(outF + (size_t)(row + 8) * 64 + c2) =
                        make_float2(acc[mi][ni][2], acc[mi][ni][3]);
            }
        }
    }

    // fused attention-logit epilogue (fp32 accumulators)
    if (aSrcVec != nullptr) {
        int head = w >> 2;
        float asv[4], adv[4];
        #pragma unroll
        for (int ni = 0; ni < 2; ni++)
            #pragma unroll
            for (int t = 0; t < 2; t++) {
                int col = w * 16 + ni * 8 + tig * 2 + t;
                asv[ni * 2 + t] = __ldg(aSrcVec + col);
                adv[ni * 2 + t] = __ldg(aDstVec + col);
            }
        #pragma unroll
        for (int mi = 0; mi < 4; mi++) {
            float ps0 = 0.f, pd0 = 0.f, ps1 = 0.f, pd1 = 0.f;
            #pragma unroll
            for (int ni = 0; ni < 2; ni++) {
                ps0 += acc[mi][ni][0] * asv[ni * 2] + acc[mi][ni][1] * asv[ni * 2 + 1];
                pd0 += acc[mi][ni][0] * adv[ni * 2] + acc[mi][ni][1] * adv[ni * 2 + 1];
                ps1 += acc[mi][ni][2] * asv[ni * 2] + acc[mi][ni][3] * asv[ni * 2 + 1];
                pd1 += acc[mi][ni][2] * adv[ni * 2] + acc[mi][ni][3] * adv[ni * 2 + 1];
            }
            #pragma unroll
            for (int o = 1; o < 4; o <<= 1) {
                ps0 += __shfl_xor_sync(0xffffffffu, ps0, o);
                pd0 += __shfl_xor_sync(0xffffffffu, pd0, o);
                ps1 += __shfl_xor_sync(0xffffffffu, ps1, o);
                pd1 += __shfl_xor_sync(0xffffffffu, pd1, o);
            }
            if (tig == 0) {
                int row = rowBase + mi * 16 + g;
                if (row < M) {
                    atomicAdd(&als[row * 2 + head], ps0);
                    atomicAdd(&ald[row * 2 + head], pd0);
                }
                if (row + 8 < M) {
                    atomicAdd(&als[(row + 8) * 2 + head], ps1);
                    atomicAdd(&ald[(row + 8) * 2 + head], pd1);
                }
            }
        }
    }
}

// ---------------- CSR build ---------------------------------------------------
__global__ void hist_kernel(const int* __restrict__ dst, int* __restrict__ deg)
{
    int e = blockIdx.x * blockDim.x + threadIdx.x;
    if (e < E_EDGES) atomicAdd(&deg[dst[e]], 1);
}

__global__ __launch_bounds__(256) void scan1_kernel(
    const int* __restrict__ deg, int* __restrict__ roff, int* __restrict__ bsum)
{
    int b = blockIdx.x, t = threadIdx.x;
    int idx = b * 256 + t;
    int v = (idx < N_NODES) ? deg[idx] : 0;
    int lane = t & 31, w = t >> 5;

    int x = v;
    #pragma unroll
    for (int o = 1; o < 32; o <<= 1) {
        int y = __shfl_up_sync(0xffffffffu, x, o);
        if (lane >= o) x += y;
    }
    __shared__ int ws[8];
    if (lane == 31) ws[w] = x;
    __syncthreads();
    if (t < 8) {
        int y = ws[t], z = y;
        #pragma unroll
        for (int o = 1; o < 8; o <<= 1) {
            int q = __shfl_up_sync(0xffu, z, o);
            if (t >= o) z += q;
        }
        ws[t] = z - y;
    }
    __syncthreads();
    int excl = x - v + ws[w];
    if (idx < N_NODES) roff[idx] = excl;
    if (t == 255) bsum[b] = excl + v;
}

__global__ __launch_bounds__(256) void scan2_kernel(
    const int* __restrict__ bsum, int* __restrict__ boff, int* __restrict__ roff)
{
    int t = threadIdx.x;
    int v = (t < SCAN_NB) ? bsum[t] : 0;
    int lane = t & 31, w = t >> 5;
    int x = v;
    #pragma unroll
    for (int o = 1; o < 32; o <<= 1) {
        int y = __shfl_up_sync(0xffffffffu, x, o);
        if (lane >= o) x += y;
    }
    __shared__ int ws[8];
    if (lane == 31) ws[w] = x;
    __syncthreads();
    if (t < 8) {
        int y = ws[t], z = y;
        #pragma unroll
        for (int o = 1; o < 8; o <<= 1) {
            int q = __shfl_up_sync(0xffu, z, o);
            if (t >= o) z += q;
        }
        ws[t] = z - y;
    }
    __syncthreads();
    int excl = x - v + ws[w];
    boff[t] = excl;
    if (t == 255) roff[N_NODES] = excl + v;
}

__global__ __launch_bounds__(256) void scan3_kernel(
    int* __restrict__ roff, const int* __restrict__ boff, int* __restrict__ cur)
{
    int idx = blockIdx.x * 256 + threadIdx.x;
    if (idx >= N_NODES) return;
    int r = roff[idx] + boff[blockIdx.x];
    roff[idx] = r;
    cur[idx]  = r;
}

__global__ void scatter_kernel(const int* __restrict__ src,
                               const int* __restrict__ dst,
                               int* __restrict__ cur, int* __restrict__ esrc)
{
    int e = blockIdx.x * blockDim.x + threadIdx.x;
    if (e >= E_EDGES) return;
    int d = dst[e];
    int p = atomicAdd(&cur[d], 1);
    esrc[p] = src[e];
}

// ---------------- fused GAT gather: fp16 features, single pass ----------------
__global__ __launch_bounds__(256) void gat_gather_kernel(
    const int* __restrict__ roff, const int* __restrict__ esrc,
    const float* __restrict__ als, const float* __restrict__ ald,
    const __half* __restrict__ h, const float* __restrict__ bias,
    float* __restrict__ out, int relu)
{
    int d = (blockIdx.x * blockDim.x + threadIdx.x) >> 5;
    int lane = threadIdx.x & 31;
    if (d >= N_NODES) return;

    float2 ad = *(const float2*)(ald + 2 * d);
    float2 a_self = *(const float2*)(als + 2 * d);
    int head = (lane >= 16);

    float w_self0 = __expf(lrelu(a_self.x + ad.x));
    float w_self1 = __expf(lrelu(a_self.y + ad.y));
    float s0 = w_self0, s1 = w_self1;
    float wsh = head ? w_self1 : w_self0;

    uint2 us = *(const uint2*)(h + (size_t)d * 128 + lane * 4);
    float2 f0 = __half22float2(*(__half2*)&us.x);
    float2 f1 = __half22float2(*(__half2*)&us.y);
    float4 acc;
    acc.x = wsh * f0.x;
    acc.y = wsh * f0.y;
    acc.z = wsh * f1.x;
    acc.w = wsh * f1.y;

    int beg = roff[d], end = roff[d + 1];
    int i = beg;
    for (; i + 4 <= end; i += 4) {
        int sI[4];
        float2 aI[4];
        uint2 uI[4];
        #pragma unroll
        for (int j = 0; j < 4; j++) sI[j] = __ldg(esrc + i + j);
        #pragma unroll
        for (int j = 0; j < 4; j++) aI[j] = *(const float2*)(als + 2 * sI[j]);
        #pragma unroll
        for (int j = 0; j < 4; j++)
            uI[j] = *(const uint2*)(h + (size_t)sI[j] * 128 + lane * 4);
        #pragma unroll
        for (int j = 0; j < 4; j++) {
            float w0 = __expf(lrelu(aI[j].x + ad.x));
            float w1 = __expf(lrelu(aI[j].y + ad.y));
            s0 += w0;
            s1 += w1;
            float wh = head ? w1 : w0;
            float2 v0 = __half22float2(*(__half2*)&uI[j].x);
            float2 v1 = __half22float2(*(__half2*)&uI[j].y);
            acc.x = fmaf(wh, v0.x, acc.x);
            acc.y = fmaf(wh, v0.y, acc.y);
            acc.z = fmaf(wh, v1.x, acc.z);
            acc.w = fmaf(wh, v1.y, acc.w);
        }
    }
    for (; i < end; i++) {
        int s = __ldg(esrc + i);
        float2 a = *(const float2*)(als + 2 * s);
        uint2 u = *(const uint2*)(h + (size_t)s * 128 + lane * 4);
        float w0 = __expf(lrelu(a.x + ad.x));
        float w1 = __expf(lrelu(a.y + ad.y));
        s0 += w0;
        s1 += w1;
        float wh = head ? w1 : w0;
        float2 v0 = __half22float2(*(__half2*)&u.x);
        float2 v1 = __half22float2(*(__half2*)&u.y);
        acc.x = fmaf(wh, v0.x, acc.x);
        acc.y = fmaf(wh, v0.y, acc.y);
        acc.z = fmaf(wh, v1.x, acc.z);
        acc.w = fmaf(wh, v1.y, acc.w);
    }

    float inv = 1.0f / (head ? s1 : s0);
    float4 b = *(const float4*)(bias + lane * 4);
    acc.x = fmaf(acc.x, inv, b.x);
    acc.y = fmaf(acc.y, inv, b.y);
    acc.z = fmaf(acc.z, inv, b.z);
    acc.w = fmaf(acc.w, inv, b.w);
    if (relu) {
        acc.x = fmaxf(acc.x, 0.0f);
        acc.y = fmaxf(acc.y, 0.0f);
        acc.z = fmaxf(acc.z, 0.0f);
        acc.w = fmaxf(acc.w, 0.0f);
    }
    *(float4*)(out + (size_t)d * 128 + lane * 4) = acc;
}

// ---------------- weight concat for fused SAGE GEMM --------------------------
__global__ void concat_w_kernel(const float* __restrict__ wl,
                                const float* __restrict__ wr,
                                float* __restrict__ wc, int K)
{
    int i = blockIdx.x * blockDim.x + threadIdx.x;
    if (i >= K * 64) return;
    int k = i >> 6, c = i & 63;
    wc[k * 128 + c]      = wl[i];
    wc[k * 128 + 64 + c] = wr[i];
}

// ---------------- fused SAGE gather: fp16 y, 8-way unrolled -------------------
__global__ __launch_bounds__(256) void sage_gather_kernel(
    const int* __restrict__ roff, const int* __restrict__ esrc,
    const __half* __restrict__ y, const float* __restrict__ bl,
    const float* __restrict__ r, float* __restrict__ out,
    const float* __restrict__ gamma, const float* __restrict__ beta,
    const float* __restrict__ mean, const float* __restrict__ var,
    int do_bn)
{
    int d = (blockIdx.x * blockDim.x + threadIdx.x) >> 5;
    int lane = threadIdx.x & 31;
    if (d >= N_NODES) return;

    int beg = roff[d], end = roff[d + 1];
    float ax = 0.0f, ay = 0.0f;
    int i = beg;
    for (; i + 8 <= end; i += 8) {
        int sI[8];
        uint32_t uI[8];
        #pragma unroll
        for (int j = 0; j < 8; j++) sI[j] = __ldg(esrc + i + j);
        #pragma unroll
        for (int j = 0; j < 8; j++)
            uI[j] = *(const uint32_t*)(y + (size_t)sI[j] * 64 + lane * 2);
        #pragma unroll
        for (int j = 0; j < 8; j++) {
            float2 v = __half22float2(*(__half2*)&uI[j]);
            ax += v.x;
            ay += v.y;
        }
    }
    for (; i < end; i++) {
        int s = __ldg(esrc + i);
        uint32_t u = *(const uint32_t*)(y + (size_t)s * 64 + lane * 2);
        float2 v = __half22float2(*(__half2*)&u);
        ax += v.x;
        ay += v.y;
    }
    float invc = 1.0f / fmaxf((float)(end - beg), 1.0f);
    int c = lane * 2;
    float2 bb = *(const float2*)(bl + c);
    float2 rr = *(const float2*)(r + (size_t)d * 64 + c);
    float vx = fmaxf(ax * invc + bb.x + rr.x, 0.0f);
    float vy = fmaxf(ay * invc + bb.y + rr.y, 0.0f);
    if (do_bn) {
        float sx = gamma[c]     * rsqrtf(var[c]     + BN_EPS);
        float sy = gamma[c + 1] * rsqrtf(var[c + 1] + BN_EPS);
        vx = (vx - mean[c])     * sx + beta[c];
        vy = (vy - mean[c + 1]) * sy + beta[c + 1];
    }
    *(float2*)(out + (size_t)d * 64 + c) = make_float2(vx, vy);
}

// ---------------- host orchestration -----------------------------------------
extern "C" void kernel_launch(void* const* d_in, const int* in_sizes, int n_in,
                              void* d_out, int out_size)
{
    const float* x      = (const float*)d_in[0];
    const int*   ei     = (const int*)d_in[1];
    const float* W1     = (const float*)d_in[2];
    const float* a_src1 = (const float*)d_in[3];
    const float* a_dst1 = (const float*)d_in[4];
    const float* b1     = (const float*)d_in[5];
    const float* W2     = (const float*)d_in[6];
    const float* a_src2 = (const float*)d_in[7];
    const float* a_dst2 = (const float*)d_in[8];
    const float* b2     = (const float*)d_in[9];
    const float* s1wl   = (const float*)d_in[10];
    const float* s1bl   = (const float*)d_in[11];
    const float* s1wr   = (const float*)d_in[12];
    const float* s2wl   = (const float*)d_in[13];
    const float* s2bl   = (const float*)d_in[14];
    const float* s2wr   = (const float*)d_in[15];
    const float* bng    = (const float*)d_in[16];
    const float* bnb    = (const float*)d_in[17];
    const float* bnm    = (const float*)d_in[18];
    const float* bnv    = (const float*)d_in[19];
    float* out = (float*)d_out;

    const int* src = ei;
    const int* dst = ei + E_EDGES;

    float *A, *B, *Ebuf, *F, *als1, *ald1, *als2, *ald2, *wc1, *wc2;
    __half *H16, *Y16;
    int *deg, *roff, *cur, *esrc, *bsum, *boff;
    cudaGetSymbolAddress((void**)&A,    g_bufA);
    cudaGetSymbolAddress((void**)&B,    g_bufB);
    cudaGetSymbolAddress((void**)&Ebuf, g_bufE);
    cudaGetSymbolAddress((void**)&F,    g_bufF);
    cudaGetSymbolAddress((void**)&H16,  g_h16);
    cudaGetSymbolAddress((void**)&Y16,  g_y16);
    cudaGetSymbolAddress((void**)&als1, g_als1);
    cudaGetSymbolAddress((void**)&ald1, g_ald1);
    cudaGetSymbolAddress((void**)&als2, g_als2);
    cudaGetSymbolAddress((void**)&ald2, g_ald2);
    cudaGetSymbolAddress((void**)&wc1,  g_wc1);
    cudaGetSymbolAddress((void**)&wc2,  g_wc2);
    cudaGetSymbolAddress((void**)&deg,  g_deg);
    cudaGetSymbolAddress((void**)&roff, g_roff);
    cudaGetSymbolAddress((void**)&cur,  g_cur);
    cudaGetSymbolAddress((void**)&esrc, g_esrc);
    cudaGetSymbolAddress((void**)&bsum, g_bsum);
    cudaGetSymbolAddress((void**)&boff, g_boff);

    static cudaStream_t s_side = nullptr;
    static cudaEvent_t ev_fork = nullptr, ev_join = nullptr;
    if (s_side == nullptr) {
        cudaStreamCreateWithFlags(&s_side, cudaStreamNonBlocking);
        cudaEventCreateWithFlags(&ev_fork, cudaEventDisableTiming);
        cudaEventCreateWithFlags(&ev_join, cudaEventDisableTiming);
    }

    int gemmBlocks   = (N_NODES + 63) / 64;
    int gatherBlocks = (N_NODES * 32 + 255) / 256;

    // ---- fork: CSR build + weight concats + layer-2 al zeroing (side) ----
    cudaEventRecord(ev_fork, 0);
    cudaStreamWaitEvent(s_side, ev_fork, 0);
    cudaMemsetAsync(deg, 0, N_NODES * sizeof(int), s_side);
    cudaMemsetAsync(als2, 0, N_NODES * 2 * sizeof(float), s_side);
    cudaMemsetAsync(ald2, 0, N_NODES * 2 * sizeof(float), s_side);
    hist_kernel<<<(E_EDGES + 255) / 256, 256, 0, s_side>>>(dst, deg);
    scan1_kernel<<<SCAN_NB, 256, 0, s_side>>>(deg, roff, bsum);
    scan2_kernel<<<1, 256, 0, s_side>>>(bsum, boff, roff);
    scan3_kernel<<<SCAN_NB, 256, 0, s_side>>>(roff, boff, cur);
    scatter_kernel<<<(E_EDGES + 255) / 256, 256, 0, s_side>>>(src, dst, cur, esrc);
    concat_w_kernel<<<(128 * 64 + 255) / 256, 256, 0, s_side>>>(s1wl, s1wr, wc1, 128);
    concat_w_kernel<<<(64 * 64 + 255) / 256, 256, 0, s_side>>>(s2wl, s2wr, wc2, 64);
    cudaEventRecord(ev_join, s_side);

    // ---- main: GAT layer 1 GEMM (fp16 h + fused al) ----
    cudaMemsetAsync(als1, 0, N_NODES * 2 * sizeof(float), 0);
    cudaMemsetAsync(ald1, 0, N_NODES * 2 * sizeof(float), 0);
    mma_gemm_kernel<<<gemmBlocks, 256>>>(x, W1, H16, nullptr,
                                         N_NODES, 256, a_src1, a_dst1, als1, ald1);

    // ---- join: gathers need CSR ----
    cudaStreamWaitEvent(0, ev_join, 0);
    gat_gather_kernel<<<gatherBlocks, 256>>>(roff, esrc, als1, ald1, H16, b1, B, 1);

    // ---- GAT layer 2 ----
    mma_gemm_kernel<<<gemmBlocks, 256>>>(B, W2, H16, nullptr,
                                         N_NODES, 128, a_src2, a_dst2, als2, ald2);
    gat_gather_kernel<<<gatherBlocks, 256>>>(roff, esrc, als2, ald2, H16, b2, A, 0);

    // ---- SAGE layer 1: y (fp16) + r (fp32) in one GEMM ----
    mma_gemm_kernel<<<gemmBlocks, 256>>>(A, wc1, Y16, Ebuf, N_NODES, 128,
                                         nullptr, nullptr, nullptr, nullptr);
    sage_gather_kernel<<<gatherBlocks, 256>>>(roff, esrc, Y16, s1bl, Ebuf, F,
                                              nullptr, nullptr, nullptr, nullptr, 0);

    // ---- SAGE layer 2 + BN fused ----
    mma_gemm_kernel<<<gemmBlocks, 256>>>(F, wc2, Y16, Ebuf, N_NODES, 64,
                                         nullptr, nullptr, nullptr, nullptr);
    sage_gather_kernel<<<gatherBlocks, 256>>>(roff, esrc, Y16, s2bl, Ebuf, out,
                                              bng, bnb, bnm, bnv, 1);
}

// round 12
// speedup vs baseline: 1.4211x; 1.0743x over previous
#include <cuda_runtime.h>
#include <cuda_bf16.h>
#include <cuda_fp16.h>
#include <math.h>
#include <stdint.h>

#define N_NODES 50000
#define E_EDGES 1600000
#define NEG_SLOPE 0.2f
#define BN_EPS 1e-5f
#define SCAN_NB ((N_NODES + 255) / 256)   // 196

// ---------------- scratch (static device globals; no allocation) ------------
__device__ float  g_bufA[(size_t)N_NODES * 128];
__device__ float  g_bufB[(size_t)N_NODES * 128];
__device__ float  g_bufE[(size_t)N_NODES * 64];
__device__ float  g_bufF[(size_t)N_NODES * 64];
__device__ __half g_h16[(size_t)N_NODES * 128];   // fp16 GAT features
__device__ __half g_y16[(size_t)N_NODES * 64];    // fp16 SAGE projected feats
__device__ float  g_als1[N_NODES * 2];
__device__ float  g_ald1[N_NODES * 2];
__device__ float  g_als2[N_NODES * 2];
__device__ float  g_ald2[N_NODES * 2];
__device__ float  g_wc1[128 * 128];
__device__ float  g_wc2[128 * 128];
__device__ int    g_deg[N_NODES];
__device__ int    g_roff[N_NODES + 1];
__device__ int    g_cur[N_NODES];
__device__ int    g_esrc[E_EDGES];
__device__ int    g_bsum[256];
__device__ int    g_boff[256];

// ---------------- helpers ----------------------------------------------------
__device__ __forceinline__ float lrelu(float x) {
    return x > 0.0f ? x : NEG_SLOPE * x;
}

__device__ __forceinline__ uint32_t smem_u32(const void* p) {
    return (uint32_t)__cvta_generic_to_shared(p);
}

__device__ __forceinline__ void ldsm_x4(uint32_t* r, uint32_t addr) {
    asm volatile("ldmatrix.sync.aligned.m8n8.x4.shared.b16 {%0,%1,%2,%3}, [%4];"
        : "=r"(r[0]), "=r"(r[1]), "=r"(r[2]), "=r"(r[3]) : "r"(addr));
}

__device__ __forceinline__ void ldsm_x4_t(uint32_t* r, uint32_t addr) {
    asm volatile("ldmatrix.sync.aligned.m8n8.x4.trans.shared.b16 {%0,%1,%2,%3}, [%4];"
        : "=r"(r[0]), "=r"(r[1]), "=r"(r[2]), "=r"(r[3]) : "r"(addr));
}

__device__ __forceinline__ void mma_bf16(float* d, const uint32_t* a,
                                         const uint32_t* b) {
    asm volatile(
        "mma.sync.aligned.m16n8k16.row.col.f32.bf16.bf16.f32 "
        "{%0,%1,%2,%3}, {%4,%5,%6,%7}, {%8,%9}, {%0,%1,%2,%3};"
        : "+f"(d[0]), "+f"(d[1]), "+f"(d[2]), "+f"(d[3])
        : "r"(a[0]), "r"(a[1]), "r"(a[2]), "r"(a[3]), "r"(b[0]), "r"(b[1]));
}

// ---------------- tensor-core GEMM via mma.sync (bf16 x3 split) --------------
// BM=64, 256 threads, double-buffered. Output modes:
//   outF == null : all 128 cols -> fp16 outH (stride 128)    [GAT]
//   outF != null : cols 0-63 -> fp16 outH (stride 64),
//                  cols 64-127 -> fp32 outF (stride 64)       [SAGE]
// al epilogue uses smem reduction + direct store (no pre-zero, no gmem atomics)
#define APAD 24
#define BPAD 136

struct MmaSmem {
    __align__(16) __nv_bfloat16 Ahi[64 * APAD];
    __align__(16) __nv_bfloat16 Alo[64 * APAD];
    __align__(16) __nv_bfloat16 Bhi[16 * BPAD];
    __align__(16) __nv_bfloat16 Blo[16 * BPAD];
};

__global__ __launch_bounds__(256, 3) void mma_gemm_kernel(
    const float* __restrict__ A, const float* __restrict__ W,
    __half* __restrict__ outH, float* __restrict__ outF,
    int M, int K,
    const float* __restrict__ aSrcVec, const float* __restrict__ aDstVec,
    float* __restrict__ als, float* __restrict__ ald)
{
    __shared__ MmaSmem sm[2];
    __shared__ float red[4][64];   // [als_h0, ald_h0, als_h1, ald_h1][local row]

    int tid  = threadIdx.x;
    int w    = tid >> 5;
    int lane = tid & 31;
    int rowBase = blockIdx.x * 64;

    float acc[4][2][4];
    #pragma unroll
    for (int mi = 0; mi < 4; mi++)
        #pragma unroll
        for (int ni = 0; ni < 2; ni++)
            #pragma unroll
            for (int q = 0; q < 4; q++) acc[mi][ni][q] = 0.0f;

    uint32_t aHiB[2] = {smem_u32(sm[0].Ahi), smem_u32(sm[1].Ahi)};
    uint32_t aLoB[2] = {smem_u32(sm[0].Alo), smem_u32(sm[1].Alo)};
    uint32_t bHiB[2] = {smem_u32(sm[0].Bhi), smem_u32(sm[1].Bhi)};
    uint32_t bLoB[2] = {smem_u32(sm[0].Blo), smem_u32(sm[1].Blo)};

    int a_r = (lane & 7) + ((lane >> 3) & 1) * 8;
    int a_c = (lane >> 4) * 8;
    int b_r = lane & 15;
    int b_c = (lane >> 4) * 8;

    int aR = tid >> 2, aC = (tid & 3) * 4;
    int arow = aR * APAD + aC;
    bool aok = (rowBase + aR) < M;
    int wR[2], wC[2], wrow[2];
    #pragma unroll
    for (int h = 0; h < 2; h++) {
        int i = tid + h * 256;
        wR[h] = i >> 5;  wC[h] = (i & 31) * 4;
        wrow[h] = wR[h] * BPAD + wC[h];
    }

    // zero al-reduction smem (no dependence on anything)
    if (aSrcVec != nullptr && tid < 256) ((float*)red)[tid] = 0.0f;

    float4 av, wv[2];
    av = make_float4(0.f, 0.f, 0.f, 0.f);
    if (aok) av = *(const float4*)(A + (size_t)(rowBase + aR) * K + aC);
    #pragma unroll
    for (int h = 0; h < 2; h++)
        wv[h] = *(const float4*)(W + (size_t)wR[h] * 128 + wC[h]);

    {
        float* vp = (float*)&av;
        #pragma unroll
        for (int q = 0; q < 4; q++) {
            __nv_bfloat16 hi = __float2bfloat16(vp[q]);
            sm[0].Ahi[arow + q] = hi;
            sm[0].Alo[arow + q] = __float2bfloat16(vp[q] - __bfloat162float(hi));
        }
        #pragma unroll
        for (int h = 0; h < 2; h++) {
            float* wp = (float*)&wv[h];
            #pragma unroll
            for (int q = 0; q < 4; q++) {
                __nv_bfloat16 hi = __float2bfloat16(wp[q]);
                sm[0].Bhi[wrow[h] + q] = hi;
                sm[0].Blo[wrow[h] + q] = __float2bfloat16(wp[q] - __bfloat162float(hi));
            }
        }
    }
    __syncthreads();

    int nchunk = K >> 4;
    for (int c = 0; c < nchunk; c++) {
        int sel = c & 1;
        bool more = (c + 1 < nchunk);
        if (more) {
            int k0n = (c + 1) << 4;
            av = make_float4(0.f, 0.f, 0.f, 0.f);
            if (aok) av = *(const float4*)(A + (size_t)(rowBase + aR) * K + k0n + aC);
            #pragma unroll
            for (int h = 0; h < 2; h++)
                wv[h] = *(const float4*)(W + (size_t)(k0n + wR[h]) * 128 + wC[h]);
        }

        uint32_t bh[4], bl[4];
        {
            uint32_t boff = (uint32_t)(b_r * BPAD + w * 16 + b_c) * 2;
            ldsm_x4_t(bh, bHiB[sel] + boff);
            ldsm_x4_t(bl, bLoB[sel] + boff);
        }
        #pragma unroll
        for (int mi = 0; mi < 4; mi++) {
            uint32_t aoff = (uint32_t)((mi * 16 + a_r) * APAD + a_c) * 2;
            uint32_t ah[4], al[4];
            ldsm_x4(ah, aHiB[sel] + aoff);
            ldsm_x4(al, aLoB[sel] + aoff);
            #pragma unroll
            for (int ni = 0; ni < 2; ni++) {
                mma_bf16(acc[mi][ni], ah, &bh[ni * 2]);
                mma_bf16(acc[mi][ni], ah, &bl[ni * 2]);
                mma_bf16(acc[mi][ni], al, &bh[ni * 2]);
            }
        }

        if (more) {
            MmaSmem& dst = sm[sel ^ 1];
            float* vp = (float*)&av;
            #pragma unroll
            for (int q = 0; q < 4; q++) {
                __nv_bfloat16 hi = __float2bfloat16(vp[q]);
                dst.Ahi[arow + q] = hi;
                dst.Alo[arow + q] = __float2bfloat16(vp[q] - __bfloat162float(hi));
            }
            #pragma unroll
            for (int h = 0; h < 2; h++) {
                float* wp = (float*)&wv[h];
                #pragma unroll
                for (int q = 0; q < 4; q++) {
                    __nv_bfloat16 hi = __float2bfloat16(wp[q]);
                    dst.Bhi[wrow[h] + q] = hi;
                    dst.Blo[wrow[h] + q] = __float2bfloat16(wp[q] - __bfloat162float(hi));
                }
            }
            __syncthreads();
        }
    }

    int g = lane >> 2, tig = lane & 3;

    // epilogue: fp16 (+ optional fp32 r split)
    #pragma unroll
    for (int mi = 0; mi < 4; mi++) {
        int row = rowBase + mi * 16 + g;
        #pragma unroll
        for (int ni = 0; ni < 2; ni++) {
            int col = w * 16 + ni * 8 + tig * 2;
            if (outF == nullptr) {
                __half2 v0 = __floats2half2_rn(acc[mi][ni][0], acc[mi][ni][1]);
                __half2 v1 = __floats2half2_rn(acc[mi][ni][2], acc[mi][ni][3]);
                if (row < M)
                    *(__half2*)(outH + (size_t)row * 128 + col) = v0;
                if (row + 8 < M)
                    *(__half2*)(outH + (size_t)(row + 8) * 128 + col) = v1;
            } else if (col < 64) {
                __half2 v0 = __floats2half2_rn(acc[mi][ni][0], acc[mi][ni][1]);
                __half2 v1 = __floats2half2_rn(acc[mi][ni][2], acc[mi][ni][3]);
                if (row < M)
                    *(__half2*)(outH + (size_t)row * 64 + col) = v0;
                if (row + 8 < M)
                    *(__half2*)(outH + (size_t)(row + 8) * 64 + col) = v1;
            } else {
                int c2 = col - 64;
                if (row < M)
                    *(float2*)(outF + (size_t)row * 64 + c2) =
                        make_float2(acc[mi][ni][0], acc[mi][ni][1]);
                if (row + 8 < M)
                    *(float2*)(outF + (size_t)(row + 8) * 64 + c2) =
                        make_float2(acc[mi][ni][2], acc[mi][ni][3]);
            }
        }
    }

    // fused attention-logit epilogue via smem reduction (no gmem atomics)
    if (aSrcVec != nullptr) {
        int head = w >> 2;
        float asv[4], adv[4];
        #pragma unroll
        for (int ni = 0; ni < 2; ni++)
            #pragma unroll
            for (int t = 0; t < 2; t++) {
                int col = w * 16 + ni * 8 + tig * 2 + t;
                asv[ni * 2 + t] = __ldg(aSrcVec + col);
                adv[ni * 2 + t] = __ldg(aDstVec + col);
            }
        #pragma unroll
        for (int mi = 0; mi < 4; mi++) {
            float ps0 = 0.f, pd0 = 0.f, ps1 = 0.f, pd1 = 0.f;
            #pragma unroll
            for (int ni = 0; ni < 2; ni++) {
                ps0 += acc[mi][ni][0] * asv[ni * 2] + acc[mi][ni][1] * asv[ni * 2 + 1];
                pd0 += acc[mi][ni][0] * adv[ni * 2] + acc[mi][ni][1] * adv[ni * 2 + 1];
                ps1 += acc[mi][ni][2] * asv[ni * 2] + acc[mi][ni][3] * asv[ni * 2 + 1];
                pd1 += acc[mi][ni][2] * adv[ni * 2] + acc[mi][ni][3] * adv[ni * 2 + 1];
            }
            #pragma unroll
            for (int o = 1; o < 4; o <<= 1) {
                ps0 += __shfl_xor_sync(0xffffffffu, ps0, o);
                pd0 += __shfl_xor_sync(0xffffffffu, pd0, o);
                ps1 += __shfl_xor_sync(0xffffffffu, ps1, o);
                pd1 += __shfl_xor_sync(0xffffffffu, pd1, o);
            }
            if (tig == 0) {
                int r0 = mi * 16 + g;
                atomicAdd(&red[head * 2 + 0][r0],     ps0);
                atomicAdd(&red[head * 2 + 1][r0],     pd0);
                atomicAdd(&red[head * 2 + 0][r0 + 8], ps1);
                atomicAdd(&red[head * 2 + 1][r0 + 8], pd1);
            }
        }
        __syncthreads();
        if (tid < 64) {
            int grow = rowBase + tid;
            if (grow < M) {
                als[grow * 2 + 0] = red[0][tid];
                ald[grow * 2 + 0] = red[1][tid];
                als[grow * 2 + 1] = red[2][tid];
                ald[grow * 2 + 1] = red[3][tid];
            }
        }
    }
}

// ---------------- CSR build ---------------------------------------------------
__global__ void hist_kernel(const int* __restrict__ dst, int* __restrict__ deg)
{
    int e = blockIdx.x * blockDim.x + threadIdx.x;
    if (e < E_EDGES) atomicAdd(&deg[dst[e]], 1);
}

__global__ __launch_bounds__(256) void scan1_kernel(
    const int* __restrict__ deg, int* __restrict__ roff, int* __restrict__ bsum)
{
    int b = blockIdx.x, t = threadIdx.x;
    int idx = b * 256 + t;
    int v = (idx < N_NODES) ? deg[idx] : 0;
    int lane = t & 31, w = t >> 5;

    int x = v;
    #pragma unroll
    for (int o = 1; o < 32; o <<= 1) {
        int y = __shfl_up_sync(0xffffffffu, x, o);
        if (lane >= o) x += y;
    }
    __shared__ int ws[8];
    if (lane == 31) ws[w] = x;
    __syncthreads();
    if (t < 8) {
        int y = ws[t], z = y;
        #pragma unroll
        for (int o = 1; o < 8; o <<= 1) {
            int q = __shfl_up_sync(0xffu, z, o);
            if (t >= o) z += q;
        }
        ws[t] = z - y;
    }
    __syncthreads();
    int excl = x - v + ws[w];
    if (idx < N_NODES) roff[idx] = excl;
    if (t == 255) bsum[b] = excl + v;
}

__global__ __launch_bounds__(256) void scan2_kernel(
    const int* __restrict__ bsum, int* __restrict__ boff, int* __restrict__ roff)
{
    int t = threadIdx.x;
    int v = (t < SCAN_NB) ? bsum[t] : 0;
    int lane = t & 31, w = t >> 5;
    int x = v;
    #pragma unroll
    for (int o = 1; o < 32; o <<= 1) {
        int y = __shfl_up_sync(0xffffffffu, x, o);
        if (lane >= o) x += y;
    }
    __shared__ int ws[8];
    if (lane == 31) ws[w] = x;
    __syncthreads();
    if (t < 8) {
        int y = ws[t], z = y;
        #pragma unroll
        for (int o = 1; o < 8; o <<= 1) {
            int q = __shfl_up_sync(0xffu, z, o);
            if (t >= o) z += q;
        }
        ws[t] = z - y;
    }
    __syncthreads();
    int excl = x - v + ws[w];
    boff[t] = excl;
    if (t == 255) roff[N_NODES] = excl + v;
}

__global__ __launch_bounds__(256) void scan3_kernel(
    int* __restrict__ roff, const int* __restrict__ boff, int* __restrict__ cur)
{
    int idx = blockIdx.x * 256 + threadIdx.x;
    if (idx >= N_NODES) return;
    int r = roff[idx] + boff[blockIdx.x];
    roff[idx] = r;
    cur[idx]  = r;
}

__global__ void scatter_kernel(const int* __restrict__ src,
                               const int* __restrict__ dst,
                               int* __restrict__ cur, int* __restrict__ esrc)
{
    int e = blockIdx.x * blockDim.x + threadIdx.x;
    if (e >= E_EDGES) return;
    int d = dst[e];
    int p = atomicAdd(&cur[d], 1);
    esrc[p] = src[e];
}

// ---------------- fused GAT gather: per-lane head, 1 exp/edge -----------------
__global__ __launch_bounds__(256) void gat_gather_kernel(
    const int* __restrict__ roff, const int* __restrict__ esrc,
    const float* __restrict__ als, const float* __restrict__ ald,
    const __half* __restrict__ h, const float* __restrict__ bias,
    float* __restrict__ out, int relu)
{
    int d = (blockIdx.x * blockDim.x + threadIdx.x) >> 5;
    int lane = threadIdx.x & 31;
    if (d >= N_NODES) return;

    int head = (lane >= 16);
    float adh = __ldg(ald + 2 * d + head);
    float ash = __ldg(als + 2 * d + head);

    // self term
    float wsh = __expf(lrelu(ash + adh));
    float s_half = wsh;

    uint2 us = *(const uint2*)(h + (size_t)d * 128 + lane * 4);
    float2 f0 = __half22float2(*(__half2*)&us.x);
    float2 f1 = __half22float2(*(__half2*)&us.y);
    float4 acc;
    acc.x = wsh * f0.x;
    acc.y = wsh * f0.y;
    acc.z = wsh * f1.x;
    acc.w = wsh * f1.y;

    int beg = roff[d], end = roff[d + 1];
    int i = beg;
    for (; i + 4 <= end; i += 4) {
        int sI[4];
        float aI[4];
        uint2 uI[4];
        #pragma unroll
        for (int j = 0; j < 4; j++) sI[j] = __ldg(esrc + i + j);
        #pragma unroll
        for (int j = 0; j < 4; j++) aI[j] = __ldg(als + 2 * sI[j] + head);
        #pragma unroll
        for (int j = 0; j < 4; j++)
            uI[j] = *(const uint2*)(h + (size_t)sI[j] * 128 + lane * 4);
        #pragma unroll
        for (int j = 0; j < 4; j++) {
            float wh = __expf(lrelu(aI[j] + adh));
            s_half += wh;
            float2 v0 = __half22float2(*(__half2*)&uI[j].x);
            float2 v1 = __half22float2(*(__half2*)&uI[j].y);
            acc.x = fmaf(wh, v0.x, acc.x);
            acc.y = fmaf(wh, v0.y, acc.y);
            acc.z = fmaf(wh, v1.x, acc.z);
            acc.w = fmaf(wh, v1.y, acc.w);
        }
    }
    for (; i < end; i++) {
        int s = __ldg(esrc + i);
        float a = __ldg(als + 2 * s + head);
        uint2 u = *(const uint2*)(h + (size_t)s * 128 + lane * 4);
        float wh = __expf(lrelu(a + adh));
        s_half += wh;
        float2 v0 = __half22float2(*(__half2*)&u.x);
        float2 v1 = __half22float2(*(__half2*)&u.y);
        acc.x = fmaf(wh, v0.x, acc.x);
        acc.y = fmaf(wh, v0.y, acc.y);
        acc.z = fmaf(wh, v1.x, acc.z);
        acc.w = fmaf(wh, v1.y, acc.w);
    }

    float inv = 1.0f / s_half;
    float4 b = *(const float4*)(bias + lane * 4);
    acc.x = fmaf(acc.x, inv, b.x);
    acc.y = fmaf(acc.y, inv, b.y);
    acc.z = fmaf(acc.z, inv, b.z);
    acc.w = fmaf(acc.w, inv, b.w);
    if (relu) {
        acc.x = fmaxf(acc.x, 0.0f);
        acc.y = fmaxf(acc.y, 0.0f);
        acc.z = fmaxf(acc.z, 0.0f);
        acc.w = fmaxf(acc.w, 0.0f);
    }
    *(float4*)(out + (size_t)d * 128 + lane * 4) = acc;
}

// ---------------- merged weight concat for both SAGE GEMMs -------------------
__global__ void concat_both_kernel(
    const float* __restrict__ wl1, const float* __restrict__ wr1,
    float* __restrict__ wc1,
    const float* __restrict__ wl2, const float* __restrict__ wr2,
    float* __restrict__ wc2)
{
    int i = blockIdx.x * blockDim.x + threadIdx.x;
    if (i < 128 * 64) {
        int k = i >> 6, c = i & 63;
        wc1[k * 128 + c]      = wl1[i];
        wc1[k * 128 + 64 + c] = wr1[i];
    } else if (i < 128 * 64 + 64 * 64) {
        int j = i - 128 * 64;
        int k = j >> 6, c = j & 63;
        wc2[k * 128 + c]      = wl2[j];
        wc2[k * 128 + 64 + c] = wr2[j];
    }
}

// ---------------- fused SAGE gather: fp16 y, 8-way unrolled -------------------
__global__ __launch_bounds__(256) void sage_gather_kernel(
    const int* __restrict__ roff, const int* __restrict__ esrc,
    const __half* __restrict__ y, const float* __restrict__ bl,
    const float* __restrict__ r, float* __restrict__ out,
    const float* __restrict__ gamma, const float* __restrict__ beta,
    const float* __restrict__ mean, const float* __restrict__ var,
    int do_bn)
{
    int d = (blockIdx.x * blockDim.x + threadIdx.x) >> 5;
    int lane = threadIdx.x & 31;
    if (d >= N_NODES) return;

    int beg = roff[d], end = roff[d + 1];
    float ax = 0.0f, ay = 0.0f;
    int i = beg;
    for (; i + 8 <= end; i += 8) {
        int sI[8];
        uint32_t uI[8];
        #pragma unroll
        for (int j = 0; j < 8; j++) sI[j] = __ldg(esrc + i + j);
        #pragma unroll
        for (int j = 0; j < 8; j++)
            uI[j] = *(const uint32_t*)(y + (size_t)sI[j] * 64 + lane * 2);
        #pragma unroll
        for (int j = 0; j < 8; j++) {
            float2 v = __half22float2(*(__half2*)&uI[j]);
            ax += v.x;
            ay += v.y;
        }
    }
    for (; i < end; i++) {
        int s = __ldg(esrc + i);
        uint32_t u = *(const uint32_t*)(y + (size_t)s * 64 + lane * 2);
        float2 v = __half22float2(*(__half2*)&u);
        ax += v.x;
        ay += v.y;
    }
    float invc = 1.0f / fmaxf((float)(end - beg), 1.0f);
    int c = lane * 2;
    float2 bb = *(const float2*)(bl + c);
    float2 rr = *(const float2*)(r + (size_t)d * 64 + c);
    float vx = fmaxf(ax * invc + bb.x + rr.x, 0.0f);
    float vy = fmaxf(ay * invc + bb.y + rr.y, 0.0f);
    if (do_bn) {
        float sx = gamma[c]     * rsqrtf(var[c]     + BN_EPS);
        float sy = gamma[c + 1] * rsqrtf(var[c + 1] + BN_EPS);
        vx = (vx - mean[c])     * sx + beta[c];
        vy = (vy - mean[c + 1]) * sy + beta[c + 1];
    }
    *(float2*)(out + (size_t)d * 64 + c) = make_float2(vx, vy);
}

// ---------------- host orchestration -----------------------------------------
extern "C" void kernel_launch(void* const* d_in, const int* in_sizes, int n_in,
                              void* d_out, int out_size)
{
    const float* x      = (const float*)d_in[0];
    const int*   ei     = (const int*)d_in[1];
    const float* W1     = (const float*)d_in[2];
    const float* a_src1 = (const float*)d_in[3];
    const float* a_dst1 = (const float*)d_in[4];
    const float* b1     = (const float*)d_in[5];
    const float* W2     = (const float*)d_in[6];
    const float* a_src2 = (const float*)d_in[7];
    const float* a_dst2 = (const float*)d_in[8];
    const float* b2     = (const float*)d_in[9];
    const float* s1wl   = (const float*)d_in[10];
    const float* s1bl   = (const float*)d_in[11];
    const float* s1wr   = (const float*)d_in[12];
    const float* s2wl   = (const float*)d_in[13];
    const float* s2bl   = (const float*)d_in[14];
    const float* s2wr   = (const float*)d_in[15];
    const float* bng    = (const float*)d_in[16];
    const float* bnb    = (const float*)d_in[17];
    const float* bnm    = (const float*)d_in[18];
    const float* bnv    = (const float*)d_in[19];
    float* out = (float*)d_out;

    const int* src = ei;
    const int* dst = ei + E_EDGES;

    float *A, *B, *Ebuf, *F, *als1, *ald1, *als2, *ald2, *wc1, *wc2;
    __half *H16, *Y16;
    int *deg, *roff, *cur, *esrc, *bsum, *boff;
    cudaGetSymbolAddress((void**)&A,    g_bufA);
    cudaGetSymbolAddress((void**)&B,    g_bufB);
    cudaGetSymbolAddress((void**)&Ebuf, g_bufE);
    cudaGetSymbolAddress((void**)&F,    g_bufF);
    cudaGetSymbolAddress((void**)&H16,  g_h16);
    cudaGetSymbolAddress((void**)&Y16,  g_y16);
    cudaGetSymbolAddress((void**)&als1, g_als1);
    cudaGetSymbolAddress((void**)&ald1, g_ald1);
    cudaGetSymbolAddress((void**)&als2, g_als2);
    cudaGetSymbolAddress((void**)&ald2, g_ald2);
    cudaGetSymbolAddress((void**)&wc1,  g_wc1);
    cudaGetSymbolAddress((void**)&wc2,  g_wc2);
    cudaGetSymbolAddress((void**)&deg,  g_deg);
    cudaGetSymbolAddress((void**)&roff, g_roff);
    cudaGetSymbolAddress((void**)&cur,  g_cur);
    cudaGetSymbolAddress((void**)&esrc, g_esrc);
    cudaGetSymbolAddress((void**)&bsum, g_bsum);
    cudaGetSymbolAddress((void**)&boff, g_boff);

    static cudaStream_t s_side = nullptr;
    static cudaEvent_t ev_fork = nullptr, ev_join = nullptr;
    if (s_side == nullptr) {
        cudaStreamCreateWithFlags(&s_side, cudaStreamNonBlocking);
        cudaEventCreateWithFlags(&ev_fork, cudaEventDisableTiming);
        cudaEventCreateWithFlags(&ev_join, cudaEventDisableTiming);
    }

    int gemmBlocks   = (N_NODES + 63) / 64;
    int gatherBlocks = (N_NODES * 32 + 255) / 256;

    // ---- fork: CSR build + weight concats (side stream) ----
    cudaEventRecord(ev_fork, 0);
    cudaStreamWaitEvent(s_side, ev_fork, 0);
    cudaMemsetAsync(deg, 0, N_NODES * sizeof(int), s_side);
    hist_kernel<<<(E_EDGES + 255) / 256, 256, 0, s_side>>>(dst, deg);
    scan1_kernel<<<SCAN_NB, 256, 0, s_side>>>(deg, roff, bsum);
    scan2_kernel<<<1, 256, 0, s_side>>>(bsum, boff, roff);
    scan3_kernel<<<SCAN_NB, 256, 0, s_side>>>(roff, boff, cur);
    scatter_kernel<<<(E_EDGES + 255) / 256, 256, 0, s_side>>>(src, dst, cur, esrc);
    concat_both_kernel<<<(128 * 64 + 64 * 64 + 255) / 256, 256, 0, s_side>>>(
        s1wl, s1wr, wc1, s2wl, s2wr, wc2);
    cudaEventRecord(ev_join, s_side);

    // ---- main: GAT layer 1 GEMM (fp16 h + smem-reduced al) ----
    mma_gemm_kernel<<<gemmBlocks, 256>>>(x, W1, H16, nullptr,
                                         N_NODES, 256, a_src1, a_dst1, als1, ald1);

    // ---- join: gathers need CSR ----
    cudaStreamWaitEvent(0, ev_join, 0);
    gat_gather_kernel<<<gatherBlocks, 256>>>(roff, esrc, als1, ald1, H16, b1, B, 1);

    // ---- GAT layer 2 ----
    mma_gemm_kernel<<<gemmBlocks, 256>>>(B, W2, H16, nullptr,
                                         N_NODES, 128, a_src2, a_dst2, als2, ald2);
    gat_gather_kernel<<<gatherBlocks, 256>>>(roff, esrc, als2, ald2, H16, b2, A, 0);

    // ---- SAGE layer 1: y (fp16) + r (fp32) in one GEMM ----
    mma_gemm_kernel<<<gemmBlocks, 256>>>(A, wc1, Y16, Ebuf, N_NODES, 128,
                                         nullptr, nullptr, nullptr, nullptr);
    sage_gather_kernel<<<gatherBlocks, 256>>>(roff, esrc, Y16, s1bl, Ebuf, F,
                                              nullptr, nullptr, nullptr, nullptr, 0);

    // ---- SAGE layer 2 + BN fused ----
    mma_gemm_kernel<<<gemmBlocks, 256>>>(F, wc2, Y16, Ebuf, N_NODES, 64,
                                         nullptr, nullptr, nullptr, nullptr);
    sage_gather_kernel<<<gatherBlocks, 256>>>(roff, esrc, Y16, s2bl, Ebuf, out,
                                              bng, bnb, bnm, bnv, 1);
}

// round 13
// speedup vs baseline: 1.4576x; 1.0257x over previous
#include <cuda_runtime.h>
#include <cuda_bf16.h>
#include <cuda_fp16.h>
#include <math.h>
#include <stdint.h>

#define N_NODES 50000
#define E_EDGES 1600000
#define NEG_SLOPE 0.2f
#define BN_EPS 1e-5f
#define SCAN_NB ((N_NODES + 255) / 256)   // 196

// weight pool offsets (bf16 hi/lo, each row 128 wide)
#define OFF_W1  0        // 256 rows
#define OFF_W2  32768    // 128 rows
#define OFF_WC1 49152    // 128 rows
#define OFF_WC2 65536    // 64 rows
#define W16_TOTAL 73728

// ---------------- scratch (static device globals; no allocation) ------------
__device__ float  g_bufA[(size_t)N_NODES * 128];
__device__ float  g_bufB[(size_t)N_NODES * 128];
__device__ float  g_bufE[(size_t)N_NODES * 64];
__device__ float  g_bufF[(size_t)N_NODES * 64];
__device__ __half g_h16[(size_t)N_NODES * 128];   // fp16 GAT features
__device__ __half g_y16[(size_t)N_NODES * 64];    // fp16 SAGE projected feats
__device__ float  g_als1[N_NODES * 2];
__device__ float  g_ald1[N_NODES * 2];
__device__ float  g_als2[N_NODES * 2];
__device__ float  g_ald2[N_NODES * 2];
__device__ __nv_bfloat16 g_w16hi[W16_TOTAL];
__device__ __nv_bfloat16 g_w16lo[W16_TOTAL];
__device__ int    g_deg[N_NODES];
__device__ int    g_roff[N_NODES + 1];
__device__ int    g_cur[N_NODES];
__device__ int    g_esrc[E_EDGES];
__device__ int    g_bsum[256];
__device__ int    g_boff[256];

// ---------------- helpers ----------------------------------------------------
__device__ __forceinline__ float lrelu(float x) {
    return x > 0.0f ? x : NEG_SLOPE * x;
}

__device__ __forceinline__ uint32_t smem_u32(const void* p) {
    return (uint32_t)__cvta_generic_to_shared(p);
}

__device__ __forceinline__ void ldsm_x4(uint32_t* r, uint32_t addr) {
    asm volatile("ldmatrix.sync.aligned.m8n8.x4.shared.b16 {%0,%1,%2,%3}, [%4];"
        : "=r"(r[0]), "=r"(r[1]), "=r"(r[2]), "=r"(r[3]) : "r"(addr));
}

__device__ __forceinline__ void ldsm_x4_t(uint32_t* r, uint32_t addr) {
    asm volatile("ldmatrix.sync.aligned.m8n8.x4.trans.shared.b16 {%0,%1,%2,%3}, [%4];"
        : "=r"(r[0]), "=r"(r[1]), "=r"(r[2]), "=r"(r[3]) : "r"(addr));
}

__device__ __forceinline__ void mma_bf16(float* d, const uint32_t* a,
                                         const uint32_t* b) {
    asm volatile(
        "mma.sync.aligned.m16n8k16.row.col.f32.bf16.bf16.f32 "
        "{%0,%1,%2,%3}, {%4,%5,%6,%7}, {%8,%9}, {%0,%1,%2,%3};"
        : "+f"(d[0]), "+f"(d[1]), "+f"(d[2]), "+f"(d[3])
        : "r"(a[0]), "r"(a[1]), "r"(a[2]), "r"(a[3]), "r"(b[0]), "r"(b[1]));
}

// ---------------- weight pre-conversion (fp32 -> bf16 hi/lo) -----------------
__global__ void convert_w_kernel(const float* __restrict__ W,
                                 __nv_bfloat16* __restrict__ hi,
                                 __nv_bfloat16* __restrict__ lo, int n)
{
    int i = blockIdx.x * blockDim.x + threadIdx.x;
    if (i >= n) return;
    float v = W[i];
    __nv_bfloat16 h = __float2bfloat16(v);
    hi[i] = h;
    lo[i] = __float2bfloat16(v - __bfloat162float(h));
}

// concat [wl|wr] -> bf16 hi/lo directly
__global__ void concat16_kernel(const float* __restrict__ wl,
                                const float* __restrict__ wr,
                                __nv_bfloat16* __restrict__ hi,
                                __nv_bfloat16* __restrict__ lo, int K)
{
    int i = blockIdx.x * blockDim.x + threadIdx.x;
    if (i >= K * 64) return;
    int k = i >> 6, c = i & 63;
    float v1 = wl[i], v2 = wr[i];
    __nv_bfloat16 h1 = __float2bfloat16(v1);
    __nv_bfloat16 h2 = __float2bfloat16(v2);
    hi[k * 128 + c]      = h1;
    lo[k * 128 + c]      = __float2bfloat16(v1 - __bfloat162float(h1));
    hi[k * 128 + 64 + c] = h2;
    lo[k * 128 + 64 + c] = __float2bfloat16(v2 - __bfloat162float(h2));
}

// ---------------- tensor-core GEMM via mma.sync (bf16 x3 split) --------------
// BM=64, 256 threads, double-buffered; W pre-split into bf16 hi/lo.
#define APAD 24
#define BPAD 136

struct MmaSmem {
    __align__(16) __nv_bfloat16 Ahi[64 * APAD];
    __align__(16) __nv_bfloat16 Alo[64 * APAD];
    __align__(16) __nv_bfloat16 Bhi[16 * BPAD];
    __align__(16) __nv_bfloat16 Blo[16 * BPAD];
};

__global__ __launch_bounds__(256, 3) void mma_gemm_kernel(
    const float* __restrict__ A,
    const __nv_bfloat16* __restrict__ Whi,
    const __nv_bfloat16* __restrict__ Wlo,
    __half* __restrict__ outH, float* __restrict__ outF,
    int M, int K,
    const float* __restrict__ aSrcVec, const float* __restrict__ aDstVec,
    float* __restrict__ als, float* __restrict__ ald)
{
    __shared__ MmaSmem sm[2];
    __shared__ float red[4][64];

    int tid  = threadIdx.x;
    int w    = tid >> 5;
    int lane = tid & 31;
    int rowBase = blockIdx.x * 64;

    float acc[4][2][4];
    #pragma unroll
    for (int mi = 0; mi < 4; mi++)
        #pragma unroll
        for (int ni = 0; ni < 2; ni++)
            #pragma unroll
            for (int q = 0; q < 4; q++) acc[mi][ni][q] = 0.0f;

    uint32_t aHiB[2] = {smem_u32(sm[0].Ahi), smem_u32(sm[1].Ahi)};
    uint32_t aLoB[2] = {smem_u32(sm[0].Alo), smem_u32(sm[1].Alo)};
    uint32_t bHiB[2] = {smem_u32(sm[0].Bhi), smem_u32(sm[1].Bhi)};
    uint32_t bLoB[2] = {smem_u32(sm[0].Blo), smem_u32(sm[1].Blo)};

    int a_r = (lane & 7) + ((lane >> 3) & 1) * 8;
    int a_c = (lane >> 4) * 8;
    int b_r = lane & 15;
    int b_c = (lane >> 4) * 8;

    int aR = tid >> 2, aC = (tid & 3) * 4;
    int arow = aR * APAD + aC;
    bool aok = (rowBase + aR) < M;
    int wR[2], wC[2], wrow[2];
    #pragma unroll
    for (int h = 0; h < 2; h++) {
        int i = tid + h * 256;
        wR[h] = i >> 5;  wC[h] = (i & 31) * 4;
        wrow[h] = wR[h] * BPAD + wC[h];
    }

    if (aSrcVec != nullptr) ((float*)red)[tid] = 0.0f;

    float4 av;
    uint2 wvh[2], wvl[2];
    av = make_float4(0.f, 0.f, 0.f, 0.f);
    if (aok) av = *(const float4*)(A + (size_t)(rowBase + aR) * K + aC);
    #pragma unroll
    for (int h = 0; h < 2; h++) {
        wvh[h] = *(const uint2*)(Whi + (size_t)wR[h] * 128 + wC[h]);
        wvl[h] = *(const uint2*)(Wlo + (size_t)wR[h] * 128 + wC[h]);
    }

    {
        float* vp = (float*)&av;
        #pragma unroll
        for (int q = 0; q < 4; q++) {
            __nv_bfloat16 hi = __float2bfloat16(vp[q]);
            sm[0].Ahi[arow + q] = hi;
            sm[0].Alo[arow + q] = __float2bfloat16(vp[q] - __bfloat162float(hi));
        }
        #pragma unroll
        for (int h = 0; h < 2; h++) {
            *(uint2*)&sm[0].Bhi[wrow[h]] = wvh[h];
            *(uint2*)&sm[0].Blo[wrow[h]] = wvl[h];
        }
    }
    __syncthreads();

    int nchunk = K >> 4;
    for (int c = 0; c < nchunk; c++) {
        int sel = c & 1;
        bool more = (c + 1 < nchunk);
        if (more) {
            int k0n = (c + 1) << 4;
            av = make_float4(0.f, 0.f, 0.f, 0.f);
            if (aok) av = *(const float4*)(A + (size_t)(rowBase + aR) * K + k0n + aC);
            #pragma unroll
            for (int h = 0; h < 2; h++) {
                wvh[h] = *(const uint2*)(Whi + (size_t)(k0n + wR[h]) * 128 + wC[h]);
                wvl[h] = *(const uint2*)(Wlo + (size_t)(k0n + wR[h]) * 128 + wC[h]);
            }
        }

        uint32_t bh[4], bl[4];
        {
            uint32_t boff = (uint32_t)(b_r * BPAD + w * 16 + b_c) * 2;
            ldsm_x4_t(bh, bHiB[sel] + boff);
            ldsm_x4_t(bl, bLoB[sel] + boff);
        }
        #pragma unroll
        for (int mi = 0; mi < 4; mi++) {
            uint32_t aoff = (uint32_t)((mi * 16 + a_r) * APAD + a_c) * 2;
            uint32_t ah[4], al[4];
            ldsm_x4(ah, aHiB[sel] + aoff);
            ldsm_x4(al, aLoB[sel] + aoff);
            #pragma unroll
            for (int ni = 0; ni < 2; ni++) {
                mma_bf16(acc[mi][ni], ah, &bh[ni * 2]);
                mma_bf16(acc[mi][ni], ah, &bl[ni * 2]);
                mma_bf16(acc[mi][ni], al, &bh[ni * 2]);
            }
        }

        if (more) {
            MmaSmem& dst = sm[sel ^ 1];
            float* vp = (float*)&av;
            #pragma unroll
            for (int q = 0; q < 4; q++) {
                __nv_bfloat16 hi = __float2bfloat16(vp[q]);
                dst.Ahi[arow + q] = hi;
                dst.Alo[arow + q] = __float2bfloat16(vp[q] - __bfloat162float(hi));
            }
            #pragma unroll
            for (int h = 0; h < 2; h++) {
                *(uint2*)&dst.Bhi[wrow[h]] = wvh[h];
                *(uint2*)&dst.Blo[wrow[h]] = wvl[h];
            }
            __syncthreads();
        }
    }

    int g = lane >> 2, tig = lane & 3;

    // epilogue: fp16 (+ optional fp32 r split)
    #pragma unroll
    for (int mi = 0; mi < 4; mi++) {
        int row = rowBase + mi * 16 + g;
        #pragma unroll
        for (int ni = 0; ni < 2; ni++) {
            int col = w * 16 + ni * 8 + tig * 2;
            if (outF == nullptr) {
                __half2 v0 = __floats2half2_rn(acc[mi][ni][0], acc[mi][ni][1]);
                __half2 v1 = __floats2half2_rn(acc[mi][ni][2], acc[mi][ni][3]);
                if (row < M)
                    *(__half2*)(outH + (size_t)row * 128 + col) = v0;
                if (row + 8 < M)
                    *(__half2*)(outH + (size_t)(row + 8) * 128 + col) = v1;
            } else if (col < 64) {
                __half2 v0 = __floats2half2_rn(acc[mi][ni][0], acc[mi][ni][1]);
                __half2 v1 = __floats2half2_rn(acc[mi][ni][2], acc[mi][ni][3]);
                if (row < M)
                    *(__half2*)(outH + (size_t)row * 64 + col) = v0;
                if (row + 8 < M)
                    *(__half2*)(outH + (size_t)(row + 8) * 64 + col) = v1;
            } else {
                int c2 = col - 64;
                if (row < M)
                    *(float2*)(outF + (size_t)row * 64 + c2) =
                        make_float2(acc[mi][ni][0], acc[mi][ni][1]);
                if (row + 8 < M)
                    *(float2*)(outF + (size_t)(row + 8) * 64 + c2) =
                        make_float2(acc[mi][ni][2], acc[mi][ni][3]);
            }
        }
    }

    // fused attention-logit epilogue via smem reduction
    if (aSrcVec != nullptr) {
        int head = w >> 2;
        float asv[4], adv[4];
        #pragma unroll
        for (int ni = 0; ni < 2; ni++)
            #pragma unroll
            for (int t = 0; t < 2; t++) {
                int col = w * 16 + ni * 8 + tig * 2 + t;
                asv[ni * 2 + t] = __ldg(aSrcVec + col);
                adv[ni * 2 + t] = __ldg(aDstVec + col);
            }
        #pragma unroll
        for (int mi = 0; mi < 4; mi++) {
            float ps0 = 0.f, pd0 = 0.f, ps1 = 0.f, pd1 = 0.f;
            #pragma unroll
            for (int ni = 0; ni < 2; ni++) {
                ps0 += acc[mi][ni][0] * asv[ni * 2] + acc[mi][ni][1] * asv[ni * 2 + 1];
                pd0 += acc[mi][ni][0] * adv[ni * 2] + acc[mi][ni][1] * adv[ni * 2 + 1];
                ps1 += acc[mi][ni][2] * asv[ni * 2] + acc[mi][ni][3] * asv[ni * 2 + 1];
                pd1 += acc[mi][ni][2] * adv[ni * 2] + acc[mi][ni][3] * adv[ni * 2 + 1];
            }
            #pragma unroll
            for (int o = 1; o < 4; o <<= 1) {
                ps0 += __shfl_xor_sync(0xffffffffu, ps0, o);
                pd0 += __shfl_xor_sync(0xffffffffu, pd0, o);
                ps1 += __shfl_xor_sync(0xffffffffu, ps1, o);
                pd1 += __shfl_xor_sync(0xffffffffu, pd1, o);
            }
            if (tig == 0) {
                int r0 = mi * 16 + g;
                atomicAdd(&red[head * 2 + 0][r0],     ps0);
                atomicAdd(&red[head * 2 + 1][r0],     pd0);
                atomicAdd(&red[head * 2 + 0][r0 + 8], ps1);
                atomicAdd(&red[head * 2 + 1][r0 + 8], pd1);
            }
        }
        __syncthreads();
        if (tid < 64) {
            int grow = rowBase + tid;
            if (grow < M) {
                als[grow * 2 + 0] = red[0][tid];
                ald[grow * 2 + 0] = red[1][tid];
                als[grow * 2 + 1] = red[2][tid];
                ald[grow * 2 + 1] = red[3][tid];
            }
        }
    }
}

// ---------------- CSR build ---------------------------------------------------
__global__ void hist_kernel(const int* __restrict__ dst, int* __restrict__ deg)
{
    int e = blockIdx.x * blockDim.x + threadIdx.x;
    if (e < E_EDGES) atomicAdd(&deg[dst[e]], 1);
}

__global__ __launch_bounds__(256) void scan1_kernel(
    const int* __restrict__ deg, int* __restrict__ roff, int* __restrict__ bsum)
{
    int b = blockIdx.x, t = threadIdx.x;
    int idx = b * 256 + t;
    int v = (idx < N_NODES) ? deg[idx] : 0;
    int lane = t & 31, w = t >> 5;

    int x = v;
    #pragma unroll
    for (int o = 1; o < 32; o <<= 1) {
        int y = __shfl_up_sync(0xffffffffu, x, o);
        if (lane >= o) x += y;
    }
    __shared__ int ws[8];
    if (lane == 31) ws[w] = x;
    __syncthreads();
    if (t < 8) {
        int y = ws[t], z = y;
        #pragma unroll
        for (int o = 1; o < 8; o <<= 1) {
            int q = __shfl_up_sync(0xffu, z, o);
            if (t >= o) z += q;
        }
        ws[t] = z - y;
    }
    __syncthreads();
    int excl = x - v + ws[w];
    if (idx < N_NODES) roff[idx] = excl;
    if (t == 255) bsum[b] = excl + v;
}

__global__ __launch_bounds__(256) void scan2_kernel(
    const int* __restrict__ bsum, int* __restrict__ boff, int* __restrict__ roff)
{
    int t = threadIdx.x;
    int v = (t < SCAN_NB) ? bsum[t] : 0;
    int lane = t & 31, w = t >> 5;
    int x = v;
    #pragma unroll
    for (int o = 1; o < 32; o <<= 1) {
        int y = __shfl_up_sync(0xffffffffu, x, o);
        if (lane >= o) x += y;
    }
    __shared__ int ws[8];
    if (lane == 31) ws[w] = x;
    __syncthreads();
    if (t < 8) {
        int y = ws[t], z = y;
        #pragma unroll
        for (int o = 1; o < 8; o <<= 1) {
            int q = __shfl_up_sync(0xffu, z, o);
            if (t >= o) z += q;
        }
        ws[t] = z - y;
    }
    __syncthreads();
    int excl = x - v + ws[w];
    boff[t] = excl;
    if (t == 255) roff[N_NODES] = excl + v;
}

__global__ __launch_bounds__(256) void scan3_kernel(
    int* __restrict__ roff, const int* __restrict__ boff, int* __restrict__ cur)
{
    int idx = blockIdx.x * 256 + threadIdx.x;
    if (idx >= N_NODES) return;
    int r = roff[idx] + boff[blockIdx.x];
    roff[idx] = r;
    cur[idx]  = r;
}

__global__ void scatter_kernel(const int* __restrict__ src,
                               const int* __restrict__ dst,
                               int* __restrict__ cur, int* __restrict__ esrc)
{
    int e = blockIdx.x * blockDim.x + threadIdx.x;
    if (e >= E_EDGES) return;
    int d = dst[e];
    int p = atomicAdd(&cur[d], 1);
    esrc[p] = src[e];
}

// ---------------- fused GAT gather: per-lane head, 1 exp/edge, 8-way ---------
__global__ __launch_bounds__(256) void gat_gather_kernel(
    const int* __restrict__ roff, const int* __restrict__ esrc,
    const float* __restrict__ als, const float* __restrict__ ald,
    const __half* __restrict__ h, const float* __restrict__ bias,
    float* __restrict__ out, int relu)
{
    int d = (blockIdx.x * blockDim.x + threadIdx.x) >> 5;
    int lane = threadIdx.x & 31;
    if (d >= N_NODES) return;

    int head = (lane >= 16);
    float adh = __ldg(ald + 2 * d + head);
    float ash = __ldg(als + 2 * d + head);

    float wsh = __expf(lrelu(ash + adh));
    float s_half = wsh;

    uint2 us = *(const uint2*)(h + (size_t)d * 128 + lane * 4);
    float2 f0 = __half22float2(*(__half2*)&us.x);
    float2 f1 = __half22float2(*(__half2*)&us.y);
    float4 acc;
    acc.x = wsh * f0.x;
    acc.y = wsh * f0.y;
    acc.z = wsh * f1.x;
    acc.w = wsh * f1.y;

    int beg = roff[d], end = roff[d + 1];
    int i = beg;
    for (; i + 8 <= end; i += 8) {
        int sI[8];
        float aI[8];
        uint2 uI[8];
        #pragma unroll
        for (int j = 0; j < 8; j++) sI[j] = __ldg(esrc + i + j);
        #pragma unroll
        for (int j = 0; j < 8; j++) aI[j] = __ldg(als + 2 * sI[j] + head);
        #pragma unroll
        for (int j = 0; j < 8; j++)
            uI[j] = *(const uint2*)(h + (size_t)sI[j] * 128 + lane * 4);
        #pragma unroll
        for (int j = 0; j < 8; j++) {
            float wh = __expf(lrelu(aI[j] + adh));
            s_half += wh;
            float2 v0 = __half22float2(*(__half2*)&uI[j].x);
            float2 v1 = __half22float2(*(__half2*)&uI[j].y);
            acc.x = fmaf(wh, v0.x, acc.x);
            acc.y = fmaf(wh, v0.y, acc.y);
            acc.z = fmaf(wh, v1.x, acc.z);
            acc.w = fmaf(wh, v1.y, acc.w);
        }
    }
    for (; i < end; i++) {
        int s = __ldg(esrc + i);
        float a = __ldg(als + 2 * s + head);
        uint2 u = *(const uint2*)(h + (size_t)s * 128 + lane * 4);
        float wh = __expf(lrelu(a + adh));
        s_half += wh;
        float2 v0 = __half22float2(*(__half2*)&u.x);
        float2 v1 = __half22float2(*(__half2*)&u.y);
        acc.x = fmaf(wh, v0.x, acc.x);
        acc.y = fmaf(wh, v0.y, acc.y);
        acc.z = fmaf(wh, v1.x, acc.z);
        acc.w = fmaf(wh, v1.y, acc.w);
    }

    float inv = 1.0f / s_half;
    float4 b = *(const float4*)(bias + lane * 4);
    acc.x = fmaf(acc.x, inv, b.x);
    acc.y = fmaf(acc.y, inv, b.y);
    acc.z = fmaf(acc.z, inv, b.z);
    acc.w = fmaf(acc.w, inv, b.w);
    if (relu) {
        acc.x = fmaxf(acc.x, 0.0f);
        acc.y = fmaxf(acc.y, 0.0f);
        acc.z = fmaxf(acc.z, 0.0f);
        acc.w = fmaxf(acc.w, 0.0f);
    }
    *(float4*)(out + (size_t)d * 128 + lane * 4) = acc;
}

// ---------------- fused SAGE gather: fp16 y, 8-way unrolled -------------------
__global__ __launch_bounds__(256) void sage_gather_kernel(
    const int* __restrict__ roff, const int* __restrict__ esrc,
    const __half* __restrict__ y, const float* __restrict__ bl,
    const float* __restrict__ r, float* __restrict__ out,
    const float* __restrict__ gamma, const float* __restrict__ beta,
    const float* __restrict__ mean, const float* __restrict__ var,
    int do_bn)
{
    int d = (blockIdx.x * blockDim.x + threadIdx.x) >> 5;
    int lane = threadIdx.x & 31;
    if (d >= N_NODES) return;

    int beg = roff[d], end = roff[d + 1];
    float ax = 0.0f, ay = 0.0f;
    int i = beg;
    for (; i + 8 <= end; i += 8) {
        int sI[8];
        uint32_t uI[8];
        #pragma unroll
        for (int j = 0; j < 8; j++) sI[j] = __ldg(esrc + i + j);
        #pragma unroll
        for (int j = 0; j < 8; j++)
            uI[j] = *(const uint32_t*)(y + (size_t)sI[j] * 64 + lane * 2);
        #pragma unroll
        for (int j = 0; j < 8; j++) {
            float2 v = __half22float2(*(__half2*)&uI[j]);
            ax += v.x;
            ay += v.y;
        }
    }
    for (; i < end; i++) {
        int s = __ldg(esrc + i);
        uint32_t u = *(const uint32_t*)(y + (size_t)s * 64 + lane * 2);
        float2 v = __half22float2(*(__half2*)&u);
        ax += v.x;
        ay += v.y;
    }
    float invc = 1.0f / fmaxf((float)(end - beg), 1.0f);
    int c = lane * 2;
    float2 bb = *(const float2*)(bl + c);
    float2 rr = *(const float2*)(r + (size_t)d * 64 + c);
    float vx = fmaxf(ax * invc + bb.x + rr.x, 0.0f);
    float vy = fmaxf(ay * invc + bb.y + rr.y, 0.0f);
    if (do_bn) {
        float sx = gamma[c]     * rsqrtf(var[c]     + BN_EPS);
        float sy = gamma[c + 1] * rsqrtf(var[c + 1] + BN_EPS);
        vx = (vx - mean[c])     * sx + beta[c];
        vy = (vy - mean[c + 1]) * sy + beta[c + 1];
    }
    *(float2*)(out + (size_t)d * 64 + c) = make_float2(vx, vy);
}

// ---------------- host orchestration -----------------------------------------
extern "C" void kernel_launch(void* const* d_in, const int* in_sizes, int n_in,
                              void* d_out, int out_size)
{
    const float* x      = (const float*)d_in[0];
    const int*   ei     = (const int*)d_in[1];
    const float* W1     = (const float*)d_in[2];
    const float* a_src1 = (const float*)d_in[3];
    const float* a_dst1 = (const float*)d_in[4];
    const float* b1     = (const float*)d_in[5];
    const float* W2     = (const float*)d_in[6];
    const float* a_src2 = (const float*)d_in[7];
    const float* a_dst2 = (const float*)d_in[8];
    const float* b2     = (const float*)d_in[9];
    const float* s1wl   = (const float*)d_in[10];
    const float* s1bl   = (const float*)d_in[11];
    const float* s1wr   = (const float*)d_in[12];
    const float* s2wl   = (const float*)d_in[13];
    const float* s2bl   = (const float*)d_in[14];
    const float* s2wr   = (const float*)d_in[15];
    const float* bng    = (const float*)d_in[16];
    const float* bnb    = (const float*)d_in[17];
    const float* bnm    = (const float*)d_in[18];
    const float* bnv    = (const float*)d_in[19];
    float* out = (float*)d_out;

    const int* src = ei;
    const int* dst = ei + E_EDGES;

    float *A, *B, *Ebuf, *F, *als1, *ald1, *als2, *ald2;
    __half *H16, *Y16;
    __nv_bfloat16 *whi, *wlo;
    int *deg, *roff, *cur, *esrc, *bsum, *boff;
    cudaGetSymbolAddress((void**)&A,    g_bufA);
    cudaGetSymbolAddress((void**)&B,    g_bufB);
    cudaGetSymbolAddress((void**)&Ebuf, g_bufE);
    cudaGetSymbolAddress((void**)&F,    g_bufF);
    cudaGetSymbolAddress((void**)&H16,  g_h16);
    cudaGetSymbolAddress((void**)&Y16,  g_y16);
    cudaGetSymbolAddress((void**)&als1, g_als1);
    cudaGetSymbolAddress((void**)&ald1, g_ald1);
    cudaGetSymbolAddress((void**)&als2, g_als2);
    cudaGetSymbolAddress((void**)&ald2, g_ald2);
    cudaGetSymbolAddress((void**)&whi,  g_w16hi);
    cudaGetSymbolAddress((void**)&wlo,  g_w16lo);
    cudaGetSymbolAddress((void**)&deg,  g_deg);
    cudaGetSymbolAddress((void**)&roff, g_roff);
    cudaGetSymbolAddress((void**)&cur,  g_cur);
    cudaGetSymbolAddress((void**)&esrc, g_esrc);
    cudaGetSymbolAddress((void**)&bsum, g_bsum);
    cudaGetSymbolAddress((void**)&boff, g_boff);

    static cudaStream_t s_side = nullptr;
    static cudaEvent_t ev_fork = nullptr, ev_join = nullptr;
    if (s_side == nullptr) {
        cudaStreamCreateWithFlags(&s_side, cudaStreamNonBlocking);
        cudaEventCreateWithFlags(&ev_fork, cudaEventDisableTiming);
        cudaEventCreateWithFlags(&ev_join, cudaEventDisableTiming);
    }

    int gemmBlocks   = (N_NODES + 63) / 64;
    int gatherBlocks = (N_NODES * 32 + 255) / 256;

    // ---- fork: CSR build + weight conversions (side stream) ----
    cudaEventRecord(ev_fork, 0);
    cudaStreamWaitEvent(s_side, ev_fork, 0);
    cudaMemsetAsync(deg, 0, N_NODES * sizeof(int), s_side);
    hist_kernel<<<(E_EDGES + 255) / 256, 256, 0, s_side>>>(dst, deg);
    scan1_kernel<<<SCAN_NB, 256, 0, s_side>>>(deg, roff, bsum);
    scan2_kernel<<<1, 256, 0, s_side>>>(bsum, boff, roff);
    scan3_kernel<<<SCAN_NB, 256, 0, s_side>>>(roff, boff, cur);
    scatter_kernel<<<(E_EDGES + 255) / 256, 256, 0, s_side>>>(src, dst, cur, esrc);
    convert_w_kernel<<<(128 * 128 + 255) / 256, 256, 0, s_side>>>(
        W2, whi + OFF_W2, wlo + OFF_W2, 128 * 128);
    concat16_kernel<<<(128 * 64 + 255) / 256, 256, 0, s_side>>>(
        s1wl, s1wr, whi + OFF_WC1, wlo + OFF_WC1, 128);
    concat16_kernel<<<(64 * 64 + 255) / 256, 256, 0, s_side>>>(
        s2wl, s2wr, whi + OFF_WC2, wlo + OFF_WC2, 64);
    cudaEventRecord(ev_join, s_side);

    // ---- main: convert W1 (needed immediately), then GAT layer 1 GEMM ----
    convert_w_kernel<<<(256 * 128 + 255) / 256, 256>>>(
        W1, whi + OFF_W1, wlo + OFF_W1, 256 * 128);
    mma_gemm_kernel<<<gemmBlocks, 256>>>(x, whi + OFF_W1, wlo + OFF_W1,
                                         H16, nullptr, N_NODES, 256,
                                         a_src1, a_dst1, als1, ald1);

    // ---- join: gathers need CSR; later GEMMs need side-stream weights ----
    cudaStreamWaitEvent(0, ev_join, 0);
    gat_gather_kernel<<<gatherBlocks, 256>>>(roff, esrc, als1, ald1, H16, b1, B, 1);

    // ---- GAT layer 2 ----
    mma_gemm_kernel<<<gemmBlocks, 256>>>(B, whi + OFF_W2, wlo + OFF_W2,
                                         H16, nullptr, N_NODES, 128,
                                         a_src2, a_dst2, als2, ald2);
    gat_gather_kernel<<<gatherBlocks, 256>>>(roff, esrc, als2, ald2, H16, b2, A, 0);

    // ---- SAGE layer 1: y (fp16) + r (fp32) in one GEMM ----
    mma_gemm_kernel<<<gemmBlocks, 256>>>(A, whi + OFF_WC1, wlo + OFF_WC1,
                                         Y16, Ebuf, N_NODES, 128,
                                         nullptr, nullptr, nullptr, nullptr);
    sage_gather_kernel<<<gatherBlocks, 256>>>(roff, esrc, Y16, s1bl, Ebuf, F,
                                              nullptr, nullptr, nullptr, nullptr, 0);

    // ---- SAGE layer 2 + BN fused ----
    mma_gemm_kernel<<<gemmBlocks, 256>>>(F, whi + OFF_WC2, wlo + OFF_WC2,
                                         Y16, Ebuf, N_NODES, 64,
                                         nullptr, nullptr, nullptr, nullptr);
    sage_gather_kernel<<<gatherBlocks, 256>>>(roff, esrc, Y16, s2bl, Ebuf, out,
                                              bng, bnb, bnm, bnv, 1);
}

// round 14
// speedup vs baseline: 1.5837x; 1.0865x over previous
#include <cuda_runtime.h>
#include <cuda_bf16.h>
#include <cuda_fp16.h>
#include <math.h>
#include <stdint.h>

#define N_NODES 50000
#define E_EDGES 1600000
#define NEG_SLOPE 0.2f
#define BN_EPS 1e-5f
#define SCAN_NB ((N_NODES + 255) / 256)   // 196

// weight pool offsets (bf16 hi/lo, each row 128 wide)
#define OFF_W1  0        // 256 rows
#define OFF_W2  32768    // 128 rows
#define OFF_WC1 49152    // 128 rows
#define OFF_WC2 65536    // 64 rows
#define W16_TOTAL 73728

// ---------------- scratch (static device globals; no allocation) ------------
__device__ float  g_bufA[(size_t)N_NODES * 128];
__device__ float  g_bufB[(size_t)N_NODES * 128];
__device__ float  g_bufE[(size_t)N_NODES * 64];
__device__ float  g_bufF[(size_t)N_NODES * 64];
__device__ __half g_h16[(size_t)N_NODES * 128];
__device__ __half g_y16[(size_t)N_NODES * 64];
__device__ float  g_als1[N_NODES * 2];
__device__ float  g_ald1[N_NODES * 2];
__device__ float  g_als2[N_NODES * 2];
__device__ float  g_ald2[N_NODES * 2];
__device__ __nv_bfloat16 g_w16hi[W16_TOTAL];
__device__ __nv_bfloat16 g_w16lo[W16_TOTAL];
__device__ int    g_deg[N_NODES];
__device__ int    g_roff[N_NODES + 1];
__device__ int    g_cur[N_NODES];
__device__ int    g_esrc[E_EDGES];
__device__ int    g_bsum[256];
__device__ int    g_boff[256];

// ---------------- helpers ----------------------------------------------------
__device__ __forceinline__ float lrelu(float x) {
    return x > 0.0f ? x : NEG_SLOPE * x;
}

__device__ __forceinline__ uint32_t smem_u32(const void* p) {
    return (uint32_t)__cvta_generic_to_shared(p);
}

__device__ __forceinline__ void ldsm_x4(uint32_t* r, uint32_t addr) {
    asm volatile("ldmatrix.sync.aligned.m8n8.x4.shared.b16 {%0,%1,%2,%3}, [%4];"
        : "=r"(r[0]), "=r"(r[1]), "=r"(r[2]), "=r"(r[3]) : "r"(addr));
}

__device__ __forceinline__ void ldsm_x4_t(uint32_t* r, uint32_t addr) {
    asm volatile("ldmatrix.sync.aligned.m8n8.x4.trans.shared.b16 {%0,%1,%2,%3}, [%4];"
        : "=r"(r[0]), "=r"(r[1]), "=r"(r[2]), "=r"(r[3]) : "r"(addr));
}

__device__ __forceinline__ void mma_bf16(float* d, const uint32_t* a,
                                         const uint32_t* b) {
    asm volatile(
        "mma.sync.aligned.m16n8k16.row.col.f32.bf16.bf16.f32 "
        "{%0,%1,%2,%3}, {%4,%5,%6,%7}, {%8,%9}, {%0,%1,%2,%3};"
        : "+f"(d[0]), "+f"(d[1]), "+f"(d[2]), "+f"(d[3])
        : "r"(a[0]), "r"(a[1]), "r"(a[2]), "r"(a[3]), "r"(b[0]), "r"(b[1]));
}

// ---------------- weight pre-conversion (fp32 -> bf16 hi/lo) -----------------
__global__ void convert_w_kernel(const float* __restrict__ W,
                                 __nv_bfloat16* __restrict__ hi,
                                 __nv_bfloat16* __restrict__ lo, int n)
{
    int i = blockIdx.x * blockDim.x + threadIdx.x;
    if (i >= n) return;
    float v = W[i];
    __nv_bfloat16 h = __float2bfloat16(v);
    hi[i] = h;
    lo[i] = __float2bfloat16(v - __bfloat162float(h));
}

__global__ void concat16_kernel(const float* __restrict__ wl,
                                const float* __restrict__ wr,
                                __nv_bfloat16* __restrict__ hi,
                                __nv_bfloat16* __restrict__ lo, int K)
{
    int i = blockIdx.x * blockDim.x + threadIdx.x;
    if (i >= K * 64) return;
    int k = i >> 6, c = i & 63;
    float v1 = wl[i], v2 = wr[i];
    __nv_bfloat16 h1 = __float2bfloat16(v1);
    __nv_bfloat16 h2 = __float2bfloat16(v2);
    hi[k * 128 + c]      = h1;
    lo[k * 128 + c]      = __float2bfloat16(v1 - __bfloat162float(h1));
    hi[k * 128 + 64 + c] = h2;
    lo[k * 128 + 64 + c] = __float2bfloat16(v2 - __bfloat162float(h2));
}

// ---------------- tensor-core GEMM via mma.sync (bf16 x3 split) --------------
#define APAD 24
#define BPAD 136

struct MmaSmem {
    __align__(16) __nv_bfloat16 Ahi[64 * APAD];
    __align__(16) __nv_bfloat16 Alo[64 * APAD];
    __align__(16) __nv_bfloat16 Bhi[16 * BPAD];
    __align__(16) __nv_bfloat16 Blo[16 * BPAD];
};

__global__ __launch_bounds__(256, 3) void mma_gemm_kernel(
    const float* __restrict__ A,
    const __nv_bfloat16* __restrict__ Whi,
    const __nv_bfloat16* __restrict__ Wlo,
    __half* __restrict__ outH, float* __restrict__ outF,
    int M, int K,
    const float* __restrict__ aSrcVec, const float* __restrict__ aDstVec,
    float* __restrict__ als, float* __restrict__ ald)
{
    __shared__ MmaSmem sm[2];
    __shared__ float red[4][64];

    int tid  = threadIdx.x;
    int w    = tid >> 5;
    int lane = tid & 31;
    int rowBase = blockIdx.x * 64;

    float acc[4][2][4];
    #pragma unroll
    for (int mi = 0; mi < 4; mi++)
        #pragma unroll
        for (int ni = 0; ni < 2; ni++)
            #pragma unroll
            for (int q = 0; q < 4; q++) acc[mi][ni][q] = 0.0f;

    uint32_t aHiB[2] = {smem_u32(sm[0].Ahi), smem_u32(sm[1].Ahi)};
    uint32_t aLoB[2] = {smem_u32(sm[0].Alo), smem_u32(sm[1].Alo)};
    uint32_t bHiB[2] = {smem_u32(sm[0].Bhi), smem_u32(sm[1].Bhi)};
    uint32_t bLoB[2] = {smem_u32(sm[0].Blo), smem_u32(sm[1].Blo)};

    int a_r = (lane & 7) + ((lane >> 3) & 1) * 8;
    int a_c = (lane >> 4) * 8;
    int b_r = lane & 15;
    int b_c = (lane >> 4) * 8;

    int aR = tid >> 2, aC = (tid & 3) * 4;
    int arow = aR * APAD + aC;
    bool aok = (rowBase + aR) < M;
    int wR[2], wC[2], wrow[2];
    #pragma unroll
    for (int h = 0; h < 2; h++) {
        int i = tid + h * 256;
        wR[h] = i >> 5;  wC[h] = (i & 31) * 4;
        wrow[h] = wR[h] * BPAD + wC[h];
    }

    if (aSrcVec != nullptr) ((float*)red)[tid] = 0.0f;

    float4 av;
    uint2 wvh[2], wvl[2];
    av = make_float4(0.f, 0.f, 0.f, 0.f);
    if (aok) av = *(const float4*)(A + (size_t)(rowBase + aR) * K + aC);
    #pragma unroll
    for (int h = 0; h < 2; h++) {
        wvh[h] = *(const uint2*)(Whi + (size_t)wR[h] * 128 + wC[h]);
        wvl[h] = *(const uint2*)(Wlo + (size_t)wR[h] * 128 + wC[h]);
    }

    {
        float* vp = (float*)&av;
        #pragma unroll
        for (int q = 0; q < 4; q++) {
            __nv_bfloat16 hi = __float2bfloat16(vp[q]);
            sm[0].Ahi[arow + q] = hi;
            sm[0].Alo[arow + q] = __float2bfloat16(vp[q] - __bfloat162float(hi));
        }
        #pragma unroll
        for (int h = 0; h < 2; h++) {
            *(uint2*)&sm[0].Bhi[wrow[h]] = wvh[h];
            *(uint2*)&sm[0].Blo[wrow[h]] = wvl[h];
        }
    }
    __syncthreads();

    int nchunk = K >> 4;
    for (int c = 0; c < nchunk; c++) {
        int sel = c & 1;
        bool more = (c + 1 < nchunk);
        if (more) {
            int k0n = (c + 1) << 4;
            av = make_float4(0.f, 0.f, 0.f, 0.f);
            if (aok) av = *(const float4*)(A + (size_t)(rowBase + aR) * K + k0n + aC);
            #pragma unroll
            for (int h = 0; h < 2; h++) {
                wvh[h] = *(const uint2*)(Whi + (size_t)(k0n + wR[h]) * 128 + wC[h]);
                wvl[h] = *(const uint2*)(Wlo + (size_t)(k0n + wR[h]) * 128 + wC[h]);
            }
        }

        uint32_t bh[4], bl[4];
        {
            uint32_t boff = (uint32_t)(b_r * BPAD + w * 16 + b_c) * 2;
            ldsm_x4_t(bh, bHiB[sel] + boff);
            ldsm_x4_t(bl, bLoB[sel] + boff);
        }
        #pragma unroll
        for (int mi = 0; mi < 4; mi++) {
            uint32_t aoff = (uint32_t)((mi * 16 + a_r) * APAD + a_c) * 2;
            uint32_t ah[4], al[4];
            ldsm_x4(ah, aHiB[sel] + aoff);
            ldsm_x4(al, aLoB[sel] + aoff);
            #pragma unroll
            for (int ni = 0; ni < 2; ni++) {
                mma_bf16(acc[mi][ni], ah, &bh[ni * 2]);
                mma_bf16(acc[mi][ni], ah, &bl[ni * 2]);
                mma_bf16(acc[mi][ni], al, &bh[ni * 2]);
            }
        }

        if (more) {
            MmaSmem& dst = sm[sel ^ 1];
            float* vp = (float*)&av;
            #pragma unroll
            for (int q = 0; q < 4; q++) {
                __nv_bfloat16 hi = __float2bfloat16(vp[q]);
                dst.Ahi[arow + q] = hi;
                dst.Alo[arow + q] = __float2bfloat16(vp[q] - __bfloat162float(hi));
            }
            #pragma unroll
            for (int h = 0; h < 2; h++) {
                *(uint2*)&dst.Bhi[wrow[h]] = wvh[h];
                *(uint2*)&dst.Blo[wrow[h]] = wvl[h];
            }
            __syncthreads();
        }
    }

    int g = lane >> 2, tig = lane & 3;

    #pragma unroll
    for (int mi = 0; mi < 4; mi++) {
        int row = rowBase + mi * 16 + g;
        #pragma unroll
        for (int ni = 0; ni < 2; ni++) {
            int col = w * 16 + ni * 8 + tig * 2;
            if (outF == nullptr) {
                __half2 v0 = __floats2half2_rn(acc[mi][ni][0], acc[mi][ni][1]);
                __half2 v1 = __floats2half2_rn(acc[mi][ni][2], acc[mi][ni][3]);
                if (row < M)
                    *(__half2*)(outH + (size_t)row * 128 + col) = v0;
                if (row + 8 < M)
                    *(__half2*)(outH + (size_t)(row + 8) * 128 + col) = v1;
            } else if (col < 64) {
                __half2 v0 = __floats2half2_rn(acc[mi][ni][0], acc[mi][ni][1]);
                __half2 v1 = __floats2half2_rn(acc[mi][ni][2], acc[mi][ni][3]);
                if (row < M)
                    *(__half2*)(outH + (size_t)row * 64 + col) = v0;
                if (row + 8 < M)
                    *(__half2*)(outH + (size_t)(row + 8) * 64 + col) = v1;
            } else {
                int c2 = col - 64;
                if (row < M)
                    *(float2*)(outF + (size_t)row * 64 + c2) =
                        make_float2(acc[mi][ni][0], acc[mi][ni][1]);
                if (row + 8 < M)
                    *(float2*)(outF + (size_t)(row + 8) * 64 + c2) =
                        make_float2(acc[mi][ni][2], acc[mi][ni][3]);
            }
        }
    }

    if (aSrcVec != nullptr) {
        int head = w >> 2;
        float asv[4], adv[4];
        #pragma unroll
        for (int ni = 0; ni < 2; ni++)
            #pragma unroll
            for (int t = 0; t < 2; t++) {
                int col = w * 16 + ni * 8 + tig * 2 + t;
                asv[ni * 2 + t] = __ldg(aSrcVec + col);
                adv[ni * 2 + t] = __ldg(aDstVec + col);
            }
        #pragma unroll
        for (int mi = 0; mi < 4; mi++) {
            float ps0 = 0.f, pd0 = 0.f, ps1 = 0.f, pd1 = 0.f;
            #pragma unroll
            for (int ni = 0; ni < 2; ni++) {
                ps0 += acc[mi][ni][0] * asv[ni * 2] + acc[mi][ni][1] * asv[ni * 2 + 1];
                pd0 += acc[mi][ni][0] * adv[ni * 2] + acc[mi][ni][1] * adv[ni * 2 + 1];
                ps1 += acc[mi][ni][2] * asv[ni * 2] + acc[mi][ni][3] * asv[ni * 2 + 1];
                pd1 += acc[mi][ni][2] * adv[ni * 2] + acc[mi][ni][3] * adv[ni * 2 + 1];
            }
            #pragma unroll
            for (int o = 1; o < 4; o <<= 1) {
                ps0 += __shfl_xor_sync(0xffffffffu, ps0, o);
                pd0 += __shfl_xor_sync(0xffffffffu, pd0, o);
                ps1 += __shfl_xor_sync(0xffffffffu, ps1, o);
                pd1 += __shfl_xor_sync(0xffffffffu, pd1, o);
            }
            if (tig == 0) {
                int r0 = mi * 16 + g;
                atomicAdd(&red[head * 2 + 0][r0],     ps0);
                atomicAdd(&red[head * 2 + 1][r0],     pd0);
                atomicAdd(&red[head * 2 + 0][r0 + 8], ps1);
                atomicAdd(&red[head * 2 + 1][r0 + 8], pd1);
            }
        }
        __syncthreads();
        if (tid < 64) {
            int grow = rowBase + tid;
            if (grow < M) {
                als[grow * 2 + 0] = red[0][tid];
                ald[grow * 2 + 0] = red[1][tid];
                als[grow * 2 + 1] = red[2][tid];
                ald[grow * 2 + 1] = red[3][tid];
            }
        }
    }
}

// ---------------- CSR build ---------------------------------------------------
__global__ void hist_kernel(const int* __restrict__ dst, int* __restrict__ deg)
{
    int e = blockIdx.x * blockDim.x + threadIdx.x;
    if (e < E_EDGES) atomicAdd(&deg[dst[e]], 1);
}

__global__ __launch_bounds__(256) void scan1_kernel(
    const int* __restrict__ deg, int* __restrict__ roff, int* __restrict__ bsum)
{
    int b = blockIdx.x, t = threadIdx.x;
    int idx = b * 256 + t;
    int v = (idx < N_NODES) ? deg[idx] : 0;
    int lane = t & 31, w = t >> 5;

    int x = v;
    #pragma unroll
    for (int o = 1; o < 32; o <<= 1) {
        int y = __shfl_up_sync(0xffffffffu, x, o);
        if (lane >= o) x += y;
    }
    __shared__ int ws[8];
    if (lane == 31) ws[w] = x;
    __syncthreads();
    if (t < 8) {
        int y = ws[t], z = y;
        #pragma unroll
        for (int o = 1; o < 8; o <<= 1) {
            int q = __shfl_up_sync(0xffu, z, o);
            if (t >= o) z += q;
        }
        ws[t] = z - y;
    }
    __syncthreads();
    int excl = x - v + ws[w];
    if (idx < N_NODES) roff[idx] = excl;
    if (t == 255) bsum[b] = excl + v;
}

__global__ __launch_bounds__(256) void scan2_kernel(
    const int* __restrict__ bsum, int* __restrict__ boff, int* __restrict__ roff)
{
    int t = threadIdx.x;
    int v = (t < SCAN_NB) ? bsum[t] : 0;
    int lane = t & 31, w = t >> 5;
    int x = v;
    #pragma unroll
    for (int o = 1; o < 32; o <<= 1) {
        int y = __shfl_up_sync(0xffffffffu, x, o);
        if (lane >= o) x += y;
    }
    __shared__ int ws[8];
    if (lane == 31) ws[w] = x;
    __syncthreads();
    if (t < 8) {
        int y = ws[t], z = y;
        #pragma unroll
        for (int o = 1; o < 8; o <<= 1) {
            int q = __shfl_up_sync(0xffu, z, o);
            if (t >= o) z += q;
        }
        ws[t] = z - y;
    }
    __syncthreads();
    int excl = x - v + ws[w];
    boff[t] = excl;
    if (t == 255) roff[N_NODES] = excl + v;
}

__global__ __launch_bounds__(256) void scan3_kernel(
    int* __restrict__ roff, const int* __restrict__ boff, int* __restrict__ cur)
{
    int idx = blockIdx.x * 256 + threadIdx.x;
    if (idx >= N_NODES) return;
    int r = roff[idx] + boff[blockIdx.x];
    roff[idx] = r;
    cur[idx]  = r;
}

__global__ void scatter_kernel(const int* __restrict__ src,
                               const int* __restrict__ dst,
                               int* __restrict__ cur, int* __restrict__ esrc)
{
    int e = blockIdx.x * blockDim.x + threadIdx.x;
    if (e >= E_EDGES) return;
    int d = dst[e];
    int p = atomicAdd(&cur[d], 1);
    esrc[p] = src[e];
}

// ---------------- fused GAT gather: HALF-WARP per node ------------------------
// lanes 0-15 -> node 2w, lanes 16-31 -> node 2w+1. Within a half, lane owns
// 8 fp16 cols (uint4); lanes 0-7 of half = head0, 8-15 = head1.
__global__ __launch_bounds__(256) void gat_gather_kernel(
    const int* __restrict__ roff, const int* __restrict__ esrc,
    const float* __restrict__ als, const float* __restrict__ ald,
    const __half* __restrict__ h, const float* __restrict__ bias,
    float* __restrict__ out, int relu)
{
    int warp = (blockIdx.x * blockDim.x + threadIdx.x) >> 5;
    int lane = threadIdx.x & 31;
    int half = lane >> 4;
    int hl   = lane & 15;
    int d = warp * 2 + half;
    if (d >= N_NODES) return;

    int head = (hl >= 8);
    float adh = __ldg(ald + 2 * d + head);
    float ash = __ldg(als + 2 * d + head);

    float wsh = __expf(lrelu(ash + adh));
    float s_half = wsh;

    float acc[8];
    {
        uint4 u = *(const uint4*)(h + (size_t)d * 128 + hl * 8);
        const __half2* p = (const __half2*)&u;
        #pragma unroll
        for (int q = 0; q < 4; q++) {
            float2 v = __half22float2(p[q]);
            acc[q * 2 + 0] = wsh * v.x;
            acc[q * 2 + 1] = wsh * v.y;
        }
    }

    int beg = roff[d], end = roff[d + 1];
    int i = beg;
    for (; i + 4 <= end; i += 4) {
        int sI[4];
        float aI[4];
        uint4 uI[4];
        #pragma unroll
        for (int j = 0; j < 4; j++) sI[j] = __ldg(esrc + i + j);
        #pragma unroll
        for (int j = 0; j < 4; j++) aI[j] = __ldg(als + 2 * sI[j] + head);
        #pragma unroll
        for (int j = 0; j < 4; j++)
            uI[j] = *(const uint4*)(h + (size_t)sI[j] * 128 + hl * 8);
        #pragma unroll
        for (int j = 0; j < 4; j++) {
            float wh = __expf(lrelu(aI[j] + adh));
            s_half += wh;
            const __half2* p = (const __half2*)&uI[j];
            #pragma unroll
            for (int q = 0; q < 4; q++) {
                float2 v = __half22float2(p[q]);
                acc[q * 2 + 0] = fmaf(wh, v.x, acc[q * 2 + 0]);
                acc[q * 2 + 1] = fmaf(wh, v.y, acc[q * 2 + 1]);
            }
        }
    }
    for (; i < end; i++) {
        int s = __ldg(esrc + i);
        float a = __ldg(als + 2 * s + head);
        uint4 u = *(const uint4*)(h + (size_t)s * 128 + hl * 8);
        float wh = __expf(lrelu(a + adh));
        s_half += wh;
        const __half2* p = (const __half2*)&u;
        #pragma unroll
        for (int q = 0; q < 4; q++) {
            float2 v = __half22float2(p[q]);
            acc[q * 2 + 0] = fmaf(wh, v.x, acc[q * 2 + 0]);
            acc[q * 2 + 1] = fmaf(wh, v.y, acc[q * 2 + 1]);
        }
    }

    float inv = 1.0f / s_half;
    float4 b0 = *(const float4*)(bias + hl * 8);
    float4 b1 = *(const float4*)(bias + hl * 8 + 4);
    float4 o0, o1;
    o0.x = fmaf(acc[0], inv, b0.x);
    o0.y = fmaf(acc[1], inv, b0.y);
    o0.z = fmaf(acc[2], inv, b0.z);
    o0.w = fmaf(acc[3], inv, b0.w);
    o1.x = fmaf(acc[4], inv, b1.x);
    o1.y = fmaf(acc[5], inv, b1.y);
    o1.z = fmaf(acc[6], inv, b1.z);
    o1.w = fmaf(acc[7], inv, b1.w);
    if (relu) {
        o0.x = fmaxf(o0.x, 0.0f); o0.y = fmaxf(o0.y, 0.0f);
        o0.z = fmaxf(o0.z, 0.0f); o0.w = fmaxf(o0.w, 0.0f);
        o1.x = fmaxf(o1.x, 0.0f); o1.y = fmaxf(o1.y, 0.0f);
        o1.z = fmaxf(o1.z, 0.0f); o1.w = fmaxf(o1.w, 0.0f);
    }
    float* op = out + (size_t)d * 128 + hl * 8;
    *(float4*)(op)     = o0;
    *(float4*)(op + 4) = o1;
}

// ---------------- fused SAGE gather: HALF-WARP per node -----------------------
// lane owns 4 fp16 cols (uint2).
__global__ __launch_bounds__(256) void sage_gather_kernel(
    const int* __restrict__ roff, const int* __restrict__ esrc,
    const __half* __restrict__ y, const float* __restrict__ bl,
    const float* __restrict__ r, float* __restrict__ out,
    const float* __restrict__ gamma, const float* __restrict__ beta,
    const float* __restrict__ mean, const float* __restrict__ var,
    int do_bn)
{
    int warp = (blockIdx.x * blockDim.x + threadIdx.x) >> 5;
    int lane = threadIdx.x & 31;
    int half = lane >> 4;
    int hl   = lane & 15;
    int d = warp * 2 + half;
    if (d >= N_NODES) return;

    int beg = roff[d], end = roff[d + 1];
    float a0 = 0.f, a1 = 0.f, a2 = 0.f, a3 = 0.f;
    int i = beg;
    for (; i + 4 <= end; i += 4) {
        int sI[4];
        uint2 uI[4];
        #pragma unroll
        for (int j = 0; j < 4; j++) sI[j] = __ldg(esrc + i + j);
        #pragma unroll
        for (int j = 0; j < 4; j++)
            uI[j] = *(const uint2*)(y + (size_t)sI[j] * 64 + hl * 4);
        #pragma unroll
        for (int j = 0; j < 4; j++) {
            float2 v0 = __half22float2(*(__half2*)&uI[j].x);
            float2 v1 = __half22float2(*(__half2*)&uI[j].y);
            a0 += v0.x; a1 += v0.y; a2 += v1.x; a3 += v1.y;
        }
    }
    for (; i < end; i++) {
        int s = __ldg(esrc + i);
        uint2 u = *(const uint2*)(y + (size_t)s * 64 + hl * 4);
        float2 v0 = __half22float2(*(__half2*)&u.x);
        float2 v1 = __half22float2(*(__half2*)&u.y);
        a0 += v0.x; a1 += v0.y; a2 += v1.x; a3 += v1.y;
    }
    float invc = 1.0f / fmaxf((float)(end - beg), 1.0f);
    int c = hl * 4;
    float4 bb = *(const float4*)(bl + c);
    float4 rr = *(const float4*)(r + (size_t)d * 64 + c);
    float v0 = fmaxf(a0 * invc + bb.x + rr.x, 0.0f);
    float v1 = fmaxf(a1 * invc + bb.y + rr.y, 0.0f);
    float v2 = fmaxf(a2 * invc + bb.z + rr.z, 0.0f);
    float v3 = fmaxf(a3 * invc + bb.w + rr.w, 0.0f);
    if (do_bn) {
        float4 gg = *(const float4*)(gamma + c);
        float4 be = *(const float4*)(beta + c);
        float4 mm = *(const float4*)(mean + c);
        float4 vv = *(const float4*)(var + c);
        v0 = (v0 - mm.x) * (gg.x * rsqrtf(vv.x + BN_EPS)) + be.x;
        v1 = (v1 - mm.y) * (gg.y * rsqrtf(vv.y + BN_EPS)) + be.y;
        v2 = (v2 - mm.z) * (gg.z * rsqrtf(vv.z + BN_EPS)) + be.z;
        v3 = (v3 - mm.w) * (gg.w * rsqrtf(vv.w + BN_EPS)) + be.w;
    }
    *(float4*)(out + (size_t)d * 64 + c) = make_float4(v0, v1, v2, v3);
}

// ---------------- host orchestration -----------------------------------------
extern "C" void kernel_launch(void* const* d_in, const int* in_sizes, int n_in,
                              void* d_out, int out_size)
{
    const float* x      = (const float*)d_in[0];
    const int*   ei     = (const int*)d_in[1];
    const float* W1     = (const float*)d_in[2];
    const float* a_src1 = (const float*)d_in[3];
    const float* a_dst1 = (const float*)d_in[4];
    const float* b1     = (const float*)d_in[5];
    const float* W2     = (const float*)d_in[6];
    const float* a_src2 = (const float*)d_in[7];
    const float* a_dst2 = (const float*)d_in[8];
    const float* b2     = (const float*)d_in[9];
    const float* s1wl   = (const float*)d_in[10];
    const float* s1bl   = (const float*)d_in[11];
    const float* s1wr   = (const float*)d_in[12];
    const float* s2wl   = (const float*)d_in[13];
    const float* s2bl   = (const float*)d_in[14];
    const float* s2wr   = (const float*)d_in[15];
    const float* bng    = (const float*)d_in[16];
    const float* bnb    = (const float*)d_in[17];
    const float* bnm    = (const float*)d_in[18];
    const float* bnv    = (const float*)d_in[19];
    float* out = (float*)d_out;

    const int* src = ei;
    const int* dst = ei + E_EDGES;

    float *A, *B, *Ebuf, *F, *als1, *ald1, *als2, *ald2;
    __half *H16, *Y16;
    __nv_bfloat16 *whi, *wlo;
    int *deg, *roff, *cur, *esrc, *bsum, *boff;
    cudaGetSymbolAddress((void**)&A,    g_bufA);
    cudaGetSymbolAddress((void**)&B,    g_bufB);
    cudaGetSymbolAddress((void**)&Ebuf, g_bufE);
    cudaGetSymbolAddress((void**)&F,    g_bufF);
    cudaGetSymbolAddress((void**)&H16,  g_h16);
    cudaGetSymbolAddress((void**)&Y16,  g_y16);
    cudaGetSymbolAddress((void**)&als1, g_als1);
    cudaGetSymbolAddress((void**)&ald1, g_ald1);
    cudaGetSymbolAddress((void**)&als2, g_als2);
    cudaGetSymbolAddress((void**)&ald2, g_ald2);
    cudaGetSymbolAddress((void**)&whi,  g_w16hi);
    cudaGetSymbolAddress((void**)&wlo,  g_w16lo);
    cudaGetSymbolAddress((void**)&deg,  g_deg);
    cudaGetSymbolAddress((void**)&roff, g_roff);
    cudaGetSymbolAddress((void**)&cur,  g_cur);
    cudaGetSymbolAddress((void**)&esrc, g_esrc);
    cudaGetSymbolAddress((void**)&bsum, g_bsum);
    cudaGetSymbolAddress((void**)&boff, g_boff);

    static cudaStream_t s_side = nullptr;
    static cudaEvent_t ev_fork = nullptr, ev_join = nullptr;
    if (s_side == nullptr) {
        cudaStreamCreateWithFlags(&s_side, cudaStreamNonBlocking);
        cudaEventCreateWithFlags(&ev_fork, cudaEventDisableTiming);
        cudaEventCreateWithFlags(&ev_join, cudaEventDisableTiming);
    }

    int gemmBlocks   = (N_NODES + 63) / 64;
    int gatherBlocks = (((N_NODES + 1) / 2) * 32 + 255) / 256;

    // ---- fork: CSR build + weight conversions (side stream) ----
    cudaEventRecord(ev_fork, 0);
    cudaStreamWaitEvent(s_side, ev_fork, 0);
    cudaMemsetAsync(deg, 0, N_NODES * sizeof(int), s_side);
    hist_kernel<<<(E_EDGES + 255) / 256, 256, 0, s_side>>>(dst, deg);
    scan1_kernel<<<SCAN_NB, 256, 0, s_side>>>(deg, roff, bsum);
    scan2_kernel<<<1, 256, 0, s_side>>>(bsum, boff, roff);
    scan3_kernel<<<SCAN_NB, 256, 0, s_side>>>(roff, boff, cur);
    scatter_kernel<<<(E_EDGES + 255) / 256, 256, 0, s_side>>>(src, dst, cur, esrc);
    convert_w_kernel<<<(128 * 128 + 255) / 256, 256, 0, s_side>>>(
        W2, whi + OFF_W2, wlo + OFF_W2, 128 * 128);
    concat16_kernel<<<(128 * 64 + 255) / 256, 256, 0, s_side>>>(
        s1wl, s1wr, whi + OFF_WC1, wlo + OFF_WC1, 128);
    concat16_kernel<<<(64 * 64 + 255) / 256, 256, 0, s_side>>>(
        s2wl, s2wr, whi + OFF_WC2, wlo + OFF_WC2, 64);
    cudaEventRecord(ev_join, s_side);

    // ---- main: convert W1, then GAT layer 1 GEMM ----
    convert_w_kernel<<<(256 * 128 + 255) / 256, 256>>>(
        W1, whi + OFF_W1, wlo + OFF_W1, 256 * 128);
    mma_gemm_kernel<<<gemmBlocks, 256>>>(x, whi + OFF_W1, wlo + OFF_W1,
                                         H16, nullptr, N_NODES, 256,
                                         a_src1, a_dst1, als1, ald1);

    // ---- join: gathers need CSR ----
    cudaStreamWaitEvent(0, ev_join, 0);
    gat_gather_kernel<<<gatherBlocks, 256>>>(roff, esrc, als1, ald1, H16, b1, B, 1);

    // ---- GAT layer 2 ----
    mma_gemm_kernel<<<gemmBlocks, 256>>>(B, whi + OFF_W2, wlo + OFF_W2,
                                         H16, nullptr, N_NODES, 128,
                                         a_src2, a_dst2, als2, ald2);
    gat_gather_kernel<<<gatherBlocks, 256>>>(roff, esrc, als2, ald2, H16, b2, A, 0);

    // ---- SAGE layer 1 ----
    mma_gemm_kernel<<<gemmBlocks, 256>>>(A, whi + OFF_WC1, wlo + OFF_WC1,
                                         Y16, Ebuf, N_NODES, 128,
                                         nullptr, nullptr, nullptr, nullptr);
    sage_gather_kernel<<<gatherBlocks, 256>>>(roff, esrc, Y16, s1bl, Ebuf, F,
                                              nullptr, nullptr, nullptr, nullptr, 0);

    // ---- SAGE layer 2 + BN fused ----
    mma_gemm_kernel<<<gemmBlocks, 256>>>(F, whi + OFF_WC2, wlo + OFF_WC2,
                                         Y16, Ebuf, N_NODES, 64,
                                         nullptr, nullptr, nullptr, nullptr);
    sage_gather_kernel<<<gatherBlocks, 256>>>(roff, esrc, Y16, s2bl, Ebuf, out,
                                              bng, bnb, bnm, bnv, 1);
}